// round 2
// baseline (speedup 1.0000x reference)
#include <cuda_runtime.h>
#include <math.h>

#define BB   2
#define SS   2048
#define DD   2048
#define NHQ  16
#define NKVH 4
#define HDIM 128

// Scratch (device globals — no allocation allowed)
__device__ float g_q[(size_t)BB*SS*NHQ*HDIM];     // 33.5 MB
__device__ float g_k[(size_t)BB*SS*NKVH*HDIM];    //  8.4 MB
__device__ float g_v[(size_t)BB*SS*NKVH*HDIM];    //  8.4 MB
__device__ float g_attn[(size_t)BB*SS*NHQ*HDIM];  // 33.5 MB

// ---------------------------------------------------------------------------
// SGEMM: C[M,N] = A[M,K] @ B[K,N], row-major. M%128==0, N%128==0, K%8==0.
// 128x128 block tile, BK=8, 256 threads, 8x8 register tile per thread.
// ---------------------------------------------------------------------------
__global__ __launch_bounds__(256) void sgemm128(
    const float* __restrict__ A, const float* __restrict__ B,
    float* __restrict__ C, int M, int N, int K)
{
    __shared__ float As[8][128];
    __shared__ float Bs[8][128];

    const int tid = threadIdx.x;
    const int ty  = tid >> 4;      // 0..15
    const int tx  = tid & 15;      // 0..15
    const int row0 = blockIdx.y * 128;
    const int col0 = blockIdx.x * 128;

    // Loaders
    const int arow  = tid >> 1;          // 0..127
    const int acol4 = (tid & 1) * 4;     // 0 or 4
    const int brow  = tid >> 5;          // 0..7
    const int bcol4 = (tid & 31) * 4;    // 0..124

    const float* Aptr = A + (size_t)(row0 + arow) * K + acol4;
    const float* Bptr = B + (size_t)brow * N + col0 + bcol4;

    float acc[8][8];
#pragma unroll
    for (int i = 0; i < 8; i++)
#pragma unroll
        for (int j = 0; j < 8; j++) acc[i][j] = 0.0f;

    for (int k0 = 0; k0 < K; k0 += 8) {
        float4 av = *(const float4*)(Aptr + k0);
        float4 bv = *(const float4*)(Bptr + (size_t)k0 * N);
        As[acol4 + 0][arow] = av.x;
        As[acol4 + 1][arow] = av.y;
        As[acol4 + 2][arow] = av.z;
        As[acol4 + 3][arow] = av.w;
        *(float4*)&Bs[brow][bcol4] = bv;
        __syncthreads();

#pragma unroll
        for (int k = 0; k < 8; k++) {
            float4 a0 = *(float4*)&As[k][ty * 8];
            float4 a1 = *(float4*)&As[k][ty * 8 + 4];
            float4 b0 = *(float4*)&Bs[k][tx * 8];
            float4 b1 = *(float4*)&Bs[k][tx * 8 + 4];
            float a[8] = {a0.x, a0.y, a0.z, a0.w, a1.x, a1.y, a1.z, a1.w};
            float b[8] = {b0.x, b0.y, b0.z, b0.w, b1.x, b1.y, b1.z, b1.w};
#pragma unroll
            for (int i = 0; i < 8; i++)
#pragma unroll
                for (int j = 0; j < 8; j++)
                    acc[i][j] = fmaf(a[i], b[j], acc[i][j]);
        }
        __syncthreads();
    }

#pragma unroll
    for (int i = 0; i < 8; i++) {
        float* cp = C + (size_t)(row0 + ty * 8 + i) * N + col0 + tx * 8;
        *(float4*)(cp)     = make_float4(acc[i][0], acc[i][1], acc[i][2], acc[i][3]);
        *(float4*)(cp + 4) = make_float4(acc[i][4], acc[i][5], acc[i][6], acc[i][7]);
    }
}

// ---------------------------------------------------------------------------
// RoPE (interleaved pairs), matches the reference fp32 math.
// buf layout: [B*S, nh*HDIM]. One thread per (b,s,h,pair).
// ---------------------------------------------------------------------------
__global__ void rope_kernel(float* __restrict__ buf, int nh, int total)
{
    int idx = blockIdx.x * blockDim.x + threadIdx.x;
    if (idx >= total) return;
    int p  = idx & 63;                 // pair index 0..63
    int h  = (idx >> 6) % nh;
    int bs = idx / (64 * nh);
    int s  = bs & (SS - 1);

    float e   = (float)(2 * p) * (1.0f / 128.0f);
    float inv = 1.0f / powf(10000.0f, e);
    float fr  = (float)s * inv;
    float sn, c;
    sincosf(fr, &sn, &c);

    size_t off = ((size_t)bs * nh + h) * HDIM + 2 * p;
    float x1 = buf[off], x2 = buf[off + 1];
    buf[off]     = x1 * c - x2 * sn;
    buf[off + 1] = x1 * sn + x2 * c;
}

// ---------------------------------------------------------------------------
// Flash attention (fp32, causal, GQA 4:1).
// grid = (S/64, NH, B), 256 threads. BM=BN=64.
// Thread (ty,tx): score rows r_i = ty+16i, cols c_j = tx+16j.
// Output cols o_j = tx+16j (j<8).
// smem rows padded to 129 (tiles) / 65 (P) floats -> conflict-free LDS.
// ---------------------------------------------------------------------------
#define LDQ 129
#define LDP 65
#define ATTN_SMEM ((3 * 64 * LDQ + 64 * LDP) * 4)

__global__ __launch_bounds__(256) void attn_kernel(
    const float* __restrict__ gq, const float* __restrict__ gk,
    const float* __restrict__ gv, float* __restrict__ gout)
{
    extern __shared__ float sm[];
    float* Qs = sm;
    float* Ks = Qs + 64 * LDQ;
    float* Vs = Ks + 64 * LDQ;
    float* Ps = Vs + 64 * LDQ;

    const int qt = blockIdx.x;
    const int h  = blockIdx.y;
    const int b  = blockIdx.z;
    const int kvh = h >> 2;                 // NH/NKV = 4

    const int tid = threadIdx.x;
    const int ty  = tid >> 4;
    const int tx  = tid & 15;

    const size_t qstride = (size_t)NHQ * HDIM;   // 2048
    const size_t kstride = (size_t)NKVH * HDIM;  // 512
    const float* qbase = gq + (size_t)b * SS * qstride + (size_t)h * HDIM;
    const float* kbase = gk + (size_t)b * SS * kstride + (size_t)kvh * HDIM;
    const float* vbase = gv + (size_t)b * SS * kstride + (size_t)kvh * HDIM;

    const int q0 = qt * 64;

    // Load Q tile (stays resident)
    for (int idx = tid; idx < 64 * 32; idx += 256) {
        int r  = idx >> 5;
        int c4 = (idx & 31) << 2;
        float4 v = *(const float4*)(qbase + (size_t)(q0 + r) * qstride + c4);
        Qs[r * LDQ + c4]     = v.x;
        Qs[r * LDQ + c4 + 1] = v.y;
        Qs[r * LDQ + c4 + 2] = v.z;
        Qs[r * LDQ + c4 + 3] = v.w;
    }

    float acc[4][8];
#pragma unroll
    for (int i = 0; i < 4; i++)
#pragma unroll
        for (int j = 0; j < 8; j++) acc[i][j] = 0.0f;
    float mrow[4], lrow[4];
#pragma unroll
    for (int i = 0; i < 4; i++) { mrow[i] = -1e30f; lrow[i] = 0.0f; }

    const float scale = 0.08838834764831845f;  // 1/sqrt(128)
    const int ntiles = qt + 1;

    for (int t = 0; t < ntiles; t++) {
        const int k0 = t * 64;
        __syncthreads();  // protect K/V/P reuse
        for (int idx = tid; idx < 64 * 32; idx += 256) {
            int r  = idx >> 5;
            int c4 = (idx & 31) << 2;
            float4 kv = *(const float4*)(kbase + (size_t)(k0 + r) * kstride + c4);
            Ks[r * LDQ + c4]     = kv.x;
            Ks[r * LDQ + c4 + 1] = kv.y;
            Ks[r * LDQ + c4 + 2] = kv.z;
            Ks[r * LDQ + c4 + 3] = kv.w;
            float4 vv = *(const float4*)(vbase + (size_t)(k0 + r) * kstride + c4);
            Vs[r * LDQ + c4]     = vv.x;
            Vs[r * LDQ + c4 + 1] = vv.y;
            Vs[r * LDQ + c4 + 2] = vv.z;
            Vs[r * LDQ + c4 + 3] = vv.w;
        }
        __syncthreads();

        // S = Q @ K^T
        float s[4][4];
#pragma unroll
        for (int i = 0; i < 4; i++)
#pragma unroll
            for (int j = 0; j < 4; j++) s[i][j] = 0.0f;

        for (int d = 0; d < HDIM; d++) {
            float qv[4], kv[4];
#pragma unroll
            for (int i = 0; i < 4; i++) qv[i] = Qs[(ty + i * 16) * LDQ + d];
#pragma unroll
            for (int j = 0; j < 4; j++) kv[j] = Ks[(tx + j * 16) * LDQ + d];
#pragma unroll
            for (int i = 0; i < 4; i++)
#pragma unroll
                for (int j = 0; j < 4; j++)
                    s[i][j] = fmaf(qv[i], kv[j], s[i][j]);
        }

#pragma unroll
        for (int i = 0; i < 4; i++)
#pragma unroll
            for (int j = 0; j < 4; j++) s[i][j] *= scale;

        if (t == qt) {  // diagonal tile: causal mask
#pragma unroll
            for (int i = 0; i < 4; i++)
#pragma unroll
                for (int j = 0; j < 4; j++)
                    if ((tx + j * 16) > (ty + i * 16)) s[i][j] = -1e30f;
        }

        // Online softmax (16-lane row groups)
#pragma unroll
        for (int i = 0; i < 4; i++) {
            float mloc = s[i][0];
#pragma unroll
            for (int j = 1; j < 4; j++) mloc = fmaxf(mloc, s[i][j]);
#pragma unroll
            for (int off = 8; off >= 1; off >>= 1)
                mloc = fmaxf(mloc, __shfl_xor_sync(0xffffffffu, mloc, off));
            float mnew = fmaxf(mrow[i], mloc);
            float fac  = __expf(mrow[i] - mnew);
            float psum = 0.0f;
#pragma unroll
            for (int j = 0; j < 4; j++) {
                float p = __expf(s[i][j] - mnew);
                s[i][j] = p;
                psum += p;
            }
#pragma unroll
            for (int off = 8; off >= 1; off >>= 1)
                psum += __shfl_xor_sync(0xffffffffu, psum, off);
            lrow[i] = lrow[i] * fac + psum;
            mrow[i] = mnew;
#pragma unroll
            for (int j = 0; j < 8; j++) acc[i][j] *= fac;
#pragma unroll
            for (int j = 0; j < 4; j++)
                Ps[(ty + i * 16) * LDP + tx + j * 16] = s[i][j];
        }
        __syncthreads();

        // O += P @ V
        for (int kk = 0; kk < 64; kk++) {
            float pv[4], vv[8];
#pragma unroll
            for (int i = 0; i < 4; i++) pv[i] = Ps[(ty + i * 16) * LDP + kk];
#pragma unroll
            for (int j = 0; j < 8; j++) vv[j] = Vs[kk * LDQ + tx + j * 16];
#pragma unroll
            for (int i = 0; i < 4; i++)
#pragma unroll
                for (int j = 0; j < 8; j++)
                    acc[i][j] = fmaf(pv[i], vv[j], acc[i][j]);
        }
    }

    // Epilogue: normalize + store to [b, s, h*128 + col]
    float* obase = gout + (size_t)b * SS * qstride + (size_t)h * HDIM;
#pragma unroll
    for (int i = 0; i < 4; i++) {
        float inv_l = 1.0f / lrow[i];
        int r = ty + i * 16;
        float* op = obase + (size_t)(q0 + r) * qstride;
#pragma unroll
        for (int j = 0; j < 8; j++)
            op[tx + j * 16] = acc[i][j] * inv_l;
    }
}

// ---------------------------------------------------------------------------
extern "C" void kernel_launch(void* const* d_in, const int* in_sizes, int n_in,
                              void* d_out, int out_size)
{
    const float* x  = (const float*)d_in[0];
    // d_in[1] = mask (unused — causal handled analytically)
    const float* Wq = (const float*)d_in[2];
    const float* Wk = (const float*)d_in[3];
    const float* Wv = (const float*)d_in[4];
    const float* Wo = (const float*)d_in[5];
    float* out = (float*)d_out;

    float *q, *k, *v, *attn;
    (void)cudaGetSymbolAddress((void**)&q, g_q);
    (void)cudaGetSymbolAddress((void**)&k, g_k);
    (void)cudaGetSymbolAddress((void**)&v, g_v);
    (void)cudaGetSymbolAddress((void**)&attn, g_attn);

    (void)cudaFuncSetAttribute(attn_kernel,
                               cudaFuncAttributeMaxDynamicSharedMemorySize,
                               ATTN_SMEM);

    const int M = BB * SS;  // 4096

    // QKV projections
    sgemm128<<<dim3(DD / 128, M / 128), 256>>>(x, Wq, q, M, NHQ * HDIM, DD);
    sgemm128<<<dim3((NKVH * HDIM) / 128, M / 128), 256>>>(x, Wk, k, M, NKVH * HDIM, DD);
    sgemm128<<<dim3((NKVH * HDIM) / 128, M / 128), 256>>>(x, Wv, v, M, NKVH * HDIM, DD);

    // RoPE
    {
        int qtot = BB * SS * NHQ * 64;
        int ktot = BB * SS * NKVH * 64;
        rope_kernel<<<(qtot + 255) / 256, 256>>>(q, NHQ, qtot);
        rope_kernel<<<(ktot + 255) / 256, 256>>>(k, NKVH, ktot);
    }

    // Attention
    attn_kernel<<<dim3(SS / 64, NHQ, BB), 256, ATTN_SMEM>>>(q, k, v, attn);

    // Output projection
    sgemm128<<<dim3(DD / 128, M / 128), 256>>>(attn, Wo, out, M, DD, NHQ * HDIM);
}

// round 4
// speedup vs baseline: 1.6285x; 1.6285x over previous
#include <cuda_runtime.h>
#include <cuda_bf16.h>
#include <math.h>
#include <stdint.h>

#define BB   2
#define SS   2048
#define DD   2048
#define NHQ  16
#define NKVH 4
#define HDIM 128
#define MM   (BB*SS)       // 4096
#define KK   2048          // inner dim for all 4 GEMMs
#define NQ   (NHQ*HDIM)    // 2048
#define NKV  (NKVH*HDIM)   // 512

// ---------------- scratch (device globals; no allocation allowed) ----------
__device__ float g_q[(size_t)MM*NQ];
__device__ float g_k[(size_t)MM*NKV];
__device__ float g_v[(size_t)MM*NKV];
__device__ float g_attn[(size_t)MM*NQ];

__device__ __nv_bfloat16 g_xhi[(size_t)MM*KK],  g_xlo[(size_t)MM*KK];
__device__ __nv_bfloat16 g_ahi[(size_t)MM*NQ],  g_alo[(size_t)MM*NQ];
__device__ __nv_bfloat16 g_wqThi[(size_t)NQ*KK],  g_wqTlo[(size_t)NQ*KK];
__device__ __nv_bfloat16 g_wkThi[(size_t)NKV*KK], g_wkTlo[(size_t)NKV*KK];
__device__ __nv_bfloat16 g_wvThi[(size_t)NKV*KK], g_wvTlo[(size_t)NKV*KK];
__device__ __nv_bfloat16 g_woThi[(size_t)NQ*KK],  g_woTlo[(size_t)NQ*KK];

// ---------------- PTX helpers (sm_80-era: valid on plain sm_103 target) ----
__device__ __forceinline__ uint32_t smem_u32(const void* p) {
    uint32_t a;
    asm("{ .reg .u64 t; cvta.to.shared.u64 t, %1; cvt.u32.u64 %0, t; }"
        : "=r"(a) : "l"(p));
    return a;
}

__device__ __forceinline__ void cp16(uint32_t s, const void* g) {
    asm volatile("cp.async.cg.shared.global [%0], [%1], 16;" :: "r"(s), "l"(g));
}
#define CP_COMMIT() asm volatile("cp.async.commit_group;" ::: "memory")
#define CP_WAIT(n)  asm volatile("cp.async.wait_group %0;" :: "n"(n) : "memory")

__device__ __forceinline__ void ldm_x4(uint32_t& r0, uint32_t& r1,
                                       uint32_t& r2, uint32_t& r3, uint32_t a) {
    asm volatile("ldmatrix.sync.aligned.m8n8.x4.shared.b16 {%0,%1,%2,%3}, [%4];"
                 : "=r"(r0), "=r"(r1), "=r"(r2), "=r"(r3) : "r"(a));
}

__device__ __forceinline__ void mma16816(float* c,
    uint32_t a0, uint32_t a1, uint32_t a2, uint32_t a3, uint32_t b0, uint32_t b1)
{
    asm volatile(
        "mma.sync.aligned.m16n8k16.row.col.f32.bf16.bf16.f32 "
        "{%0,%1,%2,%3}, {%4,%5,%6,%7}, {%8,%9}, {%0,%1,%2,%3};"
        : "+f"(c[0]), "+f"(c[1]), "+f"(c[2]), "+f"(c[3])
        : "r"(a0), "r"(a1), "r"(a2), "r"(a3), "r"(b0), "r"(b1));
}

// ---------------------------------------------------------------------------
// bf16x3 mma.sync GEMM:  C[M,N](fp32) = A[M,K] @ Bt[N,K]^T
// A = Ahi+Alo, Bt = Bhi+Blo; C ≈ Ahi·Bhi + Ahi·Blo + Alo·Bhi (fp32 accum).
// CTA: 128x128 tile, 256 threads (8 warps, warp tile 64x32), BK=32,
// cp.async double buffer. Smem row pitch 80 B (conflict-free ldmatrix).
// ---------------------------------------------------------------------------
#define BK        32
#define ROWB      80                   // bytes per smem row (32 bf16 + 8 pad)
#define TILEB     (128 * ROWB)         // 10240 B
#define OFF_AHI   0
#define OFF_ALO   (TILEB)
#define OFF_BHI   (2 * TILEB)
#define OFF_BLO   (3 * TILEB)
#define STAGEB    (4 * TILEB)          // 40960 B
#define GEMM_DSMEM (2 * STAGEB)        // 81920 B
#define NCHUNK    (KK / BK)            // 64

__device__ __forceinline__ void load_stage(uint32_t sBase,
    const __nv_bfloat16* Ahi, const __nv_bfloat16* Alo,
    const __nv_bfloat16* Bhi, const __nv_bfloat16* Blo,
    int row0, int col0, int k0, int tid)
{
#pragma unroll
    for (int t = 0; t < 8; t++) {
        int i    = tid + t * 256;
        int tile = i >> 9;             // constant per unrolled t
        int w    = i & 511;
        int r    = w >> 2;
        int seg  = w & 3;
        const __nv_bfloat16* src =
            (tile == 0) ? Ahi : (tile == 1) ? Alo : (tile == 2) ? Bhi : Blo;
        int rb = (tile < 2) ? row0 : col0;
        cp16(sBase + tile * TILEB + r * ROWB + seg * 16,
             src + (size_t)(rb + r) * KK + k0 + seg * 8);
    }
}

__device__ __forceinline__ void mma_pass(uint32_t aW, uint32_t bW, int lane,
                                         float acc[4][4][4])
{
#pragma unroll
    for (int ks = 0; ks < 2; ks++) {
        uint32_t A[4][4];
#pragma unroll
        for (int am = 0; am < 4; am++) {
            uint32_t ad = aW + (uint32_t)((am * 16 + (lane & 15)) * ROWB
                        + (ks * 16 + ((lane >> 4) << 3)) * 2);
            ldm_x4(A[am][0], A[am][1], A[am][2], A[am][3], ad);
        }
        uint32_t Bg[2][4];
#pragma unroll
        for (int bn = 0; bn < 2; bn++) {
            uint32_t bd = bW + (uint32_t)((bn * 16 + ((lane >> 4) << 3) + (lane & 7)) * ROWB
                        + (ks * 16 + ((lane >> 3) & 1) * 8) * 2);
            ldm_x4(Bg[bn][0], Bg[bn][1], Bg[bn][2], Bg[bn][3], bd);
        }
#pragma unroll
        for (int am = 0; am < 4; am++)
#pragma unroll
            for (int an = 0; an < 4; an++)
                mma16816(acc[am][an], A[am][0], A[am][1], A[am][2], A[am][3],
                         Bg[an >> 1][(an & 1) * 2], Bg[an >> 1][(an & 1) * 2 + 1]);
    }
}

__global__ __launch_bounds__(256) void gemm_bf16x3(
    const __nv_bfloat16* __restrict__ Ahi, const __nv_bfloat16* __restrict__ Alo,
    const __nv_bfloat16* __restrict__ Bhi, const __nv_bfloat16* __restrict__ Blo,
    float* __restrict__ C, int N)
{
    extern __shared__ char dsm[];
    const uint32_t sBase = smem_u32(dsm);

    const int tid  = threadIdx.x;
    const int lane = tid & 31;
    const int wid  = tid >> 5;
    const int wr   = wid >> 2;         // 0..1
    const int wc   = wid & 3;          // 0..3
    const int row0 = blockIdx.y * 128;
    const int col0 = blockIdx.x * 128;

    float acc[4][4][4];
#pragma unroll
    for (int i = 0; i < 4; i++)
#pragma unroll
        for (int j = 0; j < 4; j++)
#pragma unroll
            for (int l = 0; l < 4; l++) acc[i][j][l] = 0.0f;

    load_stage(sBase, Ahi, Alo, Bhi, Blo, row0, col0, 0, tid);
    CP_COMMIT();

#pragma unroll 1
    for (int c = 0; c < NCHUNK; c++) {
        const uint32_t st = sBase + (uint32_t)(c & 1) * STAGEB;
        if (c + 1 < NCHUNK) {
            load_stage(sBase + (uint32_t)((c + 1) & 1) * STAGEB,
                       Ahi, Alo, Bhi, Blo, row0, col0, (c + 1) * BK, tid);
            CP_COMMIT();
            CP_WAIT(1);
        } else {
            CP_WAIT(0);
        }
        __syncthreads();

        const uint32_t aHiW = st + OFF_AHI + (uint32_t)(wr * 64) * ROWB;
        const uint32_t aLoW = st + OFF_ALO + (uint32_t)(wr * 64) * ROWB;
        const uint32_t bHiW = st + OFF_BHI + (uint32_t)(wc * 32) * ROWB;
        const uint32_t bLoW = st + OFF_BLO + (uint32_t)(wc * 32) * ROWB;
        mma_pass(aHiW, bHiW, lane, acc);
        mma_pass(aHiW, bLoW, lane, acc);
        mma_pass(aLoW, bHiW, lane, acc);
        __syncthreads();
    }

    const int rbase = row0 + wr * 64;
    const int cbase = col0 + wc * 32;
#pragma unroll
    for (int am = 0; am < 4; am++)
#pragma unroll
        for (int an = 0; an < 4; an++) {
            float* cf = acc[am][an];
            int r  = rbase + am * 16 + (lane >> 2);
            int cc = cbase + an * 8 + (lane & 3) * 2;
            *(float2*)(C + (size_t)r * N + cc)       = make_float2(cf[0], cf[1]);
            *(float2*)(C + (size_t)(r + 8) * N + cc) = make_float2(cf[2], cf[3]);
        }
}

// ---------------------------------------------------------------------------
// fp32 -> (hi, lo) bf16 split, elementwise
// ---------------------------------------------------------------------------
__global__ void split_pair(const float2* __restrict__ src,
                           __nv_bfloat162* __restrict__ hi,
                           __nv_bfloat162* __restrict__ lo, int n2)
{
    int i = blockIdx.x * blockDim.x + threadIdx.x;
    if (i >= n2) return;
    float2 v = src[i];
    __nv_bfloat16 hx = __float2bfloat16(v.x);
    __nv_bfloat16 hy = __float2bfloat16(v.y);
    hi[i] = __halves2bfloat162(hx, hy);
    lo[i] = __halves2bfloat162(__float2bfloat16(v.x - __bfloat162float(hx)),
                               __float2bfloat16(v.y - __bfloat162float(hy)));
}

// ---------------------------------------------------------------------------
// W [K,N] fp32 -> Wt hi/lo [N,K] bf16 (transpose + split)
// ---------------------------------------------------------------------------
__global__ void transpose_split(const float* __restrict__ src,
                                __nv_bfloat16* __restrict__ hi,
                                __nv_bfloat16* __restrict__ lo, int K, int N)
{
    __shared__ float t[32][33];
    int k0 = blockIdx.y * 32, n0 = blockIdx.x * 32;
    int tx = threadIdx.x, ty = threadIdx.y;
#pragma unroll
    for (int j = 0; j < 32; j += 8)
        t[ty + j][tx] = src[(size_t)(k0 + ty + j) * N + n0 + tx];
    __syncthreads();
#pragma unroll
    for (int j = 0; j < 32; j += 8) {
        float v = t[tx][ty + j];
        __nv_bfloat16 h = __float2bfloat16(v);
        size_t o = (size_t)(n0 + ty + j) * K + k0 + tx;
        hi[o] = h;
        lo[o] = __float2bfloat16(v - __bfloat162float(h));
    }
}

// ---------------------------------------------------------------------------
// RoPE (interleaved pairs), fp32, matches reference math
// ---------------------------------------------------------------------------
__global__ void rope_kernel(float* __restrict__ buf, int nh, int total)
{
    int idx = blockIdx.x * blockDim.x + threadIdx.x;
    if (idx >= total) return;
    int p  = idx & 63;
    int h  = (idx >> 6) % nh;
    int bs = idx / (64 * nh);
    int s  = bs & (SS - 1);

    float e   = (float)(2 * p) * (1.0f / 128.0f);
    float inv = 1.0f / powf(10000.0f, e);
    float fr  = (float)s * inv;
    float sn, c;
    sincosf(fr, &sn, &c);

    size_t off = ((size_t)bs * nh + h) * HDIM + 2 * p;
    float x1 = buf[off], x2 = buf[off + 1];
    buf[off]     = x1 * c - x2 * sn;
    buf[off + 1] = x1 * sn + x2 * c;
}

// ---------------------------------------------------------------------------
// Flash attention (fp32, causal, GQA 4:1). Unchanged from passing round.
// ---------------------------------------------------------------------------
#define LDQ 129
#define LDP 65
#define ATTN_SMEM ((3 * 64 * LDQ + 64 * LDP) * 4)

__global__ __launch_bounds__(256) void attn_kernel(
    const float* __restrict__ gq, const float* __restrict__ gk,
    const float* __restrict__ gv, float* __restrict__ gout)
{
    extern __shared__ float sm[];
    float* Qs = sm;
    float* Ks = Qs + 64 * LDQ;
    float* Vs = Ks + 64 * LDQ;
    float* Ps = Vs + 64 * LDQ;

    const int qt = blockIdx.x;
    const int h  = blockIdx.y;
    const int b  = blockIdx.z;
    const int kvh = h >> 2;

    const int tid = threadIdx.x;
    const int ty  = tid >> 4;
    const int tx  = tid & 15;

    const size_t qstride = (size_t)NHQ * HDIM;
    const size_t kstride = (size_t)NKVH * HDIM;
    const float* qbase = gq + (size_t)b * SS * qstride + (size_t)h * HDIM;
    const float* kbase = gk + (size_t)b * SS * kstride + (size_t)kvh * HDIM;
    const float* vbase = gv + (size_t)b * SS * kstride + (size_t)kvh * HDIM;

    const int q0 = qt * 64;

    for (int idx = tid; idx < 64 * 32; idx += 256) {
        int r  = idx >> 5;
        int c4 = (idx & 31) << 2;
        float4 v = *(const float4*)(qbase + (size_t)(q0 + r) * qstride + c4);
        Qs[r * LDQ + c4]     = v.x;
        Qs[r * LDQ + c4 + 1] = v.y;
        Qs[r * LDQ + c4 + 2] = v.z;
        Qs[r * LDQ + c4 + 3] = v.w;
    }

    float acc[4][8];
#pragma unroll
    for (int i = 0; i < 4; i++)
#pragma unroll
        for (int j = 0; j < 8; j++) acc[i][j] = 0.0f;
    float mrow[4], lrow[4];
#pragma unroll
    for (int i = 0; i < 4; i++) { mrow[i] = -1e30f; lrow[i] = 0.0f; }

    const float scale = 0.08838834764831845f;
    const int ntiles = qt + 1;

    for (int t = 0; t < ntiles; t++) {
        const int k0 = t * 64;
        __syncthreads();
        for (int idx = tid; idx < 64 * 32; idx += 256) {
            int r  = idx >> 5;
            int c4 = (idx & 31) << 2;
            float4 kv = *(const float4*)(kbase + (size_t)(k0 + r) * kstride + c4);
            Ks[r * LDQ + c4]     = kv.x;
            Ks[r * LDQ + c4 + 1] = kv.y;
            Ks[r * LDQ + c4 + 2] = kv.z;
            Ks[r * LDQ + c4 + 3] = kv.w;
            float4 vv = *(const float4*)(vbase + (size_t)(k0 + r) * kstride + c4);
            Vs[r * LDQ + c4]     = vv.x;
            Vs[r * LDQ + c4 + 1] = vv.y;
            Vs[r * LDQ + c4 + 2] = vv.z;
            Vs[r * LDQ + c4 + 3] = vv.w;
        }
        __syncthreads();

        float s[4][4];
#pragma unroll
        for (int i = 0; i < 4; i++)
#pragma unroll
            for (int j = 0; j < 4; j++) s[i][j] = 0.0f;

        for (int d = 0; d < HDIM; d++) {
            float qv[4], kv[4];
#pragma unroll
            for (int i = 0; i < 4; i++) qv[i] = Qs[(ty + i * 16) * LDQ + d];
#pragma unroll
            for (int j = 0; j < 4; j++) kv[j] = Ks[(tx + j * 16) * LDQ + d];
#pragma unroll
            for (int i = 0; i < 4; i++)
#pragma unroll
                for (int j = 0; j < 4; j++)
                    s[i][j] = fmaf(qv[i], kv[j], s[i][j]);
        }

#pragma unroll
        for (int i = 0; i < 4; i++)
#pragma unroll
            for (int j = 0; j < 4; j++) s[i][j] *= scale;

        if (t == qt) {
#pragma unroll
            for (int i = 0; i < 4; i++)
#pragma unroll
                for (int j = 0; j < 4; j++)
                    if ((tx + j * 16) > (ty + i * 16)) s[i][j] = -1e30f;
        }

#pragma unroll
        for (int i = 0; i < 4; i++) {
            float mloc = s[i][0];
#pragma unroll
            for (int j = 1; j < 4; j++) mloc = fmaxf(mloc, s[i][j]);
#pragma unroll
            for (int off = 8; off >= 1; off >>= 1)
                mloc = fmaxf(mloc, __shfl_xor_sync(0xffffffffu, mloc, off));
            float mnew = fmaxf(mrow[i], mloc);
            float fac  = __expf(mrow[i] - mnew);
            float psum = 0.0f;
#pragma unroll
            for (int j = 0; j < 4; j++) {
                float p = __expf(s[i][j] - mnew);
                s[i][j] = p;
                psum += p;
            }
#pragma unroll
            for (int off = 8; off >= 1; off >>= 1)
                psum += __shfl_xor_sync(0xffffffffu, psum, off);
            lrow[i] = lrow[i] * fac + psum;
            mrow[i] = mnew;
#pragma unroll
            for (int j = 0; j < 8; j++) acc[i][j] *= fac;
#pragma unroll
            for (int j = 0; j < 4; j++)
                Ps[(ty + i * 16) * LDP + tx + j * 16] = s[i][j];
        }
        __syncthreads();

        for (int kk = 0; kk < 64; kk++) {
            float pv[4], vv[8];
#pragma unroll
            for (int i = 0; i < 4; i++) pv[i] = Ps[(ty + i * 16) * LDP + kk];
#pragma unroll
            for (int j = 0; j < 8; j++) vv[j] = Vs[kk * LDQ + tx + j * 16];
#pragma unroll
            for (int i = 0; i < 4; i++)
#pragma unroll
                for (int j = 0; j < 8; j++)
                    acc[i][j] = fmaf(pv[i], vv[j], acc[i][j]);
        }
    }

    float* obase = gout + (size_t)b * SS * qstride + (size_t)h * HDIM;
#pragma unroll
    for (int i = 0; i < 4; i++) {
        float inv_l = 1.0f / lrow[i];
        int r = ty + i * 16;
        float* op = obase + (size_t)(q0 + r) * qstride;
#pragma unroll
        for (int j = 0; j < 8; j++)
            op[tx + j * 16] = acc[i][j] * inv_l;
    }
}

// ---------------------------------------------------------------------------
extern "C" void kernel_launch(void* const* d_in, const int* in_sizes, int n_in,
                              void* d_out, int out_size)
{
    const float* x  = (const float*)d_in[0];
    const float* Wq = (const float*)d_in[2];
    const float* Wk = (const float*)d_in[3];
    const float* Wv = (const float*)d_in[4];
    const float* Wo = (const float*)d_in[5];
    float* out = (float*)d_out;

    float *q, *k, *v, *attn;
    (void)cudaGetSymbolAddress((void**)&q, g_q);
    (void)cudaGetSymbolAddress((void**)&k, g_k);
    (void)cudaGetSymbolAddress((void**)&v, g_v);
    (void)cudaGetSymbolAddress((void**)&attn, g_attn);

    __nv_bfloat16 *xhi, *xlo, *ahi, *alo;
    __nv_bfloat16 *wqThi, *wqTlo, *wkThi, *wkTlo, *wvThi, *wvTlo, *woThi, *woTlo;
    (void)cudaGetSymbolAddress((void**)&xhi, g_xhi);
    (void)cudaGetSymbolAddress((void**)&xlo, g_xlo);
    (void)cudaGetSymbolAddress((void**)&ahi, g_ahi);
    (void)cudaGetSymbolAddress((void**)&alo, g_alo);
    (void)cudaGetSymbolAddress((void**)&wqThi, g_wqThi);
    (void)cudaGetSymbolAddress((void**)&wqTlo, g_wqTlo);
    (void)cudaGetSymbolAddress((void**)&wkThi, g_wkThi);
    (void)cudaGetSymbolAddress((void**)&wkTlo, g_wkTlo);
    (void)cudaGetSymbolAddress((void**)&wvThi, g_wvThi);
    (void)cudaGetSymbolAddress((void**)&wvTlo, g_wvTlo);
    (void)cudaGetSymbolAddress((void**)&woThi, g_woThi);
    (void)cudaGetSymbolAddress((void**)&woTlo, g_woTlo);

    (void)cudaFuncSetAttribute(attn_kernel,
                               cudaFuncAttributeMaxDynamicSharedMemorySize, ATTN_SMEM);
    (void)cudaFuncSetAttribute(gemm_bf16x3,
                               cudaFuncAttributeMaxDynamicSharedMemorySize, GEMM_DSMEM);

    // 1) split x into bf16 hi/lo
    {
        int n2 = (MM * KK) / 2;
        split_pair<<<(n2 + 255) / 256, 256>>>((const float2*)x,
                                              (__nv_bfloat162*)xhi,
                                              (__nv_bfloat162*)xlo, n2);
    }
    // 2) transpose+split weights -> [N, K] bf16
    transpose_split<<<dim3(NQ / 32, KK / 32), dim3(32, 8)>>>(Wq, wqThi, wqTlo, KK, NQ);
    transpose_split<<<dim3(NKV / 32, KK / 32), dim3(32, 8)>>>(Wk, wkThi, wkTlo, KK, NKV);
    transpose_split<<<dim3(NKV / 32, KK / 32), dim3(32, 8)>>>(Wv, wvThi, wvTlo, KK, NKV);
    transpose_split<<<dim3(NQ / 32, KK / 32), dim3(32, 8)>>>(Wo, woThi, woTlo, KK, NQ);

    // 3) QKV projections on tensor cores (mma.sync bf16x3)
    gemm_bf16x3<<<dim3(NQ / 128, MM / 128), 256, GEMM_DSMEM>>>(xhi, xlo, wqThi, wqTlo, q, NQ);
    gemm_bf16x3<<<dim3(NKV / 128, MM / 128), 256, GEMM_DSMEM>>>(xhi, xlo, wkThi, wkTlo, k, NKV);
    gemm_bf16x3<<<dim3(NKV / 128, MM / 128), 256, GEMM_DSMEM>>>(xhi, xlo, wvThi, wvTlo, v, NKV);

    // 4) RoPE
    {
        int qtot = MM * NHQ * 64;
        int ktot = MM * NKVH * 64;
        rope_kernel<<<(qtot + 255) / 256, 256>>>(q, NHQ, qtot);
        rope_kernel<<<(ktot + 255) / 256, 256>>>(k, NKVH, ktot);
    }

    // 5) attention (fp32)
    attn_kernel<<<dim3(SS / 64, NHQ, BB), 256, ATTN_SMEM>>>(q, k, v, attn);

    // 6) split attn output, 7) output projection on tensor cores
    {
        int n2 = (MM * NQ) / 2;
        split_pair<<<(n2 + 255) / 256, 256>>>((const float2*)attn,
                                              (__nv_bfloat162*)ahi,
                                              (__nv_bfloat162*)alo, n2);
    }
    gemm_bf16x3<<<dim3(NQ / 128, MM / 128), 256, GEMM_DSMEM>>>(ahi, alo, woThi, woTlo, out, NQ);
}

// round 5
// speedup vs baseline: 2.8321x; 1.7391x over previous
#include <cuda_runtime.h>
#include <cuda_bf16.h>
#include <math.h>
#include <stdint.h>

#define BB   2
#define SS   2048
#define DD   2048
#define NHQ  16
#define NKVH 4
#define HDIM 128
#define MM   (BB*SS)       // 4096
#define KK   2048
#define NQ   (NHQ*HDIM)    // 2048
#define NKV  (NKVH*HDIM)   // 512

// ---------------- scratch (device globals; no allocation allowed) ----------
__device__ float g_q[(size_t)MM*NQ];
__device__ float g_k[(size_t)MM*NKV];
__device__ float g_v[(size_t)MM*NKV];

__device__ __nv_bfloat16 g_xhi[(size_t)MM*KK],  g_xlo[(size_t)MM*KK];
__device__ __nv_bfloat16 g_ahi[(size_t)MM*NQ],  g_alo[(size_t)MM*NQ];
__device__ __nv_bfloat16 g_qhi[(size_t)MM*NQ],  g_qlo[(size_t)MM*NQ];
__device__ __nv_bfloat16 g_khi[(size_t)MM*NKV], g_klo[(size_t)MM*NKV];
__device__ __nv_bfloat16 g_vhi[(size_t)MM*NKV], g_vlo[(size_t)MM*NKV];
__device__ __nv_bfloat16 g_wqThi[(size_t)NQ*KK],  g_wqTlo[(size_t)NQ*KK];
__device__ __nv_bfloat16 g_wkThi[(size_t)NKV*KK], g_wkTlo[(size_t)NKV*KK];
__device__ __nv_bfloat16 g_wvThi[(size_t)NKV*KK], g_wvTlo[(size_t)NKV*KK];
__device__ __nv_bfloat16 g_woThi[(size_t)NQ*KK],  g_woTlo[(size_t)NQ*KK];

// ---------------- PTX helpers (sm_80-era: valid on plain sm_103 target) ----
__device__ __forceinline__ uint32_t smem_u32(const void* p) {
    uint32_t a;
    asm("{ .reg .u64 t; cvta.to.shared.u64 t, %1; cvt.u32.u64 %0, t; }"
        : "=r"(a) : "l"(p));
    return a;
}

__device__ __forceinline__ void cp16(uint32_t s, const void* g) {
    asm volatile("cp.async.cg.shared.global [%0], [%1], 16;" :: "r"(s), "l"(g));
}
#define CP_COMMIT() asm volatile("cp.async.commit_group;" ::: "memory")
#define CP_WAIT(n)  asm volatile("cp.async.wait_group %0;" :: "n"(n) : "memory")

__device__ __forceinline__ void ldm_x4(uint32_t& r0, uint32_t& r1,
                                       uint32_t& r2, uint32_t& r3, uint32_t a) {
    asm volatile("ldmatrix.sync.aligned.m8n8.x4.shared.b16 {%0,%1,%2,%3}, [%4];"
                 : "=r"(r0), "=r"(r1), "=r"(r2), "=r"(r3) : "r"(a));
}
__device__ __forceinline__ void ldm_x4_t(uint32_t& r0, uint32_t& r1,
                                         uint32_t& r2, uint32_t& r3, uint32_t a) {
    asm volatile("ldmatrix.sync.aligned.m8n8.x4.trans.shared.b16 {%0,%1,%2,%3}, [%4];"
                 : "=r"(r0), "=r"(r1), "=r"(r2), "=r"(r3) : "r"(a));
}

__device__ __forceinline__ void mma16816(float* c,
    uint32_t a0, uint32_t a1, uint32_t a2, uint32_t a3, uint32_t b0, uint32_t b1)
{
    asm volatile(
        "mma.sync.aligned.m16n8k16.row.col.f32.bf16.bf16.f32 "
        "{%0,%1,%2,%3}, {%4,%5,%6,%7}, {%8,%9}, {%0,%1,%2,%3};"
        : "+f"(c[0]), "+f"(c[1]), "+f"(c[2]), "+f"(c[3])
        : "r"(a0), "r"(a1), "r"(a2), "r"(a3), "r"(b0), "r"(b1));
}

__device__ __forceinline__ uint32_t pack_bf2(float x, float y) {
    __nv_bfloat162 t = __floats2bfloat162_rn(x, y);   // x -> low half
    return *reinterpret_cast<uint32_t*>(&t);
}

// ---------------------------------------------------------------------------
// bf16x3 mma.sync GEMM (unchanged from passing round)
// ---------------------------------------------------------------------------
#define BK        32
#define ROWB      80
#define TILEB     (128 * ROWB)
#define OFF_AHI   0
#define OFF_ALO   (TILEB)
#define OFF_BHI   (2 * TILEB)
#define OFF_BLO   (3 * TILEB)
#define STAGEB    (4 * TILEB)
#define GEMM_DSMEM (2 * STAGEB)
#define NCHUNK    (KK / BK)

__device__ __forceinline__ void load_stage(uint32_t sBase,
    const __nv_bfloat16* Ahi, const __nv_bfloat16* Alo,
    const __nv_bfloat16* Bhi, const __nv_bfloat16* Blo,
    int row0, int col0, int k0, int tid)
{
#pragma unroll
    for (int t = 0; t < 8; t++) {
        int i    = tid + t * 256;
        int tile = i >> 9;
        int w    = i & 511;
        int r    = w >> 2;
        int seg  = w & 3;
        const __nv_bfloat16* src =
            (tile == 0) ? Ahi : (tile == 1) ? Alo : (tile == 2) ? Bhi : Blo;
        int rb = (tile < 2) ? row0 : col0;
        cp16(sBase + tile * TILEB + r * ROWB + seg * 16,
             src + (size_t)(rb + r) * KK + k0 + seg * 8);
    }
}

__device__ __forceinline__ void mma_pass(uint32_t aW, uint32_t bW, int lane,
                                         float acc[4][4][4])
{
#pragma unroll
    for (int ks = 0; ks < 2; ks++) {
        uint32_t A[4][4];
#pragma unroll
        for (int am = 0; am < 4; am++) {
            uint32_t ad = aW + (uint32_t)((am * 16 + (lane & 15)) * ROWB
                        + (ks * 16 + ((lane >> 4) << 3)) * 2);
            ldm_x4(A[am][0], A[am][1], A[am][2], A[am][3], ad);
        }
        uint32_t Bg[2][4];
#pragma unroll
        for (int bn = 0; bn < 2; bn++) {
            uint32_t bd = bW + (uint32_t)((bn * 16 + ((lane >> 4) << 3) + (lane & 7)) * ROWB
                        + (ks * 16 + ((lane >> 3) & 1) * 8) * 2);
            ldm_x4(Bg[bn][0], Bg[bn][1], Bg[bn][2], Bg[bn][3], bd);
        }
#pragma unroll
        for (int am = 0; am < 4; am++)
#pragma unroll
            for (int an = 0; an < 4; an++)
                mma16816(acc[am][an], A[am][0], A[am][1], A[am][2], A[am][3],
                         Bg[an >> 1][(an & 1) * 2], Bg[an >> 1][(an & 1) * 2 + 1]);
    }
}

__global__ __launch_bounds__(256) void gemm_bf16x3(
    const __nv_bfloat16* __restrict__ Ahi, const __nv_bfloat16* __restrict__ Alo,
    const __nv_bfloat16* __restrict__ Bhi, const __nv_bfloat16* __restrict__ Blo,
    float* __restrict__ C, int N)
{
    extern __shared__ char dsm[];
    const uint32_t sBase = smem_u32(dsm);

    const int tid  = threadIdx.x;
    const int lane = tid & 31;
    const int wid  = tid >> 5;
    const int wr   = wid >> 2;
    const int wc   = wid & 3;
    const int row0 = blockIdx.y * 128;
    const int col0 = blockIdx.x * 128;

    float acc[4][4][4];
#pragma unroll
    for (int i = 0; i < 4; i++)
#pragma unroll
        for (int j = 0; j < 4; j++)
#pragma unroll
            for (int l = 0; l < 4; l++) acc[i][j][l] = 0.0f;

    load_stage(sBase, Ahi, Alo, Bhi, Blo, row0, col0, 0, tid);
    CP_COMMIT();

#pragma unroll 1
    for (int c = 0; c < NCHUNK; c++) {
        const uint32_t st = sBase + (uint32_t)(c & 1) * STAGEB;
        if (c + 1 < NCHUNK) {
            load_stage(sBase + (uint32_t)((c + 1) & 1) * STAGEB,
                       Ahi, Alo, Bhi, Blo, row0, col0, (c + 1) * BK, tid);
            CP_COMMIT();
            CP_WAIT(1);
        } else {
            CP_WAIT(0);
        }
        __syncthreads();

        const uint32_t aHiW = st + OFF_AHI + (uint32_t)(wr * 64) * ROWB;
        const uint32_t aLoW = st + OFF_ALO + (uint32_t)(wr * 64) * ROWB;
        const uint32_t bHiW = st + OFF_BHI + (uint32_t)(wc * 32) * ROWB;
        const uint32_t bLoW = st + OFF_BLO + (uint32_t)(wc * 32) * ROWB;
        mma_pass(aHiW, bHiW, lane, acc);
        mma_pass(aHiW, bLoW, lane, acc);
        mma_pass(aLoW, bHiW, lane, acc);
        __syncthreads();
    }

    const int rbase = row0 + wr * 64;
    const int cbase = col0 + wc * 32;
#pragma unroll
    for (int am = 0; am < 4; am++)
#pragma unroll
        for (int an = 0; an < 4; an++) {
            float* cf = acc[am][an];
            int r  = rbase + am * 16 + (lane >> 2);
            int cc = cbase + an * 8 + (lane & 3) * 2;
            *(float2*)(C + (size_t)r * N + cc)       = make_float2(cf[0], cf[1]);
            *(float2*)(C + (size_t)(r + 8) * N + cc) = make_float2(cf[2], cf[3]);
        }
}

// ---------------------------------------------------------------------------
// fp32 -> hi/lo bf16 split (for x and v)
// ---------------------------------------------------------------------------
__global__ void split_pair(const float2* __restrict__ src,
                           __nv_bfloat162* __restrict__ hi,
                           __nv_bfloat162* __restrict__ lo, int n2)
{
    int i = blockIdx.x * blockDim.x + threadIdx.x;
    if (i >= n2) return;
    float2 v = src[i];
    __nv_bfloat16 hx = __float2bfloat16(v.x);
    __nv_bfloat16 hy = __float2bfloat16(v.y);
    hi[i] = __halves2bfloat162(hx, hy);
    lo[i] = __halves2bfloat162(__float2bfloat16(v.x - __bfloat162float(hx)),
                               __float2bfloat16(v.y - __bfloat162float(hy)));
}

// ---------------------------------------------------------------------------
// W [K,N] fp32 -> Wt hi/lo [N,K] bf16 (transpose + split)
// ---------------------------------------------------------------------------
__global__ void transpose_split(const float* __restrict__ src,
                                __nv_bfloat16* __restrict__ hi,
                                __nv_bfloat16* __restrict__ lo, int K, int N)
{
    __shared__ float t[32][33];
    int k0 = blockIdx.y * 32, n0 = blockIdx.x * 32;
    int tx = threadIdx.x, ty = threadIdx.y;
#pragma unroll
    for (int j = 0; j < 32; j += 8)
        t[ty + j][tx] = src[(size_t)(k0 + ty + j) * N + n0 + tx];
    __syncthreads();
#pragma unroll
    for (int j = 0; j < 32; j += 8) {
        float v = t[tx][ty + j];
        __nv_bfloat16 h = __float2bfloat16(v);
        size_t o = (size_t)(n0 + ty + j) * K + k0 + tx;
        hi[o] = h;
        lo[o] = __float2bfloat16(v - __bfloat162float(h));
    }
}

// ---------------------------------------------------------------------------
// RoPE + hi/lo split fused: reads fp32 proj, writes bf16 hi/lo
// ---------------------------------------------------------------------------
__global__ void rope_split(const float* __restrict__ src,
                           __nv_bfloat16* __restrict__ hi,
                           __nv_bfloat16* __restrict__ lo, int nh, int total)
{
    int idx = blockIdx.x * blockDim.x + threadIdx.x;
    if (idx >= total) return;
    int p  = idx & 63;
    int h  = (idx >> 6) % nh;
    int bs = idx / (64 * nh);
    int s  = bs & (SS - 1);

    float e   = (float)(2 * p) * (1.0f / 128.0f);
    float inv = 1.0f / powf(10000.0f, e);
    float fr  = (float)s * inv;
    float sn, c;
    sincosf(fr, &sn, &c);

    size_t off = ((size_t)bs * nh + h) * HDIM + 2 * p;
    float x1 = src[off], x2 = src[off + 1];
    float o1 = x1 * c - x2 * sn;
    float o2 = x1 * sn + x2 * c;
    __nv_bfloat16 h1 = __float2bfloat16(o1), h2 = __float2bfloat16(o2);
    hi[off]     = h1;
    hi[off + 1] = h2;
    lo[off]     = __float2bfloat16(o1 - __bfloat162float(h1));
    lo[off + 1] = __float2bfloat16(o2 - __bfloat162float(h2));
}

// ---------------------------------------------------------------------------
// Flash attention on mma.sync bf16 (hi/lo x3 both GEMMs), causal, GQA 4:1.
// CTA: 128 Q-rows, 64-key tiles, 8 warps (16 rows each), 256 threads.
// Smem: Q hi/lo resident + double-buffered K/V hi/lo tiles, pitch 272 B.
// grid = (S/128, NH, B).
// ---------------------------------------------------------------------------
#define AP      272                       // smem pitch bytes (128 bf16 + 8 pad)
#define QTB     (128 * AP)                // 34816  (one Q matrix)
#define KVTB    (64 * AP)                 // 17408  (one K or V 64-row matrix)
#define KVB     (2 * QTB)                 // KV region base (69632)
#define KVSTG   (4 * KVTB)                // stage stride   (69632)
#define ATTN_SMEM (2 * QTB + 2 * KVSTG)   // 208896

__device__ __forceinline__ void load_kv_tile(uint32_t sb, uint32_t stg,
    const __nv_bfloat16* kh, const __nv_bfloat16* kl,
    const __nv_bfloat16* vh, const __nv_bfloat16* vl, int k0, int tid)
{
#pragma unroll
    for (int t = 0; t < 16; t++) {
        int i  = tid + t * 256;
        int m  = i >> 10;                  // constant per unrolled t
        int w  = i & 1023;
        int r  = w >> 4;
        int sg = w & 15;
        const __nv_bfloat16* src = (m == 0) ? kh : (m == 1) ? kl
                                 : (m == 2) ? vh : vl;
        cp16(sb + stg + (uint32_t)m * KVTB + (uint32_t)(r * AP + sg * 16),
             src + (size_t)(k0 + r) * NKV + sg * 8);
    }
}

__global__ __launch_bounds__(256) void attn_mma(
    const __nv_bfloat16* __restrict__ qhi, const __nv_bfloat16* __restrict__ qlo,
    const __nv_bfloat16* __restrict__ khi, const __nv_bfloat16* __restrict__ klo,
    const __nv_bfloat16* __restrict__ vhi, const __nv_bfloat16* __restrict__ vlo,
    __nv_bfloat16* __restrict__ ohi, __nv_bfloat16* __restrict__ olo)
{
    extern __shared__ char sm[];
    const uint32_t sb = smem_u32(sm);

    const int qt = blockIdx.x;
    const int h  = blockIdx.y;
    const int b  = blockIdx.z;
    const int kvh = h >> 2;
    const int q0  = qt * 128;

    const int tid  = threadIdx.x;
    const int lane = tid & 31;
    const int wid  = tid >> 5;
    const int wq0  = wid * 16;            // warp's q-row base within tile
    const int gr   = lane >> 2;

    const __nv_bfloat16* qhb = qhi + ((size_t)b * SS + q0) * NQ + h * HDIM;
    const __nv_bfloat16* qlb = qlo + ((size_t)b * SS + q0) * NQ + h * HDIM;
    const __nv_bfloat16* khb = khi + (size_t)b * SS * NKV + kvh * HDIM;
    const __nv_bfloat16* klb = klo + (size_t)b * SS * NKV + kvh * HDIM;
    const __nv_bfloat16* vhb = vhi + (size_t)b * SS * NKV + kvh * HDIM;
    const __nv_bfloat16* vlb = vlo + (size_t)b * SS * NKV + kvh * HDIM;

    // Load resident Q hi/lo (4096 x 16B)
#pragma unroll
    for (int t = 0; t < 16; t++) {
        int i   = tid + t * 256;
        int hl  = i >> 11;                 // constant per unrolled t
        int w   = i & 2047;
        int r   = w >> 4;
        int sg  = w & 15;
        const __nv_bfloat16* src = hl ? qlb : qhb;
        cp16(sb + (uint32_t)hl * QTB + (uint32_t)(r * AP + sg * 16),
             src + (size_t)r * NQ + sg * 8);
    }
    load_kv_tile(sb, KVB, khb, klb, vhb, vlb, 0, tid);
    CP_COMMIT();

    float oacc[16][4];
#pragma unroll
    for (int j = 0; j < 16; j++)
#pragma unroll
        for (int e = 0; e < 4; e++) oacc[j][e] = 0.0f;
    float mA = -1e30f, mB = -1e30f, lA = 0.0f, lB = 0.0f;

    const float scale = 0.08838834764831845f;   // 1/sqrt(128)
    const int ntiles = 2 * qt + 2;
    const int rAg = q0 + wq0 + gr;
    const int rBg = rAg + 8;

#pragma unroll 1
    for (int t = 0; t < ntiles; t++) {
        if (t + 1 < ntiles) {
            load_kv_tile(sb, KVB + (uint32_t)((t + 1) & 1) * KVSTG,
                         khb, klb, vhb, vlb, (t + 1) * 64, tid);
            CP_COMMIT();
            CP_WAIT(1);
        } else {
            CP_WAIT(0);
        }
        __syncthreads();

        const uint32_t kv = sb + KVB + (uint32_t)(t & 1) * KVSTG;

        // ---- S = Q @ K^T (3 hi/lo passes) ----
        float sacc[8][4];
#pragma unroll
        for (int j = 0; j < 8; j++)
#pragma unroll
            for (int e = 0; e < 4; e++) sacc[j][e] = 0.0f;

#pragma unroll
        for (int pass = 0; pass < 3; pass++) {
            const uint32_t aB = sb + (pass < 2 ? 0u : QTB) + (uint32_t)wq0 * AP;
            const uint32_t bB = kv + (pass == 1 ? KVTB : 0u);
#pragma unroll
            for (int c = 0; c < 8; c++) {
                uint32_t a0, a1, a2, a3;
                ldm_x4(a0, a1, a2, a3,
                       aB + (uint32_t)((lane & 15) * AP
                          + (c * 16 + ((lane >> 4) << 3)) * 2));
#pragma unroll
                for (int g = 0; g < 4; g++) {
                    uint32_t b0, b1, b2, b3;
                    ldm_x4(b0, b1, b2, b3,
                           bB + (uint32_t)((g * 16 + ((lane >> 4) << 3) + (lane & 7)) * AP
                              + (c * 16 + ((lane >> 3) & 1) * 8) * 2));
                    mma16816(sacc[2 * g],     a0, a1, a2, a3, b0, b1);
                    mma16816(sacc[2 * g + 1], a0, a1, a2, a3, b2, b3);
                }
            }
        }

        // ---- scale + causal mask ----
#pragma unroll
        for (int j = 0; j < 8; j++)
#pragma unroll
            for (int e = 0; e < 4; e++) sacc[j][e] *= scale;

        if (t >= 2 * qt) {
#pragma unroll
            for (int j = 0; j < 8; j++) {
                int col = t * 64 + j * 8 + 2 * (lane & 3);
                if (col     > rAg) sacc[j][0] = -1e30f;
                if (col + 1 > rAg) sacc[j][1] = -1e30f;
                if (col     > rBg) sacc[j][2] = -1e30f;
                if (col + 1 > rBg) sacc[j][3] = -1e30f;
            }
        }

        // ---- online softmax (two rows per thread: gr, gr+8) ----
        float mxA = -1e30f, mxB = -1e30f;
#pragma unroll
        for (int j = 0; j < 8; j++) {
            mxA = fmaxf(mxA, fmaxf(sacc[j][0], sacc[j][1]));
            mxB = fmaxf(mxB, fmaxf(sacc[j][2], sacc[j][3]));
        }
        mxA = fmaxf(mxA, __shfl_xor_sync(0xffffffffu, mxA, 1));
        mxA = fmaxf(mxA, __shfl_xor_sync(0xffffffffu, mxA, 2));
        mxB = fmaxf(mxB, __shfl_xor_sync(0xffffffffu, mxB, 1));
        mxB = fmaxf(mxB, __shfl_xor_sync(0xffffffffu, mxB, 2));

        float mnA = fmaxf(mA, mxA), mnB = fmaxf(mB, mxB);
        float facA = __expf(mA - mnA), facB = __expf(mB - mnB);
        float sA = 0.0f, sB = 0.0f;
#pragma unroll
        for (int j = 0; j < 8; j++) {
            float p0 = __expf(sacc[j][0] - mnA);
            float p1 = __expf(sacc[j][1] - mnA);
            float p2 = __expf(sacc[j][2] - mnB);
            float p3 = __expf(sacc[j][3] - mnB);
            sacc[j][0] = p0; sacc[j][1] = p1; sacc[j][2] = p2; sacc[j][3] = p3;
            sA += p0 + p1; sB += p2 + p3;
        }
        sA += __shfl_xor_sync(0xffffffffu, sA, 1);
        sA += __shfl_xor_sync(0xffffffffu, sA, 2);
        sB += __shfl_xor_sync(0xffffffffu, sB, 1);
        sB += __shfl_xor_sync(0xffffffffu, sB, 2);
        lA = lA * facA + sA; lB = lB * facB + sB;
        mA = mnA; mB = mnB;
#pragma unroll
        for (int j = 0; j < 16; j++) {
            oacc[j][0] *= facA; oacc[j][1] *= facA;
            oacc[j][2] *= facB; oacc[j][3] *= facB;
        }

        // ---- O += P @ V (3 hi/lo passes; P repacked in registers) ----
#pragma unroll
        for (int kc = 0; kc < 4; kc++) {
            const int j0 = 2 * kc, j1 = 2 * kc + 1;
            uint32_t phi[4], plo[4];
            {
                float v00 = sacc[j0][0], v01 = sacc[j0][1];
                float v02 = sacc[j0][2], v03 = sacc[j0][3];
                float v10 = sacc[j1][0], v11 = sacc[j1][1];
                float v12 = sacc[j1][2], v13 = sacc[j1][3];
                phi[0] = pack_bf2(v00, v01);
                phi[1] = pack_bf2(v02, v03);
                phi[2] = pack_bf2(v10, v11);
                phi[3] = pack_bf2(v12, v13);
                plo[0] = pack_bf2(v00 - __bfloat162float(__float2bfloat16(v00)),
                                  v01 - __bfloat162float(__float2bfloat16(v01)));
                plo[1] = pack_bf2(v02 - __bfloat162float(__float2bfloat16(v02)),
                                  v03 - __bfloat162float(__float2bfloat16(v03)));
                plo[2] = pack_bf2(v10 - __bfloat162float(__float2bfloat16(v10)),
                                  v11 - __bfloat162float(__float2bfloat16(v11)));
                plo[3] = pack_bf2(v12 - __bfloat162float(__float2bfloat16(v12)),
                                  v13 - __bfloat162float(__float2bfloat16(v13)));
            }
#pragma unroll
            for (int bn = 0; bn < 8; bn++) {
                const uint32_t rowsel =
                    (uint32_t)((kc * 16 + ((lane >> 4) << 3) + (lane & 7)) * AP
                             + (bn * 16 + ((lane >> 3) & 1) * 8) * 2);
                uint32_t r0, r1, r2, r3, s0, s1, s2, s3;
                ldm_x4_t(r0, r1, r2, r3, kv + 2 * KVTB + rowsel);   // Vhi
                ldm_x4_t(s0, s1, s2, s3, kv + 3 * KVTB + rowsel);   // Vlo
                mma16816(oacc[2 * bn],     phi[0], phi[1], phi[2], phi[3], r0, r2);
                mma16816(oacc[2 * bn + 1], phi[0], phi[1], phi[2], phi[3], r1, r3);
                mma16816(oacc[2 * bn],     phi[0], phi[1], phi[2], phi[3], s0, s2);
                mma16816(oacc[2 * bn + 1], phi[0], phi[1], phi[2], phi[3], s1, s3);
                mma16816(oacc[2 * bn],     plo[0], plo[1], plo[2], plo[3], r0, r2);
                mma16816(oacc[2 * bn + 1], plo[0], plo[1], plo[2], plo[3], r1, r3);
            }
        }
        __syncthreads();
    }

    // ---- epilogue: normalize, split to bf16 hi/lo, store ----
    const float invA = 1.0f / lA, invB = 1.0f / lB;
    const size_t rowA = ((size_t)b * SS + rAg) * NQ;
    const size_t rowB = ((size_t)b * SS + rBg) * NQ;
#pragma unroll
    for (int j = 0; j < 16; j++) {
        int col = h * HDIM + j * 8 + 2 * (lane & 3);
        float o0 = oacc[j][0] * invA, o1 = oacc[j][1] * invA;
        float o2 = oacc[j][2] * invB, o3 = oacc[j][3] * invB;
        __nv_bfloat16 h0 = __float2bfloat16(o0), h1 = __float2bfloat16(o1);
        __nv_bfloat16 h2 = __float2bfloat16(o2), h3 = __float2bfloat16(o3);
        *(__nv_bfloat162*)(ohi + rowA + col) = __halves2bfloat162(h0, h1);
        *(__nv_bfloat162*)(ohi + rowB + col) = __halves2bfloat162(h2, h3);
        *(__nv_bfloat162*)(olo + rowA + col) = __halves2bfloat162(
            __float2bfloat16(o0 - __bfloat162float(h0)),
            __float2bfloat16(o1 - __bfloat162float(h1)));
        *(__nv_bfloat162*)(olo + rowB + col) = __halves2bfloat162(
            __float2bfloat16(o2 - __bfloat162float(h2)),
            __float2bfloat16(o3 - __bfloat162float(h3)));
    }
}

// ---------------------------------------------------------------------------
extern "C" void kernel_launch(void* const* d_in, const int* in_sizes, int n_in,
                              void* d_out, int out_size)
{
    const float* x  = (const float*)d_in[0];
    const float* Wq = (const float*)d_in[2];
    const float* Wk = (const float*)d_in[3];
    const float* Wv = (const float*)d_in[4];
    const float* Wo = (const float*)d_in[5];
    float* out = (float*)d_out;

    float *q, *k, *v;
    (void)cudaGetSymbolAddress((void**)&q, g_q);
    (void)cudaGetSymbolAddress((void**)&k, g_k);
    (void)cudaGetSymbolAddress((void**)&v, g_v);

    __nv_bfloat16 *xhi, *xlo, *ahi, *alo, *qh, *ql, *kh, *kl, *vh, *vl;
    __nv_bfloat16 *wqThi, *wqTlo, *wkThi, *wkTlo, *wvThi, *wvTlo, *woThi, *woTlo;
    (void)cudaGetSymbolAddress((void**)&xhi, g_xhi);
    (void)cudaGetSymbolAddress((void**)&xlo, g_xlo);
    (void)cudaGetSymbolAddress((void**)&ahi, g_ahi);
    (void)cudaGetSymbolAddress((void**)&alo, g_alo);
    (void)cudaGetSymbolAddress((void**)&qh, g_qhi);
    (void)cudaGetSymbolAddress((void**)&ql, g_qlo);
    (void)cudaGetSymbolAddress((void**)&kh, g_khi);
    (void)cudaGetSymbolAddress((void**)&kl, g_klo);
    (void)cudaGetSymbolAddress((void**)&vh, g_vhi);
    (void)cudaGetSymbolAddress((void**)&vl, g_vlo);
    (void)cudaGetSymbolAddress((void**)&wqThi, g_wqThi);
    (void)cudaGetSymbolAddress((void**)&wqTlo, g_wqTlo);
    (void)cudaGetSymbolAddress((void**)&wkThi, g_wkThi);
    (void)cudaGetSymbolAddress((void**)&wkTlo, g_wkTlo);
    (void)cudaGetSymbolAddress((void**)&wvThi, g_wvThi);
    (void)cudaGetSymbolAddress((void**)&wvTlo, g_wvTlo);
    (void)cudaGetSymbolAddress((void**)&woThi, g_woThi);
    (void)cudaGetSymbolAddress((void**)&woTlo, g_woTlo);

    (void)cudaFuncSetAttribute(gemm_bf16x3,
                               cudaFuncAttributeMaxDynamicSharedMemorySize, GEMM_DSMEM);
    (void)cudaFuncSetAttribute(attn_mma,
                               cudaFuncAttributeMaxDynamicSharedMemorySize, ATTN_SMEM);

    // 1) split x into bf16 hi/lo
    {
        int n2 = (MM * KK) / 2;
        split_pair<<<(n2 + 255) / 256, 256>>>((const float2*)x,
                                              (__nv_bfloat162*)xhi,
                                              (__nv_bfloat162*)xlo, n2);
    }
    // 2) transpose+split weights -> [N, K] bf16
    transpose_split<<<dim3(NQ / 32, KK / 32), dim3(32, 8)>>>(Wq, wqThi, wqTlo, KK, NQ);
    transpose_split<<<dim3(NKV / 32, KK / 32), dim3(32, 8)>>>(Wk, wkThi, wkTlo, KK, NKV);
    transpose_split<<<dim3(NKV / 32, KK / 32), dim3(32, 8)>>>(Wv, wvThi, wvTlo, KK, NKV);
    transpose_split<<<dim3(NQ / 32, KK / 32), dim3(32, 8)>>>(Wo, woThi, woTlo, KK, NQ);

    // 3) QKV projections (tensor cores, bf16x3)
    gemm_bf16x3<<<dim3(NQ / 128, MM / 128), 256, GEMM_DSMEM>>>(xhi, xlo, wqThi, wqTlo, q, NQ);
    gemm_bf16x3<<<dim3(NKV / 128, MM / 128), 256, GEMM_DSMEM>>>(xhi, xlo, wkThi, wkTlo, k, NKV);
    gemm_bf16x3<<<dim3(NKV / 128, MM / 128), 256, GEMM_DSMEM>>>(xhi, xlo, wvThi, wvTlo, v, NKV);

    // 4) RoPE fused with hi/lo split; V plain split
    {
        int qtot = MM * NHQ * 64;
        int ktot = MM * NKVH * 64;
        rope_split<<<(qtot + 255) / 256, 256>>>(q, qh, ql, NHQ, qtot);
        rope_split<<<(ktot + 255) / 256, 256>>>(k, kh, kl, NKVH, ktot);
        int n2 = (MM * NKV) / 2;
        split_pair<<<(n2 + 255) / 256, 256>>>((const float2*)v,
                                              (__nv_bfloat162*)vh,
                                              (__nv_bfloat162*)vl, n2);
    }

    // 5) attention (tensor cores, hi/lo x3 both GEMMs); writes ahi/alo directly
    attn_mma<<<dim3(SS / 128, NHQ, BB), 256, ATTN_SMEM>>>(qh, ql, kh, kl, vh, vl, ahi, alo);

    // 6) output projection (tensor cores, bf16x3)
    gemm_bf16x3<<<dim3(NQ / 128, MM / 128), 256, GEMM_DSMEM>>>(ahi, alo, woThi, woTlo, out, NQ);
}

// round 6
// speedup vs baseline: 3.3874x; 1.1961x over previous
#include <cuda_runtime.h>
#include <cuda_bf16.h>
#include <math.h>
#include <stdint.h>

#define BB   2
#define SS   2048
#define DD   2048
#define NHQ  16
#define NKVH 4
#define HDIM 128
#define MM   (BB*SS)       // 4096
#define KK   2048
#define NQ   (NHQ*HDIM)    // 2048
#define NKV  (NKVH*HDIM)   // 512

// ---------------- scratch (device globals; no allocation allowed) ----------
__device__ __nv_bfloat16 g_xhi[(size_t)MM*KK],  g_xlo[(size_t)MM*KK];
__device__ __nv_bfloat16 g_ahi[(size_t)MM*NQ],  g_alo[(size_t)MM*NQ];
__device__ __nv_bfloat16 g_qhi[(size_t)MM*NQ],  g_qlo[(size_t)MM*NQ];
__device__ __nv_bfloat16 g_khi[(size_t)MM*NKV], g_klo[(size_t)MM*NKV];
__device__ __nv_bfloat16 g_vhi[(size_t)MM*NKV], g_vlo[(size_t)MM*NKV];
__device__ __nv_bfloat16 g_wqThi[(size_t)NQ*KK],  g_wqTlo[(size_t)NQ*KK];
__device__ __nv_bfloat16 g_wkThi[(size_t)NKV*KK], g_wkTlo[(size_t)NKV*KK];
__device__ __nv_bfloat16 g_wvThi[(size_t)NKV*KK], g_wvTlo[(size_t)NKV*KK];
__device__ __nv_bfloat16 g_woThi[(size_t)NQ*KK],  g_woTlo[(size_t)NQ*KK];
__device__ float2 g_rope[(size_t)SS*64];          // (cos, sin) per (s, pair)

// ---------------- PTX helpers (sm_80-era: valid on plain sm_103 target) ----
__device__ __forceinline__ uint32_t smem_u32(const void* p) {
    uint32_t a;
    asm("{ .reg .u64 t; cvta.to.shared.u64 t, %1; cvt.u32.u64 %0, t; }"
        : "=r"(a) : "l"(p));
    return a;
}

__device__ __forceinline__ void cp16(uint32_t s, const void* g) {
    asm volatile("cp.async.cg.shared.global [%0], [%1], 16;" :: "r"(s), "l"(g));
}
#define CP_COMMIT() asm volatile("cp.async.commit_group;" ::: "memory")
#define CP_WAIT(n)  asm volatile("cp.async.wait_group %0;" :: "n"(n) : "memory")

__device__ __forceinline__ void ldm_x4(uint32_t& r0, uint32_t& r1,
                                       uint32_t& r2, uint32_t& r3, uint32_t a) {
    asm volatile("ldmatrix.sync.aligned.m8n8.x4.shared.b16 {%0,%1,%2,%3}, [%4];"
                 : "=r"(r0), "=r"(r1), "=r"(r2), "=r"(r3) : "r"(a));
}
__device__ __forceinline__ void ldm_x4_t(uint32_t& r0, uint32_t& r1,
                                         uint32_t& r2, uint32_t& r3, uint32_t a) {
    asm volatile("ldmatrix.sync.aligned.m8n8.x4.trans.shared.b16 {%0,%1,%2,%3}, [%4];"
                 : "=r"(r0), "=r"(r1), "=r"(r2), "=r"(r3) : "r"(a));
}

__device__ __forceinline__ void mma16816(float* c,
    uint32_t a0, uint32_t a1, uint32_t a2, uint32_t a3, uint32_t b0, uint32_t b1)
{
    asm volatile(
        "mma.sync.aligned.m16n8k16.row.col.f32.bf16.bf16.f32 "
        "{%0,%1,%2,%3}, {%4,%5,%6,%7}, {%8,%9}, {%0,%1,%2,%3};"
        : "+f"(c[0]), "+f"(c[1]), "+f"(c[2]), "+f"(c[3])
        : "r"(a0), "r"(a1), "r"(a2), "r"(a3), "r"(b0), "r"(b1));
}

__device__ __forceinline__ uint32_t pack_bf2(float x, float y) {
    __nv_bfloat162 t = __floats2bfloat162_rn(x, y);
    return *reinterpret_cast<uint32_t*>(&t);
}

__device__ __forceinline__ void store_hilo(__nv_bfloat16* hi, __nv_bfloat16* lo,
                                           size_t off, float a, float b)
{
    __nv_bfloat16 ha = __float2bfloat16(a), hb = __float2bfloat16(b);
    *(__nv_bfloat162*)(hi + off) = __halves2bfloat162(ha, hb);
    *(__nv_bfloat162*)(lo + off) = __halves2bfloat162(
        __float2bfloat16(a - __bfloat162float(ha)),
        __float2bfloat16(b - __bfloat162float(hb)));
}

// ---------------------------------------------------------------------------
// bf16x3 mma.sync GEMM with fused epilogues.
// MODE 0: fp32 C.  MODE 1: bf16 hi/lo split.  MODE 2: RoPE (table) + split.
// ---------------------------------------------------------------------------
#define BK        32
#define ROWB      80
#define TILEB     (128 * ROWB)
#define OFF_AHI   0
#define OFF_ALO   (TILEB)
#define OFF_BHI   (2 * TILEB)
#define OFF_BLO   (3 * TILEB)
#define STAGEB    (4 * TILEB)
#define GEMM_DSMEM (2 * STAGEB)
#define NCHUNK    (KK / BK)

__device__ __forceinline__ void load_stage(uint32_t sBase,
    const __nv_bfloat16* Ahi, const __nv_bfloat16* Alo,
    const __nv_bfloat16* Bhi, const __nv_bfloat16* Blo,
    int row0, int col0, int k0, int tid)
{
#pragma unroll
    for (int t = 0; t < 8; t++) {
        int i    = tid + t * 256;
        int tile = i >> 9;
        int w    = i & 511;
        int r    = w >> 2;
        int seg  = w & 3;
        const __nv_bfloat16* src =
            (tile == 0) ? Ahi : (tile == 1) ? Alo : (tile == 2) ? Bhi : Blo;
        int rb = (tile < 2) ? row0 : col0;
        cp16(sBase + tile * TILEB + r * ROWB + seg * 16,
             src + (size_t)(rb + r) * KK + k0 + seg * 8);
    }
}

template<int MODE>
__global__ __launch_bounds__(256) void gemm_bf16x3(
    const __nv_bfloat16* __restrict__ Ahi, const __nv_bfloat16* __restrict__ Alo,
    const __nv_bfloat16* __restrict__ Bhi, const __nv_bfloat16* __restrict__ Blo,
    float* __restrict__ C,
    __nv_bfloat16* __restrict__ Ohi, __nv_bfloat16* __restrict__ Olo,
    const float2* __restrict__ rope, int N)
{
    extern __shared__ char dsm[];
    const uint32_t sBase = smem_u32(dsm);

    const int tid  = threadIdx.x;
    const int lane = tid & 31;
    const int wid  = tid >> 5;
    const int wr   = wid >> 2;
    const int wc   = wid & 3;
    const int row0 = blockIdx.y * 128;
    const int col0 = blockIdx.x * 128;

    float acc[4][4][4];
#pragma unroll
    for (int i = 0; i < 4; i++)
#pragma unroll
        for (int j = 0; j < 4; j++)
#pragma unroll
            for (int l = 0; l < 4; l++) acc[i][j][l] = 0.0f;

    load_stage(sBase, Ahi, Alo, Bhi, Blo, row0, col0, 0, tid);
    CP_COMMIT();

#pragma unroll 1
    for (int c = 0; c < NCHUNK; c++) {
        const uint32_t st = sBase + (uint32_t)(c & 1) * STAGEB;
        if (c + 1 < NCHUNK) {
            load_stage(sBase + (uint32_t)((c + 1) & 1) * STAGEB,
                       Ahi, Alo, Bhi, Blo, row0, col0, (c + 1) * BK, tid);
            CP_COMMIT();
            CP_WAIT(1);
        } else {
            CP_WAIT(0);
        }
        __syncthreads();

        const uint32_t aHiW = st + OFF_AHI + (uint32_t)(wr * 64) * ROWB;
        const uint32_t aLoW = st + OFF_ALO + (uint32_t)(wr * 64) * ROWB;
        const uint32_t bHiW = st + OFF_BHI + (uint32_t)(wc * 32) * ROWB;
        const uint32_t bLoW = st + OFF_BLO + (uint32_t)(wc * 32) * ROWB;

#pragma unroll
        for (int ks = 0; ks < 2; ks++) {
            const uint32_t aoff = (uint32_t)((lane & 15) * ROWB
                                + (ks * 16 + ((lane >> 4) << 3)) * 2);
            uint32_t AH[4][4], AL[4][4];
#pragma unroll
            for (int am = 0; am < 4; am++) {
                ldm_x4(AH[am][0], AH[am][1], AH[am][2], AH[am][3],
                       aHiW + (uint32_t)(am * 16) * ROWB + aoff);
                ldm_x4(AL[am][0], AL[am][1], AL[am][2], AL[am][3],
                       aLoW + (uint32_t)(am * 16) * ROWB + aoff);
            }
            const uint32_t boff = (uint32_t)((((lane >> 4) << 3) + (lane & 7)) * ROWB
                                + (ks * 16 + ((lane >> 3) & 1) * 8) * 2);
            uint32_t BH[2][4], BL[2][4];
#pragma unroll
            for (int bn = 0; bn < 2; bn++) {
                ldm_x4(BH[bn][0], BH[bn][1], BH[bn][2], BH[bn][3],
                       bHiW + (uint32_t)(bn * 16) * ROWB + boff);
                ldm_x4(BL[bn][0], BL[bn][1], BL[bn][2], BL[bn][3],
                       bLoW + (uint32_t)(bn * 16) * ROWB + boff);
            }
#pragma unroll
            for (int am = 0; am < 4; am++)
#pragma unroll
                for (int an = 0; an < 4; an++) {
                    uint32_t b0h = BH[an >> 1][(an & 1) * 2];
                    uint32_t b1h = BH[an >> 1][(an & 1) * 2 + 1];
                    uint32_t b0l = BL[an >> 1][(an & 1) * 2];
                    uint32_t b1l = BL[an >> 1][(an & 1) * 2 + 1];
                    mma16816(acc[am][an], AH[am][0], AH[am][1], AH[am][2], AH[am][3], b0h, b1h);
                    mma16816(acc[am][an], AH[am][0], AH[am][1], AH[am][2], AH[am][3], b0l, b1l);
                    mma16816(acc[am][an], AL[am][0], AL[am][1], AL[am][2], AL[am][3], b0h, b1h);
                }
        }
        __syncthreads();
    }

    const int rbase = row0 + wr * 64;
    const int cbase = col0 + wc * 32;
#pragma unroll
    for (int am = 0; am < 4; am++)
#pragma unroll
        for (int an = 0; an < 4; an++) {
            float* cf = acc[am][an];
            int r  = rbase + am * 16 + (lane >> 2);
            int cc = cbase + an * 8 + (lane & 3) * 2;
            if (MODE == 0) {
                *(float2*)(C + (size_t)r * N + cc)       = make_float2(cf[0], cf[1]);
                *(float2*)(C + (size_t)(r + 8) * N + cc) = make_float2(cf[2], cf[3]);
            } else if (MODE == 1) {
                store_hilo(Ohi, Olo, (size_t)r * N + cc,       cf[0], cf[1]);
                store_hilo(Ohi, Olo, (size_t)(r + 8) * N + cc, cf[2], cf[3]);
            } else {
                int p = (cc & 127) >> 1;
                float2 cs0 = rope[(size_t)(r & (SS - 1)) * 64 + p];
                float2 cs1 = rope[(size_t)((r + 8) & (SS - 1)) * 64 + p];
                float o0 = cf[0] * cs0.x - cf[1] * cs0.y;
                float o1 = cf[0] * cs0.y + cf[1] * cs0.x;
                float o2 = cf[2] * cs1.x - cf[3] * cs1.y;
                float o3 = cf[2] * cs1.y + cf[3] * cs1.x;
                store_hilo(Ohi, Olo, (size_t)r * N + cc,       o0, o1);
                store_hilo(Ohi, Olo, (size_t)(r + 8) * N + cc, o2, o3);
            }
        }
}

// ---------------------------------------------------------------------------
// rope table: (cos, sin) for (s, pair)
// ---------------------------------------------------------------------------
__global__ void rope_table(float2* __restrict__ t)
{
    int i = blockIdx.x * 256 + threadIdx.x;      // SS*64 total
    if (i >= SS * 64) return;
    int s = i >> 6, p = i & 63;
    float e   = (float)(2 * p) * (1.0f / 128.0f);
    float inv = 1.0f / powf(10000.0f, e);
    float sn, c;
    sincosf((float)s * inv, &sn, &c);
    t[i] = make_float2(c, sn);
}

// ---------------------------------------------------------------------------
// fp32 -> hi/lo bf16 split (x only)
// ---------------------------------------------------------------------------
__global__ void split_pair(const float2* __restrict__ src,
                           __nv_bfloat162* __restrict__ hi,
                           __nv_bfloat162* __restrict__ lo, int n2)
{
    int i = blockIdx.x * blockDim.x + threadIdx.x;
    if (i >= n2) return;
    float2 v = src[i];
    __nv_bfloat16 hx = __float2bfloat16(v.x);
    __nv_bfloat16 hy = __float2bfloat16(v.y);
    hi[i] = __halves2bfloat162(hx, hy);
    lo[i] = __halves2bfloat162(__float2bfloat16(v.x - __bfloat162float(hx)),
                               __float2bfloat16(v.y - __bfloat162float(hy)));
}

// ---------------------------------------------------------------------------
// W [K,N] fp32 -> Wt hi/lo [N,K] bf16 (transpose + split)
// ---------------------------------------------------------------------------
__global__ void transpose_split(const float* __restrict__ src,
                                __nv_bfloat16* __restrict__ hi,
                                __nv_bfloat16* __restrict__ lo, int K, int N)
{
    __shared__ float t[32][33];
    int k0 = blockIdx.y * 32, n0 = blockIdx.x * 32;
    int tx = threadIdx.x, ty = threadIdx.y;
#pragma unroll
    for (int j = 0; j < 32; j += 8)
        t[ty + j][tx] = src[(size_t)(k0 + ty + j) * N + n0 + tx];
    __syncthreads();
#pragma unroll
    for (int j = 0; j < 32; j += 8) {
        float v = t[tx][ty + j];
        __nv_bfloat16 h = __float2bfloat16(v);
        size_t o = (size_t)(n0 + ty + j) * K + k0 + tx;
        hi[o] = h;
        lo[o] = __float2bfloat16(v - __bfloat162float(h));
    }
}

// ---------------------------------------------------------------------------
// Flash attention on mma.sync bf16 (hi/lo x3), causal, GQA 4:1.
// 1-D LPT grid: large-qt CTAs dispatch first.
// ---------------------------------------------------------------------------
#define AP      272
#define QTB     (128 * AP)
#define KVTB    (64 * AP)
#define KVB     (2 * QTB)
#define KVSTG   (4 * KVTB)
#define ATTN_SMEM (2 * QTB + 2 * KVSTG)

__device__ __forceinline__ void load_kv_tile(uint32_t sb, uint32_t stg,
    const __nv_bfloat16* kh, const __nv_bfloat16* kl,
    const __nv_bfloat16* vh, const __nv_bfloat16* vl, int k0, int tid)
{
#pragma unroll
    for (int t = 0; t < 16; t++) {
        int i  = tid + t * 256;
        int m  = i >> 10;
        int w  = i & 1023;
        int r  = w >> 4;
        int sg = w & 15;
        const __nv_bfloat16* src = (m == 0) ? kh : (m == 1) ? kl
                                 : (m == 2) ? vh : vl;
        cp16(sb + stg + (uint32_t)m * KVTB + (uint32_t)(r * AP + sg * 16),
             src + (size_t)(k0 + r) * NKV + sg * 8);
    }
}

__global__ __launch_bounds__(256) void attn_mma(
    const __nv_bfloat16* __restrict__ qhi, const __nv_bfloat16* __restrict__ qlo,
    const __nv_bfloat16* __restrict__ khi, const __nv_bfloat16* __restrict__ klo,
    const __nv_bfloat16* __restrict__ vhi, const __nv_bfloat16* __restrict__ vlo,
    __nv_bfloat16* __restrict__ ohi, __nv_bfloat16* __restrict__ olo)
{
    extern __shared__ char sm[];
    const uint32_t sb = smem_u32(sm);

    // LPT decode: big qt first in dispatch order
    const int bid = blockIdx.x;
    const int qt  = (SS / 128 - 1) - (bid >> 5);
    const int hb  = bid & 31;
    const int h   = hb & 15;
    const int b   = hb >> 4;
    const int kvh = h >> 2;
    const int q0  = qt * 128;

    const int tid  = threadIdx.x;
    const int lane = tid & 31;
    const int wid  = tid >> 5;
    const int wq0  = wid * 16;
    const int gr   = lane >> 2;

    const __nv_bfloat16* qhb = qhi + ((size_t)b * SS + q0) * NQ + h * HDIM;
    const __nv_bfloat16* qlb = qlo + ((size_t)b * SS + q0) * NQ + h * HDIM;
    const __nv_bfloat16* khb = khi + (size_t)b * SS * NKV + kvh * HDIM;
    const __nv_bfloat16* klb = klo + (size_t)b * SS * NKV + kvh * HDIM;
    const __nv_bfloat16* vhb = vhi + (size_t)b * SS * NKV + kvh * HDIM;
    const __nv_bfloat16* vlb = vlo + (size_t)b * SS * NKV + kvh * HDIM;

#pragma unroll
    for (int t = 0; t < 16; t++) {
        int i   = tid + t * 256;
        int hl  = i >> 11;
        int w   = i & 2047;
        int r   = w >> 4;
        int sg  = w & 15;
        const __nv_bfloat16* src = hl ? qlb : qhb;
        cp16(sb + (uint32_t)hl * QTB + (uint32_t)(r * AP + sg * 16),
             src + (size_t)r * NQ + sg * 8);
    }
    load_kv_tile(sb, KVB, khb, klb, vhb, vlb, 0, tid);
    CP_COMMIT();

    float oacc[16][4];
#pragma unroll
    for (int j = 0; j < 16; j++)
#pragma unroll
        for (int e = 0; e < 4; e++) oacc[j][e] = 0.0f;
    float mA = -1e30f, mB = -1e30f, lA = 0.0f, lB = 0.0f;

    const float scale = 0.08838834764831845f;
    const int ntiles = 2 * qt + 2;
    const int rAg = q0 + wq0 + gr;
    const int rBg = rAg + 8;

#pragma unroll 1
    for (int t = 0; t < ntiles; t++) {
        if (t + 1 < ntiles) {
            load_kv_tile(sb, KVB + (uint32_t)((t + 1) & 1) * KVSTG,
                         khb, klb, vhb, vlb, (t + 1) * 64, tid);
            CP_COMMIT();
            CP_WAIT(1);
        } else {
            CP_WAIT(0);
        }
        __syncthreads();

        const uint32_t kv = sb + KVB + (uint32_t)(t & 1) * KVSTG;

        // ---- S = Q @ K^T (shared-fragment hi/lo x3) ----
        float sacc[8][4];
#pragma unroll
        for (int j = 0; j < 8; j++)
#pragma unroll
            for (int e = 0; e < 4; e++) sacc[j][e] = 0.0f;

        const uint32_t aB = sb + (uint32_t)wq0 * AP;
#pragma unroll
        for (int c = 0; c < 8; c++) {
            const uint32_t ao = (uint32_t)((lane & 15) * AP
                              + (c * 16 + ((lane >> 4) << 3)) * 2);
            uint32_t ah0, ah1, ah2, ah3, al0, al1, al2, al3;
            ldm_x4(ah0, ah1, ah2, ah3, aB + ao);
            ldm_x4(al0, al1, al2, al3, aB + QTB + ao);
#pragma unroll
            for (int g = 0; g < 4; g++) {
                const uint32_t bo = (uint32_t)((g * 16 + ((lane >> 4) << 3) + (lane & 7)) * AP
                                  + (c * 16 + ((lane >> 3) & 1) * 8) * 2);
                uint32_t bh0, bh1, bh2, bh3, bl0, bl1, bl2, bl3;
                ldm_x4(bh0, bh1, bh2, bh3, kv + bo);
                ldm_x4(bl0, bl1, bl2, bl3, kv + KVTB + bo);
                mma16816(sacc[2 * g],     ah0, ah1, ah2, ah3, bh0, bh1);
                mma16816(sacc[2 * g + 1], ah0, ah1, ah2, ah3, bh2, bh3);
                mma16816(sacc[2 * g],     ah0, ah1, ah2, ah3, bl0, bl1);
                mma16816(sacc[2 * g + 1], ah0, ah1, ah2, ah3, bl2, bl3);
                mma16816(sacc[2 * g],     al0, al1, al2, al3, bh0, bh1);
                mma16816(sacc[2 * g + 1], al0, al1, al2, al3, bh2, bh3);
            }
        }

        // ---- scale + causal mask ----
#pragma unroll
        for (int j = 0; j < 8; j++)
#pragma unroll
            for (int e = 0; e < 4; e++) sacc[j][e] *= scale;

        if (t >= 2 * qt) {
#pragma unroll
            for (int j = 0; j < 8; j++) {
                int col = t * 64 + j * 8 + 2 * (lane & 3);
                if (col     > rAg) sacc[j][0] = -1e30f;
                if (col + 1 > rAg) sacc[j][1] = -1e30f;
                if (col     > rBg) sacc[j][2] = -1e30f;
                if (col + 1 > rBg) sacc[j][3] = -1e30f;
            }
        }

        // ---- online softmax ----
        float mxA = -1e30f, mxB = -1e30f;
#pragma unroll
        for (int j = 0; j < 8; j++) {
            mxA = fmaxf(mxA, fmaxf(sacc[j][0], sacc[j][1]));
            mxB = fmaxf(mxB, fmaxf(sacc[j][2], sacc[j][3]));
        }
        mxA = fmaxf(mxA, __shfl_xor_sync(0xffffffffu, mxA, 1));
        mxA = fmaxf(mxA, __shfl_xor_sync(0xffffffffu, mxA, 2));
        mxB = fmaxf(mxB, __shfl_xor_sync(0xffffffffu, mxB, 1));
        mxB = fmaxf(mxB, __shfl_xor_sync(0xffffffffu, mxB, 2));

        float mnA = fmaxf(mA, mxA), mnB = fmaxf(mB, mxB);
        float facA = __expf(mA - mnA), facB = __expf(mB - mnB);
        float sA = 0.0f, sB = 0.0f;
#pragma unroll
        for (int j = 0; j < 8; j++) {
            float p0 = __expf(sacc[j][0] - mnA);
            float p1 = __expf(sacc[j][1] - mnA);
            float p2 = __expf(sacc[j][2] - mnB);
            float p3 = __expf(sacc[j][3] - mnB);
            sacc[j][0] = p0; sacc[j][1] = p1; sacc[j][2] = p2; sacc[j][3] = p3;
            sA += p0 + p1; sB += p2 + p3;
        }
        sA += __shfl_xor_sync(0xffffffffu, sA, 1);
        sA += __shfl_xor_sync(0xffffffffu, sA, 2);
        sB += __shfl_xor_sync(0xffffffffu, sB, 1);
        sB += __shfl_xor_sync(0xffffffffu, sB, 2);
        lA = lA * facA + sA; lB = lB * facB + sB;
        mA = mnA; mB = mnB;
#pragma unroll
        for (int j = 0; j < 16; j++) {
            oacc[j][0] *= facA; oacc[j][1] *= facA;
            oacc[j][2] *= facB; oacc[j][3] *= facB;
        }

        // ---- O += P @ V (hi/lo x3; P repacked in registers) ----
#pragma unroll
        for (int kc = 0; kc < 4; kc++) {
            const int j0 = 2 * kc, j1 = 2 * kc + 1;
            uint32_t phi[4], plo[4];
            {
                float v00 = sacc[j0][0], v01 = sacc[j0][1];
                float v02 = sacc[j0][2], v03 = sacc[j0][3];
                float v10 = sacc[j1][0], v11 = sacc[j1][1];
                float v12 = sacc[j1][2], v13 = sacc[j1][3];
                phi[0] = pack_bf2(v00, v01);
                phi[1] = pack_bf2(v02, v03);
                phi[2] = pack_bf2(v10, v11);
                phi[3] = pack_bf2(v12, v13);
                plo[0] = pack_bf2(v00 - __bfloat162float(__float2bfloat16(v00)),
                                  v01 - __bfloat162float(__float2bfloat16(v01)));
                plo[1] = pack_bf2(v02 - __bfloat162float(__float2bfloat16(v02)),
                                  v03 - __bfloat162float(__float2bfloat16(v03)));
                plo[2] = pack_bf2(v10 - __bfloat162float(__float2bfloat16(v10)),
                                  v11 - __bfloat162float(__float2bfloat16(v11)));
                plo[3] = pack_bf2(v12 - __bfloat162float(__float2bfloat16(v12)),
                                  v13 - __bfloat162float(__float2bfloat16(v13)));
            }
#pragma unroll
            for (int bn = 0; bn < 8; bn++) {
                const uint32_t rowsel =
                    (uint32_t)((kc * 16 + ((lane >> 4) << 3) + (lane & 7)) * AP
                             + (bn * 16 + ((lane >> 3) & 1) * 8) * 2);
                uint32_t r0, r1, r2, r3, s0, s1, s2, s3;
                ldm_x4_t(r0, r1, r2, r3, kv + 2 * KVTB + rowsel);   // Vhi
                ldm_x4_t(s0, s1, s2, s3, kv + 3 * KVTB + rowsel);   // Vlo
                mma16816(oacc[2 * bn],     phi[0], phi[1], phi[2], phi[3], r0, r2);
                mma16816(oacc[2 * bn + 1], phi[0], phi[1], phi[2], phi[3], r1, r3);
                mma16816(oacc[2 * bn],     phi[0], phi[1], phi[2], phi[3], s0, s2);
                mma16816(oacc[2 * bn + 1], phi[0], phi[1], phi[2], phi[3], s1, s3);
                mma16816(oacc[2 * bn],     plo[0], plo[1], plo[2], plo[3], r0, r2);
                mma16816(oacc[2 * bn + 1], plo[0], plo[1], plo[2], plo[3], r1, r3);
            }
        }
        __syncthreads();
    }

    // ---- epilogue ----
    const float invA = 1.0f / lA, invB = 1.0f / lB;
    const size_t rowA = ((size_t)b * SS + rAg) * NQ;
    const size_t rowB = ((size_t)b * SS + rBg) * NQ;
#pragma unroll
    for (int j = 0; j < 16; j++) {
        int col = h * HDIM + j * 8 + 2 * (lane & 3);
        store_hilo(ohi, olo, rowA + col, oacc[j][0] * invA, oacc[j][1] * invA);
        store_hilo(ohi, olo, rowB + col, oacc[j][2] * invB, oacc[j][3] * invB);
    }
}

// ---------------------------------------------------------------------------
extern "C" void kernel_launch(void* const* d_in, const int* in_sizes, int n_in,
                              void* d_out, int out_size)
{
    const float* x  = (const float*)d_in[0];
    const float* Wq = (const float*)d_in[2];
    const float* Wk = (const float*)d_in[3];
    const float* Wv = (const float*)d_in[4];
    const float* Wo = (const float*)d_in[5];
    float* out = (float*)d_out;

    __nv_bfloat16 *xhi, *xlo, *ahi, *alo, *qh, *ql, *kh, *kl, *vh, *vl;
    __nv_bfloat16 *wqThi, *wqTlo, *wkThi, *wkTlo, *wvThi, *wvTlo, *woThi, *woTlo;
    float2* rope;
    (void)cudaGetSymbolAddress((void**)&xhi, g_xhi);
    (void)cudaGetSymbolAddress((void**)&xlo, g_xlo);
    (void)cudaGetSymbolAddress((void**)&ahi, g_ahi);
    (void)cudaGetSymbolAddress((void**)&alo, g_alo);
    (void)cudaGetSymbolAddress((void**)&qh, g_qhi);
    (void)cudaGetSymbolAddress((void**)&ql, g_qlo);
    (void)cudaGetSymbolAddress((void**)&kh, g_khi);
    (void)cudaGetSymbolAddress((void**)&kl, g_klo);
    (void)cudaGetSymbolAddress((void**)&vh, g_vhi);
    (void)cudaGetSymbolAddress((void**)&vl, g_vlo);
    (void)cudaGetSymbolAddress((void**)&wqThi, g_wqThi);
    (void)cudaGetSymbolAddress((void**)&wqTlo, g_wqTlo);
    (void)cudaGetSymbolAddress((void**)&wkThi, g_wkThi);
    (void)cudaGetSymbolAddress((void**)&wkTlo, g_wkTlo);
    (void)cudaGetSymbolAddress((void**)&wvThi, g_wvThi);
    (void)cudaGetSymbolAddress((void**)&wvTlo, g_wvTlo);
    (void)cudaGetSymbolAddress((void**)&woThi, g_woThi);
    (void)cudaGetSymbolAddress((void**)&woTlo, g_woTlo);
    (void)cudaGetSymbolAddress((void**)&rope, g_rope);

    (void)cudaFuncSetAttribute(gemm_bf16x3<0>,
                               cudaFuncAttributeMaxDynamicSharedMemorySize, GEMM_DSMEM);
    (void)cudaFuncSetAttribute(gemm_bf16x3<1>,
                               cudaFuncAttributeMaxDynamicSharedMemorySize, GEMM_DSMEM);
    (void)cudaFuncSetAttribute(gemm_bf16x3<2>,
                               cudaFuncAttributeMaxDynamicSharedMemorySize, GEMM_DSMEM);
    (void)cudaFuncSetAttribute(attn_mma,
                               cudaFuncAttributeMaxDynamicSharedMemorySize, ATTN_SMEM);

    // 0) rope table
    rope_table<<<(SS * 64 + 255) / 256, 256>>>(rope);

    // 1) split x into bf16 hi/lo
    {
        int n2 = (MM * KK) / 2;
        split_pair<<<(n2 + 255) / 256, 256>>>((const float2*)x,
                                              (__nv_bfloat162*)xhi,
                                              (__nv_bfloat162*)xlo, n2);
    }
    // 2) transpose+split weights -> [N, K] bf16
    transpose_split<<<dim3(NQ / 32, KK / 32), dim3(32, 8)>>>(Wq, wqThi, wqTlo, KK, NQ);
    transpose_split<<<dim3(NKV / 32, KK / 32), dim3(32, 8)>>>(Wk, wkThi, wkTlo, KK, NKV);
    transpose_split<<<dim3(NKV / 32, KK / 32), dim3(32, 8)>>>(Wv, wvThi, wvTlo, KK, NKV);
    transpose_split<<<dim3(NQ / 32, KK / 32), dim3(32, 8)>>>(Wo, woThi, woTlo, KK, NQ);

    // 3) projections with fused epilogues: Q,K rope+split; V split
    gemm_bf16x3<2><<<dim3(NQ / 128, MM / 128), 256, GEMM_DSMEM>>>(
        xhi, xlo, wqThi, wqTlo, nullptr, qh, ql, rope, NQ);
    gemm_bf16x3<2><<<dim3(NKV / 128, MM / 128), 256, GEMM_DSMEM>>>(
        xhi, xlo, wkThi, wkTlo, nullptr, kh, kl, rope, NKV);
    gemm_bf16x3<1><<<dim3(NKV / 128, MM / 128), 256, GEMM_DSMEM>>>(
        xhi, xlo, wvThi, wvTlo, nullptr, vh, vl, nullptr, NKV);

    // 4) attention (LPT 1-D grid)
    attn_mma<<<(SS / 128) * NHQ * BB, 256, ATTN_SMEM>>>(qh, ql, kh, kl, vh, vl, ahi, alo);

    // 5) output projection -> fp32 out
    gemm_bf16x3<0><<<dim3(NQ / 128, MM / 128), 256, GEMM_DSMEM>>>(
        ahi, alo, woThi, woTlo, out, nullptr, nullptr, nullptr, NQ);
}

// round 7
// speedup vs baseline: 3.5606x; 1.0512x over previous
#include <cuda_runtime.h>
#include <cuda_bf16.h>
#include <math.h>
#include <stdint.h>

#define BB   2
#define SS   2048
#define DD   2048
#define NHQ  16
#define NKVH 4
#define HDIM 128
#define MM   (BB*SS)       // 4096
#define KK   2048
#define NQ   (NHQ*HDIM)    // 2048
#define NKV  (NKVH*HDIM)   // 512

// ---------------- scratch (device globals; no allocation allowed) ----------
__device__ __nv_bfloat16 g_xhi[(size_t)MM*KK],  g_xlo[(size_t)MM*KK];
__device__ __nv_bfloat16 g_ahi[(size_t)MM*NQ],  g_alo[(size_t)MM*NQ];
__device__ __nv_bfloat16 g_qhi[(size_t)MM*NQ],  g_qlo[(size_t)MM*NQ];
__device__ __nv_bfloat16 g_khi[(size_t)MM*NKV], g_klo[(size_t)MM*NKV];
__device__ __nv_bfloat16 g_vhi[(size_t)MM*NKV], g_vlo[(size_t)MM*NKV];
__device__ __nv_bfloat16 g_wqThi[(size_t)NQ*KK],  g_wqTlo[(size_t)NQ*KK];
__device__ __nv_bfloat16 g_wkThi[(size_t)NKV*KK], g_wkTlo[(size_t)NKV*KK];
__device__ __nv_bfloat16 g_wvThi[(size_t)NKV*KK], g_wvTlo[(size_t)NKV*KK];
__device__ __nv_bfloat16 g_woThi[(size_t)NQ*KK],  g_woTlo[(size_t)NQ*KK];
__device__ float2 g_rope[(size_t)SS*64];          // (cos, sin) per (s, pair)

// ---------------- PTX helpers (sm_80-era: valid on plain sm_103 target) ----
__device__ __forceinline__ uint32_t smem_u32(const void* p) {
    uint32_t a;
    asm("{ .reg .u64 t; cvta.to.shared.u64 t, %1; cvt.u32.u64 %0, t; }"
        : "=r"(a) : "l"(p));
    return a;
}

__device__ __forceinline__ void cp16(uint32_t s, const void* g) {
    asm volatile("cp.async.cg.shared.global [%0], [%1], 16;" :: "r"(s), "l"(g));
}
#define CP_COMMIT() asm volatile("cp.async.commit_group;" ::: "memory")
#define CP_WAIT(n)  asm volatile("cp.async.wait_group %0;" :: "n"(n) : "memory")

__device__ __forceinline__ void ldm_x4(uint32_t& r0, uint32_t& r1,
                                       uint32_t& r2, uint32_t& r3, uint32_t a) {
    asm volatile("ldmatrix.sync.aligned.m8n8.x4.shared.b16 {%0,%1,%2,%3}, [%4];"
                 : "=r"(r0), "=r"(r1), "=r"(r2), "=r"(r3) : "r"(a));
}
__device__ __forceinline__ void ldm_x4_t(uint32_t& r0, uint32_t& r1,
                                         uint32_t& r2, uint32_t& r3, uint32_t a) {
    asm volatile("ldmatrix.sync.aligned.m8n8.x4.trans.shared.b16 {%0,%1,%2,%3}, [%4];"
                 : "=r"(r0), "=r"(r1), "=r"(r2), "=r"(r3) : "r"(a));
}

__device__ __forceinline__ void mma16816(float* c,
    uint32_t a0, uint32_t a1, uint32_t a2, uint32_t a3, uint32_t b0, uint32_t b1)
{
    asm volatile(
        "mma.sync.aligned.m16n8k16.row.col.f32.bf16.bf16.f32 "
        "{%0,%1,%2,%3}, {%4,%5,%6,%7}, {%8,%9}, {%0,%1,%2,%3};"
        : "+f"(c[0]), "+f"(c[1]), "+f"(c[2]), "+f"(c[3])
        : "r"(a0), "r"(a1), "r"(a2), "r"(a3), "r"(b0), "r"(b1));
}

__device__ __forceinline__ uint32_t pack_bf2(float x, float y) {
    __nv_bfloat162 t = __floats2bfloat162_rn(x, y);
    return *reinterpret_cast<uint32_t*>(&t);
}

__device__ __forceinline__ void store_hilo(__nv_bfloat16* hi, __nv_bfloat16* lo,
                                           size_t off, float a, float b)
{
    __nv_bfloat16 ha = __float2bfloat16(a), hb = __float2bfloat16(b);
    *(__nv_bfloat162*)(hi + off) = __halves2bfloat162(ha, hb);
    *(__nv_bfloat162*)(lo + off) = __halves2bfloat162(
        __float2bfloat16(a - __bfloat162float(ha)),
        __float2bfloat16(b - __bfloat162float(hb)));
}

// ---------------------------------------------------------------------------
// Shared GEMM machinery (BK=32, pitch 80 B, 2-stage cp.async)
// ---------------------------------------------------------------------------
#define BK        32
#define ROWB      80
#define TILEB     (128 * ROWB)
#define OFF_AHI   0
#define OFF_ALO   (TILEB)
#define OFF_BHI   (2 * TILEB)
#define OFF_BLO   (3 * TILEB)
#define STAGEB    (4 * TILEB)
#define GEMM_DSMEM (2 * STAGEB)
#define NCHUNK    (KK / BK)

__device__ __forceinline__ void load_stage(uint32_t sBase,
    const __nv_bfloat16* Ahi, const __nv_bfloat16* Alo,
    const __nv_bfloat16* Bhi, const __nv_bfloat16* Blo,
    int row0, int col0, int k0, int tid)
{
#pragma unroll
    for (int t = 0; t < 8; t++) {
        int i    = tid + t * 256;
        int tile = i >> 9;
        int w    = i & 511;
        int r    = w >> 2;
        int seg  = w & 3;
        const __nv_bfloat16* src =
            (tile == 0) ? Ahi : (tile == 1) ? Alo : (tile == 2) ? Bhi : Blo;
        int rb = (tile < 2) ? row0 : col0;
        cp16(sBase + tile * TILEB + r * ROWB + seg * 16,
             src + (size_t)(rb + r) * KK + k0 + seg * 8);
    }
}

// mainloop: accumulates the 128x128 tile into acc
__device__ __forceinline__ void gemm_mainloop(uint32_t sBase,
    const __nv_bfloat16* Ahi, const __nv_bfloat16* Alo,
    const __nv_bfloat16* Bhi, const __nv_bfloat16* Blo,
    int row0, int col0, int tid, int lane, int wr, int wc,
    float acc[4][4][4])
{
    load_stage(sBase, Ahi, Alo, Bhi, Blo, row0, col0, 0, tid);
    CP_COMMIT();

#pragma unroll 1
    for (int c = 0; c < NCHUNK; c++) {
        const uint32_t st = sBase + (uint32_t)(c & 1) * STAGEB;
        if (c + 1 < NCHUNK) {
            load_stage(sBase + (uint32_t)((c + 1) & 1) * STAGEB,
                       Ahi, Alo, Bhi, Blo, row0, col0, (c + 1) * BK, tid);
            CP_COMMIT();
            CP_WAIT(1);
        } else {
            CP_WAIT(0);
        }
        __syncthreads();

        const uint32_t aHiW = st + OFF_AHI + (uint32_t)(wr * 64) * ROWB;
        const uint32_t aLoW = st + OFF_ALO + (uint32_t)(wr * 64) * ROWB;
        const uint32_t bHiW = st + OFF_BHI + (uint32_t)(wc * 32) * ROWB;
        const uint32_t bLoW = st + OFF_BLO + (uint32_t)(wc * 32) * ROWB;

#pragma unroll
        for (int ks = 0; ks < 2; ks++) {
            const uint32_t aoff = (uint32_t)((lane & 15) * ROWB
                                + (ks * 16 + ((lane >> 4) << 3)) * 2);
            uint32_t AH[4][4], AL[4][4];
#pragma unroll
            for (int am = 0; am < 4; am++) {
                ldm_x4(AH[am][0], AH[am][1], AH[am][2], AH[am][3],
                       aHiW + (uint32_t)(am * 16) * ROWB + aoff);
                ldm_x4(AL[am][0], AL[am][1], AL[am][2], AL[am][3],
                       aLoW + (uint32_t)(am * 16) * ROWB + aoff);
            }
            const uint32_t boff = (uint32_t)((((lane >> 4) << 3) + (lane & 7)) * ROWB
                                + (ks * 16 + ((lane >> 3) & 1) * 8) * 2);
            uint32_t BH[2][4], BL[2][4];
#pragma unroll
            for (int bn = 0; bn < 2; bn++) {
                ldm_x4(BH[bn][0], BH[bn][1], BH[bn][2], BH[bn][3],
                       bHiW + (uint32_t)(bn * 16) * ROWB + boff);
                ldm_x4(BL[bn][0], BL[bn][1], BL[bn][2], BL[bn][3],
                       bLoW + (uint32_t)(bn * 16) * ROWB + boff);
            }
#pragma unroll
            for (int am = 0; am < 4; am++)
#pragma unroll
                for (int an = 0; an < 4; an++) {
                    uint32_t b0h = BH[an >> 1][(an & 1) * 2];
                    uint32_t b1h = BH[an >> 1][(an & 1) * 2 + 1];
                    uint32_t b0l = BL[an >> 1][(an & 1) * 2];
                    uint32_t b1l = BL[an >> 1][(an & 1) * 2 + 1];
                    mma16816(acc[am][an], AH[am][0], AH[am][1], AH[am][2], AH[am][3], b0h, b1h);
                    mma16816(acc[am][an], AH[am][0], AH[am][1], AH[am][2], AH[am][3], b0l, b1l);
                    mma16816(acc[am][an], AL[am][0], AL[am][1], AL[am][2], AL[am][3], b0h, b1h);
                }
        }
        __syncthreads();
    }
}

// ---------------------------------------------------------------------------
// Fused QKV projection: one launch, 1-D grid of 768 CTAs.
//   bid [0,512):   Q tile  -> rope+split epilogue
//   bid [512,640): K tile  -> rope+split epilogue
//   bid [640,768): V tile  -> plain split epilogue
// ---------------------------------------------------------------------------
__global__ __launch_bounds__(256) void gemm_qkv(
    const __nv_bfloat16* __restrict__ xhi, const __nv_bfloat16* __restrict__ xlo,
    const __nv_bfloat16* __restrict__ wqh, const __nv_bfloat16* __restrict__ wql,
    const __nv_bfloat16* __restrict__ wkh, const __nv_bfloat16* __restrict__ wkl,
    const __nv_bfloat16* __restrict__ wvh, const __nv_bfloat16* __restrict__ wvl,
    __nv_bfloat16* __restrict__ qh, __nv_bfloat16* __restrict__ ql,
    __nv_bfloat16* __restrict__ kh, __nv_bfloat16* __restrict__ kl,
    __nv_bfloat16* __restrict__ vh, __nv_bfloat16* __restrict__ vl,
    const float2* __restrict__ rope)
{
    extern __shared__ char dsm[];
    const uint32_t sBase = smem_u32(dsm);

    const int tid  = threadIdx.x;
    const int lane = tid & 31;
    const int wid  = tid >> 5;
    const int wr   = wid >> 2;
    const int wc   = wid & 3;

    const int bid = blockIdx.x;
    const __nv_bfloat16 *Bh, *Bl;
    __nv_bfloat16 *Oh, *Ol;
    int row0, col0, N, do_rope;
    if (bid < 512) {
        row0 = (bid >> 4) * 128; col0 = (bid & 15) * 128;
        Bh = wqh; Bl = wql; Oh = qh; Ol = ql; N = NQ; do_rope = 1;
    } else if (bid < 640) {
        int i = bid - 512;
        row0 = (i >> 2) * 128; col0 = (i & 3) * 128;
        Bh = wkh; Bl = wkl; Oh = kh; Ol = kl; N = NKV; do_rope = 1;
    } else {
        int i = bid - 640;
        row0 = (i >> 2) * 128; col0 = (i & 3) * 128;
        Bh = wvh; Bl = wvl; Oh = vh; Ol = vl; N = NKV; do_rope = 0;
    }

    float acc[4][4][4];
#pragma unroll
    for (int i = 0; i < 4; i++)
#pragma unroll
        for (int j = 0; j < 4; j++)
#pragma unroll
            for (int l = 0; l < 4; l++) acc[i][j][l] = 0.0f;

    gemm_mainloop(sBase, xhi, xlo, Bh, Bl, row0, col0, tid, lane, wr, wc, acc);

    const int rbase = row0 + wr * 64;
    const int cbase = col0 + wc * 32;
#pragma unroll
    for (int am = 0; am < 4; am++)
#pragma unroll
        for (int an = 0; an < 4; an++) {
            float* cf = acc[am][an];
            int r  = rbase + am * 16 + (lane >> 2);
            int cc = cbase + an * 8 + (lane & 3) * 2;
            if (do_rope) {
                int p = (cc & 127) >> 1;
                float2 cs0 = rope[(size_t)(r & (SS - 1)) * 64 + p];
                float2 cs1 = rope[(size_t)((r + 8) & (SS - 1)) * 64 + p];
                float o0 = cf[0] * cs0.x - cf[1] * cs0.y;
                float o1 = cf[0] * cs0.y + cf[1] * cs0.x;
                float o2 = cf[2] * cs1.x - cf[3] * cs1.y;
                float o3 = cf[2] * cs1.y + cf[3] * cs1.x;
                store_hilo(Oh, Ol, (size_t)r * N + cc,       o0, o1);
                store_hilo(Oh, Ol, (size_t)(r + 8) * N + cc, o2, o3);
            } else {
                store_hilo(Oh, Ol, (size_t)r * N + cc,       cf[0], cf[1]);
                store_hilo(Oh, Ol, (size_t)(r + 8) * N + cc, cf[2], cf[3]);
            }
        }
}

// ---------------------------------------------------------------------------
// O-projection GEMM: fp32 C output
// ---------------------------------------------------------------------------
__global__ __launch_bounds__(256) void gemm_oproj(
    const __nv_bfloat16* __restrict__ Ahi, const __nv_bfloat16* __restrict__ Alo,
    const __nv_bfloat16* __restrict__ Bhi, const __nv_bfloat16* __restrict__ Blo,
    float* __restrict__ C, int N)
{
    extern __shared__ char dsm[];
    const uint32_t sBase = smem_u32(dsm);

    const int tid  = threadIdx.x;
    const int lane = tid & 31;
    const int wid  = tid >> 5;
    const int wr   = wid >> 2;
    const int wc   = wid & 3;
    const int row0 = blockIdx.y * 128;
    const int col0 = blockIdx.x * 128;

    float acc[4][4][4];
#pragma unroll
    for (int i = 0; i < 4; i++)
#pragma unroll
        for (int j = 0; j < 4; j++)
#pragma unroll
            for (int l = 0; l < 4; l++) acc[i][j][l] = 0.0f;

    gemm_mainloop(sBase, Ahi, Alo, Bhi, Blo, row0, col0, tid, lane, wr, wc, acc);

    const int rbase = row0 + wr * 64;
    const int cbase = col0 + wc * 32;
#pragma unroll
    for (int am = 0; am < 4; am++)
#pragma unroll
        for (int an = 0; an < 4; an++) {
            float* cf = acc[am][an];
            int r  = rbase + am * 16 + (lane >> 2);
            int cc = cbase + an * 8 + (lane & 3) * 2;
            *(float2*)(C + (size_t)r * N + cc)       = make_float2(cf[0], cf[1]);
            *(float2*)(C + (size_t)(r + 8) * N + cc) = make_float2(cf[2], cf[3]);
        }
}

// ---------------------------------------------------------------------------
// rope table: (cos, sin) for (s, pair)
// ---------------------------------------------------------------------------
__global__ void rope_table(float2* __restrict__ t)
{
    int i = blockIdx.x * 256 + threadIdx.x;
    if (i >= SS * 64) return;
    int s = i >> 6, p = i & 63;
    float e   = (float)(2 * p) * (1.0f / 128.0f);
    float inv = 1.0f / powf(10000.0f, e);
    float sn, c;
    sincosf((float)s * inv, &sn, &c);
    t[i] = make_float2(c, sn);
}

// ---------------------------------------------------------------------------
// fp32 -> hi/lo bf16 split (x only)
// ---------------------------------------------------------------------------
__global__ void split_pair(const float2* __restrict__ src,
                           __nv_bfloat162* __restrict__ hi,
                           __nv_bfloat162* __restrict__ lo, int n2)
{
    int i = blockIdx.x * blockDim.x + threadIdx.x;
    if (i >= n2) return;
    float2 v = src[i];
    __nv_bfloat16 hx = __float2bfloat16(v.x);
    __nv_bfloat16 hy = __float2bfloat16(v.y);
    hi[i] = __halves2bfloat162(hx, hy);
    lo[i] = __halves2bfloat162(__float2bfloat16(v.x - __bfloat162float(hx)),
                               __float2bfloat16(v.y - __bfloat162float(hy)));
}

// ---------------------------------------------------------------------------
// W [K,N] fp32 -> Wt hi/lo [N,K] bf16 (transpose + split)
// ---------------------------------------------------------------------------
__global__ void transpose_split(const float* __restrict__ src,
                                __nv_bfloat16* __restrict__ hi,
                                __nv_bfloat16* __restrict__ lo, int K, int N)
{
    __shared__ float t[32][33];
    int k0 = blockIdx.y * 32, n0 = blockIdx.x * 32;
    int tx = threadIdx.x, ty = threadIdx.y;
#pragma unroll
    for (int j = 0; j < 32; j += 8)
        t[ty + j][tx] = src[(size_t)(k0 + ty + j) * N + n0 + tx];
    __syncthreads();
#pragma unroll
    for (int j = 0; j < 32; j += 8) {
        float v = t[tx][ty + j];
        __nv_bfloat16 h = __float2bfloat16(v);
        size_t o = (size_t)(n0 + ty + j) * K + k0 + tx;
        hi[o] = h;
        lo[o] = __float2bfloat16(v - __bfloat162float(h));
    }
}

// ---------------------------------------------------------------------------
// Flash attention on mma.sync bf16 (hi/lo x3), causal, GQA 4:1. LPT 1-D grid.
// ---------------------------------------------------------------------------
#define AP      272
#define QTB     (128 * AP)
#define KVTB    (64 * AP)
#define KVB     (2 * QTB)
#define KVSTG   (4 * KVTB)
#define ATTN_SMEM (2 * QTB + 2 * KVSTG)

__device__ __forceinline__ void load_kv_tile(uint32_t sb, uint32_t stg,
    const __nv_bfloat16* kh, const __nv_bfloat16* kl,
    const __nv_bfloat16* vh, const __nv_bfloat16* vl, int k0, int tid)
{
#pragma unroll
    for (int t = 0; t < 16; t++) {
        int i  = tid + t * 256;
        int m  = i >> 10;
        int w  = i & 1023;
        int r  = w >> 4;
        int sg = w & 15;
        const __nv_bfloat16* src = (m == 0) ? kh : (m == 1) ? kl
                                 : (m == 2) ? vh : vl;
        cp16(sb + stg + (uint32_t)m * KVTB + (uint32_t)(r * AP + sg * 16),
             src + (size_t)(k0 + r) * NKV + sg * 8);
    }
}

__global__ __launch_bounds__(256) void attn_mma(
    const __nv_bfloat16* __restrict__ qhi, const __nv_bfloat16* __restrict__ qlo,
    const __nv_bfloat16* __restrict__ khi, const __nv_bfloat16* __restrict__ klo,
    const __nv_bfloat16* __restrict__ vhi, const __nv_bfloat16* __restrict__ vlo,
    __nv_bfloat16* __restrict__ ohi, __nv_bfloat16* __restrict__ olo)
{
    extern __shared__ char sm[];
    const uint32_t sb = smem_u32(sm);

    const int bid = blockIdx.x;
    const int qt  = (SS / 128 - 1) - (bid >> 5);
    const int hb  = bid & 31;
    const int h   = hb & 15;
    const int b   = hb >> 4;
    const int kvh = h >> 2;
    const int q0  = qt * 128;

    const int tid  = threadIdx.x;
    const int lane = tid & 31;
    const int wid  = tid >> 5;
    const int wq0  = wid * 16;
    const int gr   = lane >> 2;

    const __nv_bfloat16* qhb = qhi + ((size_t)b * SS + q0) * NQ + h * HDIM;
    const __nv_bfloat16* qlb = qlo + ((size_t)b * SS + q0) * NQ + h * HDIM;
    const __nv_bfloat16* khb = khi + (size_t)b * SS * NKV + kvh * HDIM;
    const __nv_bfloat16* klb = klo + (size_t)b * SS * NKV + kvh * HDIM;
    const __nv_bfloat16* vhb = vhi + (size_t)b * SS * NKV + kvh * HDIM;
    const __nv_bfloat16* vlb = vlo + (size_t)b * SS * NKV + kvh * HDIM;

#pragma unroll
    for (int t = 0; t < 16; t++) {
        int i   = tid + t * 256;
        int hl  = i >> 11;
        int w   = i & 2047;
        int r   = w >> 4;
        int sg  = w & 15;
        const __nv_bfloat16* src = hl ? qlb : qhb;
        cp16(sb + (uint32_t)hl * QTB + (uint32_t)(r * AP + sg * 16),
             src + (size_t)r * NQ + sg * 8);
    }
    load_kv_tile(sb, KVB, khb, klb, vhb, vlb, 0, tid);
    CP_COMMIT();

    float oacc[16][4];
#pragma unroll
    for (int j = 0; j < 16; j++)
#pragma unroll
        for (int e = 0; e < 4; e++) oacc[j][e] = 0.0f;
    float mA = -1e30f, mB = -1e30f, lA = 0.0f, lB = 0.0f;

    const float scale = 0.08838834764831845f;
    const int ntiles = 2 * qt + 2;
    const int rAg = q0 + wq0 + gr;
    const int rBg = rAg + 8;

#pragma unroll 1
    for (int t = 0; t < ntiles; t++) {
        if (t + 1 < ntiles) {
            load_kv_tile(sb, KVB + (uint32_t)((t + 1) & 1) * KVSTG,
                         khb, klb, vhb, vlb, (t + 1) * 64, tid);
            CP_COMMIT();
            CP_WAIT(1);
        } else {
            CP_WAIT(0);
        }
        __syncthreads();

        const uint32_t kv = sb + KVB + (uint32_t)(t & 1) * KVSTG;

        float sacc[8][4];
#pragma unroll
        for (int j = 0; j < 8; j++)
#pragma unroll
            for (int e = 0; e < 4; e++) sacc[j][e] = 0.0f;

        const uint32_t aB = sb + (uint32_t)wq0 * AP;
#pragma unroll
        for (int c = 0; c < 8; c++) {
            const uint32_t ao = (uint32_t)((lane & 15) * AP
                              + (c * 16 + ((lane >> 4) << 3)) * 2);
            uint32_t ah0, ah1, ah2, ah3, al0, al1, al2, al3;
            ldm_x4(ah0, ah1, ah2, ah3, aB + ao);
            ldm_x4(al0, al1, al2, al3, aB + QTB + ao);
#pragma unroll
            for (int g = 0; g < 4; g++) {
                const uint32_t bo = (uint32_t)((g * 16 + ((lane >> 4) << 3) + (lane & 7)) * AP
                                  + (c * 16 + ((lane >> 3) & 1) * 8) * 2);
                uint32_t bh0, bh1, bh2, bh3, bl0, bl1, bl2, bl3;
                ldm_x4(bh0, bh1, bh2, bh3, kv + bo);
                ldm_x4(bl0, bl1, bl2, bl3, kv + KVTB + bo);
                mma16816(sacc[2 * g],     ah0, ah1, ah2, ah3, bh0, bh1);
                mma16816(sacc[2 * g + 1], ah0, ah1, ah2, ah3, bh2, bh3);
                mma16816(sacc[2 * g],     ah0, ah1, ah2, ah3, bl0, bl1);
                mma16816(sacc[2 * g + 1], ah0, ah1, ah2, ah3, bl2, bl3);
                mma16816(sacc[2 * g],     al0, al1, al2, al3, bh0, bh1);
                mma16816(sacc[2 * g + 1], al0, al1, al2, al3, bh2, bh3);
            }
        }

#pragma unroll
        for (int j = 0; j < 8; j++)
#pragma unroll
            for (int e = 0; e < 4; e++) sacc[j][e] *= scale;

        if (t >= 2 * qt) {
#pragma unroll
            for (int j = 0; j < 8; j++) {
                int col = t * 64 + j * 8 + 2 * (lane & 3);
                if (col     > rAg) sacc[j][0] = -1e30f;
                if (col + 1 > rAg) sacc[j][1] = -1e30f;
                if (col     > rBg) sacc[j][2] = -1e30f;
                if (col + 1 > rBg) sacc[j][3] = -1e30f;
            }
        }

        float mxA = -1e30f, mxB = -1e30f;
#pragma unroll
        for (int j = 0; j < 8; j++) {
            mxA = fmaxf(mxA, fmaxf(sacc[j][0], sacc[j][1]));
            mxB = fmaxf(mxB, fmaxf(sacc[j][2], sacc[j][3]));
        }
        mxA = fmaxf(mxA, __shfl_xor_sync(0xffffffffu, mxA, 1));
        mxA = fmaxf(mxA, __shfl_xor_sync(0xffffffffu, mxA, 2));
        mxB = fmaxf(mxB, __shfl_xor_sync(0xffffffffu, mxB, 1));
        mxB = fmaxf(mxB, __shfl_xor_sync(0xffffffffu, mxB, 2));

        float mnA = fmaxf(mA, mxA), mnB = fmaxf(mB, mxB);
        float facA = __expf(mA - mnA), facB = __expf(mB - mnB);
        float sA = 0.0f, sB = 0.0f;
#pragma unroll
        for (int j = 0; j < 8; j++) {
            float p0 = __expf(sacc[j][0] - mnA);
            float p1 = __expf(sacc[j][1] - mnA);
            float p2 = __expf(sacc[j][2] - mnB);
            float p3 = __expf(sacc[j][3] - mnB);
            sacc[j][0] = p0; sacc[j][1] = p1; sacc[j][2] = p2; sacc[j][3] = p3;
            sA += p0 + p1; sB += p2 + p3;
        }
        sA += __shfl_xor_sync(0xffffffffu, sA, 1);
        sA += __shfl_xor_sync(0xffffffffu, sA, 2);
        sB += __shfl_xor_sync(0xffffffffu, sB, 1);
        sB += __shfl_xor_sync(0xffffffffu, sB, 2);
        lA = lA * facA + sA; lB = lB * facB + sB;
        mA = mnA; mB = mnB;
#pragma unroll
        for (int j = 0; j < 16; j++) {
            oacc[j][0] *= facA; oacc[j][1] *= facA;
            oacc[j][2] *= facB; oacc[j][3] *= facB;
        }

#pragma unroll
        for (int kc = 0; kc < 4; kc++) {
            const int j0 = 2 * kc, j1 = 2 * kc + 1;
            uint32_t phi[4], plo[4];
            {
                float v00 = sacc[j0][0], v01 = sacc[j0][1];
                float v02 = sacc[j0][2], v03 = sacc[j0][3];
                float v10 = sacc[j1][0], v11 = sacc[j1][1];
                float v12 = sacc[j1][2], v13 = sacc[j1][3];
                phi[0] = pack_bf2(v00, v01);
                phi[1] = pack_bf2(v02, v03);
                phi[2] = pack_bf2(v10, v11);
                phi[3] = pack_bf2(v12, v13);
                plo[0] = pack_bf2(v00 - __bfloat162float(__float2bfloat16(v00)),
                                  v01 - __bfloat162float(__float2bfloat16(v01)));
                plo[1] = pack_bf2(v02 - __bfloat162float(__float2bfloat16(v02)),
                                  v03 - __bfloat162float(__float2bfloat16(v03)));
                plo[2] = pack_bf2(v10 - __bfloat162float(__float2bfloat16(v10)),
                                  v11 - __bfloat162float(__float2bfloat16(v11)));
                plo[3] = pack_bf2(v12 - __bfloat162float(__float2bfloat16(v12)),
                                  v13 - __bfloat162float(__float2bfloat16(v13)));
            }
#pragma unroll
            for (int bn = 0; bn < 8; bn++) {
                const uint32_t rowsel =
                    (uint32_t)((kc * 16 + ((lane >> 4) << 3) + (lane & 7)) * AP
                             + (bn * 16 + ((lane >> 3) & 1) * 8) * 2);
                uint32_t r0, r1, r2, r3, s0, s1, s2, s3;
                ldm_x4_t(r0, r1, r2, r3, kv + 2 * KVTB + rowsel);
                ldm_x4_t(s0, s1, s2, s3, kv + 3 * KVTB + rowsel);
                mma16816(oacc[2 * bn],     phi[0], phi[1], phi[2], phi[3], r0, r2);
                mma16816(oacc[2 * bn + 1], phi[0], phi[1], phi[2], phi[3], r1, r3);
                mma16816(oacc[2 * bn],     phi[0], phi[1], phi[2], phi[3], s0, s2);
                mma16816(oacc[2 * bn + 1], phi[0], phi[1], phi[2], phi[3], s1, s3);
                mma16816(oacc[2 * bn],     plo[0], plo[1], plo[2], plo[3], r0, r2);
                mma16816(oacc[2 * bn + 1], plo[0], plo[1], plo[2], plo[3], r1, r3);
            }
        }
        __syncthreads();
    }

    const float invA = 1.0f / lA, invB = 1.0f / lB;
    const size_t rowA = ((size_t)b * SS + rAg) * NQ;
    const size_t rowB = ((size_t)b * SS + rBg) * NQ;
#pragma unroll
    for (int j = 0; j < 16; j++) {
        int col = h * HDIM + j * 8 + 2 * (lane & 3);
        store_hilo(ohi, olo, rowA + col, oacc[j][0] * invA, oacc[j][1] * invA);
        store_hilo(ohi, olo, rowB + col, oacc[j][2] * invB, oacc[j][3] * invB);
    }
}

// ---------------------------------------------------------------------------
extern "C" void kernel_launch(void* const* d_in, const int* in_sizes, int n_in,
                              void* d_out, int out_size)
{
    const float* x  = (const float*)d_in[0];
    const float* Wq = (const float*)d_in[2];
    const float* Wk = (const float*)d_in[3];
    const float* Wv = (const float*)d_in[4];
    const float* Wo = (const float*)d_in[5];
    float* out = (float*)d_out;

    __nv_bfloat16 *xhi, *xlo, *ahi, *alo, *qh, *ql, *kh, *kl, *vh, *vl;
    __nv_bfloat16 *wqThi, *wqTlo, *wkThi, *wkTlo, *wvThi, *wvTlo, *woThi, *woTlo;
    float2* rope;
    (void)cudaGetSymbolAddress((void**)&xhi, g_xhi);
    (void)cudaGetSymbolAddress((void**)&xlo, g_xlo);
    (void)cudaGetSymbolAddress((void**)&ahi, g_ahi);
    (void)cudaGetSymbolAddress((void**)&alo, g_alo);
    (void)cudaGetSymbolAddress((void**)&qh, g_qhi);
    (void)cudaGetSymbolAddress((void**)&ql, g_qlo);
    (void)cudaGetSymbolAddress((void**)&kh, g_khi);
    (void)cudaGetSymbolAddress((void**)&kl, g_klo);
    (void)cudaGetSymbolAddress((void**)&vh, g_vhi);
    (void)cudaGetSymbolAddress((void**)&vl, g_vlo);
    (void)cudaGetSymbolAddress((void**)&wqThi, g_wqThi);
    (void)cudaGetSymbolAddress((void**)&wqTlo, g_wqTlo);
    (void)cudaGetSymbolAddress((void**)&wkThi, g_wkThi);
    (void)cudaGetSymbolAddress((void**)&wkTlo, g_wkTlo);
    (void)cudaGetSymbolAddress((void**)&wvThi, g_wvThi);
    (void)cudaGetSymbolAddress((void**)&wvTlo, g_wvTlo);
    (void)cudaGetSymbolAddress((void**)&woThi, g_woThi);
    (void)cudaGetSymbolAddress((void**)&woTlo, g_woTlo);
    (void)cudaGetSymbolAddress((void**)&rope, g_rope);

    (void)cudaFuncSetAttribute(gemm_qkv,
                               cudaFuncAttributeMaxDynamicSharedMemorySize, GEMM_DSMEM);
    (void)cudaFuncSetAttribute(gemm_oproj,
                               cudaFuncAttributeMaxDynamicSharedMemorySize, GEMM_DSMEM);
    (void)cudaFuncSetAttribute(attn_mma,
                               cudaFuncAttributeMaxDynamicSharedMemorySize, ATTN_SMEM);

    // 0) rope table
    rope_table<<<(SS * 64 + 255) / 256, 256>>>(rope);

    // 1) split x into bf16 hi/lo
    {
        int n2 = (MM * KK) / 2;
        split_pair<<<(n2 + 255) / 256, 256>>>((const float2*)x,
                                              (__nv_bfloat162*)xhi,
                                              (__nv_bfloat162*)xlo, n2);
    }
    // 2) transpose+split weights -> [N, K] bf16
    transpose_split<<<dim3(NQ / 32, KK / 32), dim3(32, 8)>>>(Wq, wqThi, wqTlo, KK, NQ);
    transpose_split<<<dim3(NKV / 32, KK / 32), dim3(32, 8)>>>(Wk, wkThi, wkTlo, KK, NKV);
    transpose_split<<<dim3(NKV / 32, KK / 32), dim3(32, 8)>>>(Wv, wvThi, wvTlo, KK, NKV);
    transpose_split<<<dim3(NQ / 32, KK / 32), dim3(32, 8)>>>(Wo, woThi, woTlo, KK, NQ);

    // 3) fused QKV projection (one launch, RoPE/split epilogues fused)
    gemm_qkv<<<768, 256, GEMM_DSMEM>>>(xhi, xlo,
                                       wqThi, wqTlo, wkThi, wkTlo, wvThi, wvTlo,
                                       qh, ql, kh, kl, vh, vl, rope);

    // 4) attention (LPT 1-D grid)
    attn_mma<<<(SS / 128) * NHQ * BB, 256, ATTN_SMEM>>>(qh, ql, kh, kl, vh, vl, ahi, alo);

    // 5) output projection -> fp32 out
    gemm_oproj<<<dim3(NQ / 128, MM / 128), 256, GEMM_DSMEM>>>(
        ahi, alo, woThi, woTlo, out, NQ);
}

// round 8
// speedup vs baseline: 3.7723x; 1.0594x over previous
#include <cuda_runtime.h>
#include <cuda_bf16.h>
#include <cuda_fp16.h>
#include <math.h>
#include <stdint.h>

#define BB   2
#define SS   2048
#define DD   2048
#define NHQ  16
#define NKVH 4
#define HDIM 128
#define MM   (BB*SS)       // 4096
#define KK   2048
#define NQ   (NHQ*HDIM)    // 2048
#define NKV  (NKVH*HDIM)   // 512

// ---------------- scratch (device globals; no allocation allowed) ----------
__device__ __nv_bfloat16 g_xhi[(size_t)MM*KK],  g_xlo[(size_t)MM*KK];
__device__ __nv_bfloat16 g_ahi[(size_t)MM*NQ],  g_alo[(size_t)MM*NQ];
__device__ __nv_bfloat16 g_qhi[(size_t)MM*NQ],  g_qlo[(size_t)MM*NQ];
__device__ __nv_bfloat16 g_khi[(size_t)MM*NKV], g_klo[(size_t)MM*NKV];
__device__ __half        g_vf[(size_t)MM*NKV];                 // V fp16 single
__device__ __nv_bfloat16 g_wqThi[(size_t)NQ*KK],  g_wqTlo[(size_t)NQ*KK];
__device__ __nv_bfloat16 g_wkThi[(size_t)NKV*KK], g_wkTlo[(size_t)NKV*KK];
__device__ __nv_bfloat16 g_wvThi[(size_t)NKV*KK], g_wvTlo[(size_t)NKV*KK];
__device__ __nv_bfloat16 g_woThi[(size_t)NQ*KK],  g_woTlo[(size_t)NQ*KK];
__device__ float2 g_rope[(size_t)SS*64];          // (cos, sin) per (s, pair)

// ---------------- PTX helpers (sm_80-era: valid on plain sm_103 target) ----
__device__ __forceinline__ uint32_t smem_u32(const void* p) {
    uint32_t a;
    asm("{ .reg .u64 t; cvta.to.shared.u64 t, %1; cvt.u32.u64 %0, t; }"
        : "=r"(a) : "l"(p));
    return a;
}

__device__ __forceinline__ void cp16(uint32_t s, const void* g) {
    asm volatile("cp.async.cg.shared.global [%0], [%1], 16;" :: "r"(s), "l"(g));
}
#define CP_COMMIT() asm volatile("cp.async.commit_group;" ::: "memory")
#define CP_WAIT(n)  asm volatile("cp.async.wait_group %0;" :: "n"(n) : "memory")

__device__ __forceinline__ void ldm_x4(uint32_t& r0, uint32_t& r1,
                                       uint32_t& r2, uint32_t& r3, uint32_t a) {
    asm volatile("ldmatrix.sync.aligned.m8n8.x4.shared.b16 {%0,%1,%2,%3}, [%4];"
                 : "=r"(r0), "=r"(r1), "=r"(r2), "=r"(r3) : "r"(a));
}
__device__ __forceinline__ void ldm_x4_t(uint32_t& r0, uint32_t& r1,
                                         uint32_t& r2, uint32_t& r3, uint32_t a) {
    asm volatile("ldmatrix.sync.aligned.m8n8.x4.trans.shared.b16 {%0,%1,%2,%3}, [%4];"
                 : "=r"(r0), "=r"(r1), "=r"(r2), "=r"(r3) : "r"(a));
}

__device__ __forceinline__ void mma16816(float* c,
    uint32_t a0, uint32_t a1, uint32_t a2, uint32_t a3, uint32_t b0, uint32_t b1)
{
    asm volatile(
        "mma.sync.aligned.m16n8k16.row.col.f32.bf16.bf16.f32 "
        "{%0,%1,%2,%3}, {%4,%5,%6,%7}, {%8,%9}, {%0,%1,%2,%3};"
        : "+f"(c[0]), "+f"(c[1]), "+f"(c[2]), "+f"(c[3])
        : "r"(a0), "r"(a1), "r"(a2), "r"(a3), "r"(b0), "r"(b1));
}

__device__ __forceinline__ void mma16816h(float* c,
    uint32_t a0, uint32_t a1, uint32_t a2, uint32_t a3, uint32_t b0, uint32_t b1)
{
    asm volatile(
        "mma.sync.aligned.m16n8k16.row.col.f32.f16.f16.f32 "
        "{%0,%1,%2,%3}, {%4,%5,%6,%7}, {%8,%9}, {%0,%1,%2,%3};"
        : "+f"(c[0]), "+f"(c[1]), "+f"(c[2]), "+f"(c[3])
        : "r"(a0), "r"(a1), "r"(a2), "r"(a3), "r"(b0), "r"(b1));
}

__device__ __forceinline__ uint32_t pack_h2(float x, float y) {
    __half2 t = __floats2half2_rn(x, y);
    return *reinterpret_cast<uint32_t*>(&t);
}

__device__ __forceinline__ void store_hilo(__nv_bfloat16* hi, __nv_bfloat16* lo,
                                           size_t off, float a, float b)
{
    __nv_bfloat16 ha = __float2bfloat16(a), hb = __float2bfloat16(b);
    *(__nv_bfloat162*)(hi + off) = __halves2bfloat162(ha, hb);
    *(__nv_bfloat162*)(lo + off) = __halves2bfloat162(
        __float2bfloat16(a - __bfloat162float(ha)),
        __float2bfloat16(b - __bfloat162float(hb)));
}

// ---------------------------------------------------------------------------
// Shared GEMM machinery (BK=32, pitch 80 B, 2-stage cp.async)
// ---------------------------------------------------------------------------
#define BK        32
#define ROWB      80
#define TILEB     (128 * ROWB)
#define OFF_AHI   0
#define OFF_ALO   (TILEB)
#define OFF_BHI   (2 * TILEB)
#define OFF_BLO   (3 * TILEB)
#define STAGEB    (4 * TILEB)
#define GEMM_DSMEM (2 * STAGEB)
#define NCHUNK    (KK / BK)

__device__ __forceinline__ void load_stage(uint32_t sBase,
    const __nv_bfloat16* Ahi, const __nv_bfloat16* Alo,
    const __nv_bfloat16* Bhi, const __nv_bfloat16* Blo,
    int row0, int col0, int k0, int tid)
{
#pragma unroll
    for (int t = 0; t < 8; t++) {
        int i    = tid + t * 256;
        int tile = i >> 9;
        int w    = i & 511;
        int r    = w >> 2;
        int seg  = w & 3;
        const __nv_bfloat16* src =
            (tile == 0) ? Ahi : (tile == 1) ? Alo : (tile == 2) ? Bhi : Blo;
        int rb = (tile < 2) ? row0 : col0;
        cp16(sBase + tile * TILEB + r * ROWB + seg * 16,
             src + (size_t)(rb + r) * KK + k0 + seg * 8);
    }
}

__device__ __forceinline__ void gemm_mainloop(uint32_t sBase,
    const __nv_bfloat16* Ahi, const __nv_bfloat16* Alo,
    const __nv_bfloat16* Bhi, const __nv_bfloat16* Blo,
    int row0, int col0, int tid, int lane, int wr, int wc,
    float acc[4][4][4])
{
    load_stage(sBase, Ahi, Alo, Bhi, Blo, row0, col0, 0, tid);
    CP_COMMIT();

#pragma unroll 1
    for (int c = 0; c < NCHUNK; c++) {
        const uint32_t st = sBase + (uint32_t)(c & 1) * STAGEB;
        if (c + 1 < NCHUNK) {
            load_stage(sBase + (uint32_t)((c + 1) & 1) * STAGEB,
                       Ahi, Alo, Bhi, Blo, row0, col0, (c + 1) * BK, tid);
            CP_COMMIT();
            CP_WAIT(1);
        } else {
            CP_WAIT(0);
        }
        __syncthreads();

        const uint32_t aHiW = st + OFF_AHI + (uint32_t)(wr * 64) * ROWB;
        const uint32_t aLoW = st + OFF_ALO + (uint32_t)(wr * 64) * ROWB;
        const uint32_t bHiW = st + OFF_BHI + (uint32_t)(wc * 32) * ROWB;
        const uint32_t bLoW = st + OFF_BLO + (uint32_t)(wc * 32) * ROWB;

#pragma unroll
        for (int ks = 0; ks < 2; ks++) {
            const uint32_t aoff = (uint32_t)((lane & 15) * ROWB
                                + (ks * 16 + ((lane >> 4) << 3)) * 2);
            uint32_t AH[4][4], AL[4][4];
#pragma unroll
            for (int am = 0; am < 4; am++) {
                ldm_x4(AH[am][0], AH[am][1], AH[am][2], AH[am][3],
                       aHiW + (uint32_t)(am * 16) * ROWB + aoff);
                ldm_x4(AL[am][0], AL[am][1], AL[am][2], AL[am][3],
                       aLoW + (uint32_t)(am * 16) * ROWB + aoff);
            }
            const uint32_t boff = (uint32_t)((((lane >> 4) << 3) + (lane & 7)) * ROWB
                                + (ks * 16 + ((lane >> 3) & 1) * 8) * 2);
            uint32_t BH[2][4], BL[2][4];
#pragma unroll
            for (int bn = 0; bn < 2; bn++) {
                ldm_x4(BH[bn][0], BH[bn][1], BH[bn][2], BH[bn][3],
                       bHiW + (uint32_t)(bn * 16) * ROWB + boff);
                ldm_x4(BL[bn][0], BL[bn][1], BL[bn][2], BL[bn][3],
                       bLoW + (uint32_t)(bn * 16) * ROWB + boff);
            }
#pragma unroll
            for (int am = 0; am < 4; am++)
#pragma unroll
                for (int an = 0; an < 4; an++) {
                    uint32_t b0h = BH[an >> 1][(an & 1) * 2];
                    uint32_t b1h = BH[an >> 1][(an & 1) * 2 + 1];
                    uint32_t b0l = BL[an >> 1][(an & 1) * 2];
                    uint32_t b1l = BL[an >> 1][(an & 1) * 2 + 1];
                    mma16816(acc[am][an], AH[am][0], AH[am][1], AH[am][2], AH[am][3], b0h, b1h);
                    mma16816(acc[am][an], AH[am][0], AH[am][1], AH[am][2], AH[am][3], b0l, b1l);
                    mma16816(acc[am][an], AL[am][0], AL[am][1], AL[am][2], AL[am][3], b0h, b1h);
                }
        }
        __syncthreads();
    }
}

// ---------------------------------------------------------------------------
// Fused QKV projection: one launch, 1-D grid of 768 CTAs.
//   bid [0,512):   Q tile  -> rope + bf16 hi/lo
//   bid [512,640): K tile  -> rope + bf16 hi/lo
//   bid [640,768): V tile  -> fp16 single
// ---------------------------------------------------------------------------
__global__ __launch_bounds__(256) void gemm_qkv(
    const __nv_bfloat16* __restrict__ xhi, const __nv_bfloat16* __restrict__ xlo,
    const __nv_bfloat16* __restrict__ wqh, const __nv_bfloat16* __restrict__ wql,
    const __nv_bfloat16* __restrict__ wkh, const __nv_bfloat16* __restrict__ wkl,
    const __nv_bfloat16* __restrict__ wvh, const __nv_bfloat16* __restrict__ wvl,
    __nv_bfloat16* __restrict__ qh, __nv_bfloat16* __restrict__ ql,
    __nv_bfloat16* __restrict__ kh, __nv_bfloat16* __restrict__ kl,
    __half* __restrict__ vf,
    const float2* __restrict__ rope)
{
    extern __shared__ char dsm[];
    const uint32_t sBase = smem_u32(dsm);

    const int tid  = threadIdx.x;
    const int lane = tid & 31;
    const int wid  = tid >> 5;
    const int wr   = wid >> 2;
    const int wc   = wid & 3;

    const int bid = blockIdx.x;
    const __nv_bfloat16 *Bh, *Bl;
    __nv_bfloat16 *Oh = nullptr, *Ol = nullptr;
    int row0, col0, N, mode;                  // mode: 0=rope hi/lo, 1=V fp16
    if (bid < 512) {
        row0 = (bid >> 4) * 128; col0 = (bid & 15) * 128;
        Bh = wqh; Bl = wql; Oh = qh; Ol = ql; N = NQ; mode = 0;
    } else if (bid < 640) {
        int i = bid - 512;
        row0 = (i >> 2) * 128; col0 = (i & 3) * 128;
        Bh = wkh; Bl = wkl; Oh = kh; Ol = kl; N = NKV; mode = 0;
    } else {
        int i = bid - 640;
        row0 = (i >> 2) * 128; col0 = (i & 3) * 128;
        Bh = wvh; Bl = wvl; N = NKV; mode = 1;
    }

    float acc[4][4][4];
#pragma unroll
    for (int i = 0; i < 4; i++)
#pragma unroll
        for (int j = 0; j < 4; j++)
#pragma unroll
            for (int l = 0; l < 4; l++) acc[i][j][l] = 0.0f;

    gemm_mainloop(sBase, xhi, xlo, Bh, Bl, row0, col0, tid, lane, wr, wc, acc);

    const int rbase = row0 + wr * 64;
    const int cbase = col0 + wc * 32;
#pragma unroll
    for (int am = 0; am < 4; am++)
#pragma unroll
        for (int an = 0; an < 4; an++) {
            float* cf = acc[am][an];
            int r  = rbase + am * 16 + (lane >> 2);
            int cc = cbase + an * 8 + (lane & 3) * 2;
            if (mode == 0) {
                int p = (cc & 127) >> 1;
                float2 cs0 = rope[(size_t)(r & (SS - 1)) * 64 + p];
                float2 cs1 = rope[(size_t)((r + 8) & (SS - 1)) * 64 + p];
                float o0 = cf[0] * cs0.x - cf[1] * cs0.y;
                float o1 = cf[0] * cs0.y + cf[1] * cs0.x;
                float o2 = cf[2] * cs1.x - cf[3] * cs1.y;
                float o3 = cf[2] * cs1.y + cf[3] * cs1.x;
                store_hilo(Oh, Ol, (size_t)r * N + cc,       o0, o1);
                store_hilo(Oh, Ol, (size_t)(r + 8) * N + cc, o2, o3);
            } else {
                *(__half2*)(vf + (size_t)r * N + cc)       = __floats2half2_rn(cf[0], cf[1]);
                *(__half2*)(vf + (size_t)(r + 8) * N + cc) = __floats2half2_rn(cf[2], cf[3]);
            }
        }
}

// ---------------------------------------------------------------------------
// O-projection GEMM: fp32 C output
// ---------------------------------------------------------------------------
__global__ __launch_bounds__(256) void gemm_oproj(
    const __nv_bfloat16* __restrict__ Ahi, const __nv_bfloat16* __restrict__ Alo,
    const __nv_bfloat16* __restrict__ Bhi, const __nv_bfloat16* __restrict__ Blo,
    float* __restrict__ C, int N)
{
    extern __shared__ char dsm[];
    const uint32_t sBase = smem_u32(dsm);

    const int tid  = threadIdx.x;
    const int lane = tid & 31;
    const int wid  = tid >> 5;
    const int wr   = wid >> 2;
    const int wc   = wid & 3;
    const int row0 = blockIdx.y * 128;
    const int col0 = blockIdx.x * 128;

    float acc[4][4][4];
#pragma unroll
    for (int i = 0; i < 4; i++)
#pragma unroll
        for (int j = 0; j < 4; j++)
#pragma unroll
            for (int l = 0; l < 4; l++) acc[i][j][l] = 0.0f;

    gemm_mainloop(sBase, Ahi, Alo, Bhi, Blo, row0, col0, tid, lane, wr, wc, acc);

    const int rbase = row0 + wr * 64;
    const int cbase = col0 + wc * 32;
#pragma unroll
    for (int am = 0; am < 4; am++)
#pragma unroll
        for (int an = 0; an < 4; an++) {
            float* cf = acc[am][an];
            int r  = rbase + am * 16 + (lane >> 2);
            int cc = cbase + an * 8 + (lane & 3) * 2;
            *(float2*)(C + (size_t)r * N + cc)       = make_float2(cf[0], cf[1]);
            *(float2*)(C + (size_t)(r + 8) * N + cc) = make_float2(cf[2], cf[3]);
        }
}

// ---------------------------------------------------------------------------
// rope table: (cos, sin) for (s, pair)
// ---------------------------------------------------------------------------
__global__ void rope_table(float2* __restrict__ t)
{
    int i = blockIdx.x * 256 + threadIdx.x;
    if (i >= SS * 64) return;
    int s = i >> 6, p = i & 63;
    float e   = (float)(2 * p) * (1.0f / 128.0f);
    float inv = 1.0f / powf(10000.0f, e);
    float sn, c;
    sincosf((float)s * inv, &sn, &c);
    t[i] = make_float2(c, sn);
}

// ---------------------------------------------------------------------------
// fp32 -> hi/lo bf16 split (x only)
// ---------------------------------------------------------------------------
__global__ void split_pair(const float2* __restrict__ src,
                           __nv_bfloat162* __restrict__ hi,
                           __nv_bfloat162* __restrict__ lo, int n2)
{
    int i = blockIdx.x * blockDim.x + threadIdx.x;
    if (i >= n2) return;
    float2 v = src[i];
    __nv_bfloat16 hx = __float2bfloat16(v.x);
    __nv_bfloat16 hy = __float2bfloat16(v.y);
    hi[i] = __halves2bfloat162(hx, hy);
    lo[i] = __halves2bfloat162(__float2bfloat16(v.x - __bfloat162float(hx)),
                               __float2bfloat16(v.y - __bfloat162float(hy)));
}

// ---------------------------------------------------------------------------
// W [K,N] fp32 -> Wt hi/lo [N,K] bf16 (transpose + split)
// ---------------------------------------------------------------------------
__global__ void transpose_split(const float* __restrict__ src,
                                __nv_bfloat16* __restrict__ hi,
                                __nv_bfloat16* __restrict__ lo, int K, int N)
{
    __shared__ float t[32][33];
    int k0 = blockIdx.y * 32, n0 = blockIdx.x * 32;
    int tx = threadIdx.x, ty = threadIdx.y;
#pragma unroll
    for (int j = 0; j < 32; j += 8)
        t[ty + j][tx] = src[(size_t)(k0 + ty + j) * N + n0 + tx];
    __syncthreads();
#pragma unroll
    for (int j = 0; j < 32; j += 8) {
        float v = t[tx][ty + j];
        __nv_bfloat16 h = __float2bfloat16(v);
        size_t o = (size_t)(n0 + ty + j) * K + k0 + tx;
        hi[o] = h;
        lo[o] = __float2bfloat16(v - __bfloat162float(h));
    }
}

// ---------------------------------------------------------------------------
// Flash attention: S = QK^T in bf16x3, P·V in single fp16. Causal, GQA 4:1.
// LPT 1-D grid. KV stage = K hi + K lo (bf16) + V (fp16) = 3 tiles.
// ---------------------------------------------------------------------------
#define AP      272
#define QTB     (128 * AP)
#define KVTB    (64 * AP)
#define KVB     (2 * QTB)
#define KVSTG   (3 * KVTB)
#define ATTN_SMEM (2 * QTB + 2 * KVSTG)   // 174080

__device__ __forceinline__ void load_kv_tile(uint32_t sb, uint32_t stg,
    const __nv_bfloat16* kh, const __nv_bfloat16* kl,
    const __half* vf, int k0, int tid)
{
#pragma unroll
    for (int t = 0; t < 12; t++) {
        int i  = tid + t * 256;
        int m  = i >> 10;                  // 0..2, constant per unrolled t
        int w  = i & 1023;
        int r  = w >> 4;
        int sg = w & 15;
        const void* src = (m == 0) ? (const void*)(kh + (size_t)(k0 + r) * NKV + sg * 8)
                        : (m == 1) ? (const void*)(kl + (size_t)(k0 + r) * NKV + sg * 8)
                                   : (const void*)(vf + (size_t)(k0 + r) * NKV + sg * 8);
        cp16(sb + stg + (uint32_t)m * KVTB + (uint32_t)(r * AP + sg * 16), src);
    }
}

__global__ __launch_bounds__(256) void attn_mma(
    const __nv_bfloat16* __restrict__ qhi, const __nv_bfloat16* __restrict__ qlo,
    const __nv_bfloat16* __restrict__ khi, const __nv_bfloat16* __restrict__ klo,
    const __half* __restrict__ vf,
    __nv_bfloat16* __restrict__ ohi, __nv_bfloat16* __restrict__ olo)
{
    extern __shared__ char sm[];
    const uint32_t sb = smem_u32(sm);

    const int bid = blockIdx.x;
    const int qt  = (SS / 128 - 1) - (bid >> 5);
    const int hb  = bid & 31;
    const int h   = hb & 15;
    const int b   = hb >> 4;
    const int kvh = h >> 2;
    const int q0  = qt * 128;

    const int tid  = threadIdx.x;
    const int lane = tid & 31;
    const int wid  = tid >> 5;
    const int wq0  = wid * 16;
    const int gr   = lane >> 2;

    const __nv_bfloat16* qhb = qhi + ((size_t)b * SS + q0) * NQ + h * HDIM;
    const __nv_bfloat16* qlb = qlo + ((size_t)b * SS + q0) * NQ + h * HDIM;
    const __nv_bfloat16* khb = khi + (size_t)b * SS * NKV + kvh * HDIM;
    const __nv_bfloat16* klb = klo + (size_t)b * SS * NKV + kvh * HDIM;
    const __half*        vfb = vf  + (size_t)b * SS * NKV + kvh * HDIM;

#pragma unroll
    for (int t = 0; t < 16; t++) {
        int i   = tid + t * 256;
        int hl  = i >> 11;
        int w   = i & 2047;
        int r   = w >> 4;
        int sg  = w & 15;
        const __nv_bfloat16* src = hl ? qlb : qhb;
        cp16(sb + (uint32_t)hl * QTB + (uint32_t)(r * AP + sg * 16),
             src + (size_t)r * NQ + sg * 8);
    }
    load_kv_tile(sb, KVB, khb, klb, vfb, 0, tid);
    CP_COMMIT();

    float oacc[16][4];
#pragma unroll
    for (int j = 0; j < 16; j++)
#pragma unroll
        for (int e = 0; e < 4; e++) oacc[j][e] = 0.0f;
    float mA = -1e30f, mB = -1e30f, lA = 0.0f, lB = 0.0f;

    const float scale = 0.08838834764831845f;
    const int ntiles = 2 * qt + 2;
    const int rAg = q0 + wq0 + gr;
    const int rBg = rAg + 8;

#pragma unroll 1
    for (int t = 0; t < ntiles; t++) {
        if (t + 1 < ntiles) {
            load_kv_tile(sb, KVB + (uint32_t)((t + 1) & 1) * KVSTG,
                         khb, klb, vfb, (t + 1) * 64, tid);
            CP_COMMIT();
            CP_WAIT(1);
        } else {
            CP_WAIT(0);
        }
        __syncthreads();

        const uint32_t kv = sb + KVB + (uint32_t)(t & 1) * KVSTG;

        // ---- S = Q @ K^T (bf16 hi/lo x3, shared fragments) ----
        float sacc[8][4];
#pragma unroll
        for (int j = 0; j < 8; j++)
#pragma unroll
            for (int e = 0; e < 4; e++) sacc[j][e] = 0.0f;

        const uint32_t aB = sb + (uint32_t)wq0 * AP;
#pragma unroll
        for (int c = 0; c < 8; c++) {
            const uint32_t ao = (uint32_t)((lane & 15) * AP
                              + (c * 16 + ((lane >> 4) << 3)) * 2);
            uint32_t ah0, ah1, ah2, ah3, al0, al1, al2, al3;
            ldm_x4(ah0, ah1, ah2, ah3, aB + ao);
            ldm_x4(al0, al1, al2, al3, aB + QTB + ao);
#pragma unroll
            for (int g = 0; g < 4; g++) {
                const uint32_t bo = (uint32_t)((g * 16 + ((lane >> 4) << 3) + (lane & 7)) * AP
                                  + (c * 16 + ((lane >> 3) & 1) * 8) * 2);
                uint32_t bh0, bh1, bh2, bh3, bl0, bl1, bl2, bl3;
                ldm_x4(bh0, bh1, bh2, bh3, kv + bo);
                ldm_x4(bl0, bl1, bl2, bl3, kv + KVTB + bo);
                mma16816(sacc[2 * g],     ah0, ah1, ah2, ah3, bh0, bh1);
                mma16816(sacc[2 * g + 1], ah0, ah1, ah2, ah3, bh2, bh3);
                mma16816(sacc[2 * g],     ah0, ah1, ah2, ah3, bl0, bl1);
                mma16816(sacc[2 * g + 1], ah0, ah1, ah2, ah3, bl2, bl3);
                mma16816(sacc[2 * g],     al0, al1, al2, al3, bh0, bh1);
                mma16816(sacc[2 * g + 1], al0, al1, al2, al3, bh2, bh3);
            }
        }

#pragma unroll
        for (int j = 0; j < 8; j++)
#pragma unroll
            for (int e = 0; e < 4; e++) sacc[j][e] *= scale;

        if (t >= 2 * qt) {
#pragma unroll
            for (int j = 0; j < 8; j++) {
                int col = t * 64 + j * 8 + 2 * (lane & 3);
                if (col     > rAg) sacc[j][0] = -1e30f;
                if (col + 1 > rAg) sacc[j][1] = -1e30f;
                if (col     > rBg) sacc[j][2] = -1e30f;
                if (col + 1 > rBg) sacc[j][3] = -1e30f;
            }
        }

        // ---- online softmax ----
        float mxA = -1e30f, mxB = -1e30f;
#pragma unroll
        for (int j = 0; j < 8; j++) {
            mxA = fmaxf(mxA, fmaxf(sacc[j][0], sacc[j][1]));
            mxB = fmaxf(mxB, fmaxf(sacc[j][2], sacc[j][3]));
        }
        mxA = fmaxf(mxA, __shfl_xor_sync(0xffffffffu, mxA, 1));
        mxA = fmaxf(mxA, __shfl_xor_sync(0xffffffffu, mxA, 2));
        mxB = fmaxf(mxB, __shfl_xor_sync(0xffffffffu, mxB, 1));
        mxB = fmaxf(mxB, __shfl_xor_sync(0xffffffffu, mxB, 2));

        float mnA = fmaxf(mA, mxA), mnB = fmaxf(mB, mxB);
        float facA = __expf(mA - mnA), facB = __expf(mB - mnB);
        float sA = 0.0f, sB = 0.0f;
#pragma unroll
        for (int j = 0; j < 8; j++) {
            float p0 = __expf(sacc[j][0] - mnA);
            float p1 = __expf(sacc[j][1] - mnA);
            float p2 = __expf(sacc[j][2] - mnB);
            float p3 = __expf(sacc[j][3] - mnB);
            sacc[j][0] = p0; sacc[j][1] = p1; sacc[j][2] = p2; sacc[j][3] = p3;
            sA += p0 + p1; sB += p2 + p3;
        }
        sA += __shfl_xor_sync(0xffffffffu, sA, 1);
        sA += __shfl_xor_sync(0xffffffffu, sA, 2);
        sB += __shfl_xor_sync(0xffffffffu, sB, 1);
        sB += __shfl_xor_sync(0xffffffffu, sB, 2);
        lA = lA * facA + sA; lB = lB * facB + sB;
        mA = mnA; mB = mnB;
#pragma unroll
        for (int j = 0; j < 16; j++) {
            oacc[j][0] *= facA; oacc[j][1] *= facA;
            oacc[j][2] *= facB; oacc[j][3] *= facB;
        }

        // ---- O += P @ V (single fp16 pass) ----
#pragma unroll
        for (int kc = 0; kc < 4; kc++) {
            const int j0 = 2 * kc, j1 = 2 * kc + 1;
            uint32_t ph[4];
            ph[0] = pack_h2(sacc[j0][0], sacc[j0][1]);
            ph[1] = pack_h2(sacc[j0][2], sacc[j0][3]);
            ph[2] = pack_h2(sacc[j1][0], sacc[j1][1]);
            ph[3] = pack_h2(sacc[j1][2], sacc[j1][3]);
#pragma unroll
            for (int bn = 0; bn < 8; bn++) {
                const uint32_t rowsel =
                    (uint32_t)((kc * 16 + ((lane >> 4) << 3) + (lane & 7)) * AP
                             + (bn * 16 + ((lane >> 3) & 1) * 8) * 2);
                uint32_t r0, r1, r2, r3;
                ldm_x4_t(r0, r1, r2, r3, kv + 2 * KVTB + rowsel);
                mma16816h(oacc[2 * bn],     ph[0], ph[1], ph[2], ph[3], r0, r2);
                mma16816h(oacc[2 * bn + 1], ph[0], ph[1], ph[2], ph[3], r1, r3);
            }
        }
        __syncthreads();
    }

    const float invA = 1.0f / lA, invB = 1.0f / lB;
    const size_t rowA = ((size_t)b * SS + rAg) * NQ;
    const size_t rowB = ((size_t)b * SS + rBg) * NQ;
#pragma unroll
    for (int j = 0; j < 16; j++) {
        int col = h * HDIM + j * 8 + 2 * (lane & 3);
        store_hilo(ohi, olo, rowA + col, oacc[j][0] * invA, oacc[j][1] * invA);
        store_hilo(ohi, olo, rowB + col, oacc[j][2] * invB, oacc[j][3] * invB);
    }
}

// ---------------------------------------------------------------------------
extern "C" void kernel_launch(void* const* d_in, const int* in_sizes, int n_in,
                              void* d_out, int out_size)
{
    const float* x  = (const float*)d_in[0];
    const float* Wq = (const float*)d_in[2];
    const float* Wk = (const float*)d_in[3];
    const float* Wv = (const float*)d_in[4];
    const float* Wo = (const float*)d_in[5];
    float* out = (float*)d_out;

    __nv_bfloat16 *xhi, *xlo, *ahi, *alo, *qh, *ql, *kh, *kl;
    __half *vf;
    __nv_bfloat16 *wqThi, *wqTlo, *wkThi, *wkTlo, *wvThi, *wvTlo, *woThi, *woTlo;
    float2* rope;
    (void)cudaGetSymbolAddress((void**)&xhi, g_xhi);
    (void)cudaGetSymbolAddress((void**)&xlo, g_xlo);
    (void)cudaGetSymbolAddress((void**)&ahi, g_ahi);
    (void)cudaGetSymbolAddress((void**)&alo, g_alo);
    (void)cudaGetSymbolAddress((void**)&qh, g_qhi);
    (void)cudaGetSymbolAddress((void**)&ql, g_qlo);
    (void)cudaGetSymbolAddress((void**)&kh, g_khi);
    (void)cudaGetSymbolAddress((void**)&kl, g_klo);
    (void)cudaGetSymbolAddress((void**)&vf, g_vf);
    (void)cudaGetSymbolAddress((void**)&wqThi, g_wqThi);
    (void)cudaGetSymbolAddress((void**)&wqTlo, g_wqTlo);
    (void)cudaGetSymbolAddress((void**)&wkThi, g_wkThi);
    (void)cudaGetSymbolAddress((void**)&wkTlo, g_wkTlo);
    (void)cudaGetSymbolAddress((void**)&wvThi, g_wvThi);
    (void)cudaGetSymbolAddress((void**)&wvTlo, g_wvTlo);
    (void)cudaGetSymbolAddress((void**)&woThi, g_woThi);
    (void)cudaGetSymbolAddress((void**)&woTlo, g_woTlo);
    (void)cudaGetSymbolAddress((void**)&rope, g_rope);

    (void)cudaFuncSetAttribute(gemm_qkv,
                               cudaFuncAttributeMaxDynamicSharedMemorySize, GEMM_DSMEM);
    (void)cudaFuncSetAttribute(gemm_oproj,
                               cudaFuncAttributeMaxDynamicSharedMemorySize, GEMM_DSMEM);
    (void)cudaFuncSetAttribute(attn_mma,
                               cudaFuncAttributeMaxDynamicSharedMemorySize, ATTN_SMEM);

    // 0) rope table
    rope_table<<<(SS * 64 + 255) / 256, 256>>>(rope);

    // 1) split x into bf16 hi/lo
    {
        int n2 = (MM * KK) / 2;
        split_pair<<<(n2 + 255) / 256, 256>>>((const float2*)x,
                                              (__nv_bfloat162*)xhi,
                                              (__nv_bfloat162*)xlo, n2);
    }
    // 2) transpose+split weights -> [N, K] bf16
    transpose_split<<<dim3(NQ / 32, KK / 32), dim3(32, 8)>>>(Wq, wqThi, wqTlo, KK, NQ);
    transpose_split<<<dim3(NKV / 32, KK / 32), dim3(32, 8)>>>(Wk, wkThi, wkTlo, KK, NKV);
    transpose_split<<<dim3(NKV / 32, KK / 32), dim3(32, 8)>>>(Wv, wvThi, wvTlo, KK, NKV);
    transpose_split<<<dim3(NQ / 32, KK / 32), dim3(32, 8)>>>(Wo, woThi, woTlo, KK, NQ);

    // 3) fused QKV projection (Q,K: rope+bf16 hi/lo; V: fp16 single)
    gemm_qkv<<<768, 256, GEMM_DSMEM>>>(xhi, xlo,
                                       wqThi, wqTlo, wkThi, wkTlo, wvThi, wvTlo,
                                       qh, ql, kh, kl, vf, rope);

    // 4) attention (LPT 1-D grid; PV in fp16)
    attn_mma<<<(SS / 128) * NHQ * BB, 256, ATTN_SMEM>>>(qh, ql, kh, kl, vf, ahi, alo);

    // 5) output projection -> fp32 out
    gemm_oproj<<<dim3(NQ / 128, MM / 128), 256, GEMM_DSMEM>>>(
        ahi, alo, woThi, woTlo, out, NQ);
}

// round 9
// speedup vs baseline: 3.8053x; 1.0087x over previous
#include <cuda_runtime.h>
#include <cuda_bf16.h>
#include <cuda_fp16.h>
#include <math.h>
#include <stdint.h>

#define BB   2
#define SS   2048
#define DD   2048
#define NHQ  16
#define NKVH 4
#define HDIM 128
#define MM   (BB*SS)       // 4096
#define KK   2048
#define NQ   (NHQ*HDIM)    // 2048
#define NKV  (NKVH*HDIM)   // 512

// ---------------- scratch (device globals; no allocation allowed) ----------
__device__ __nv_bfloat16 g_xhi[(size_t)MM*KK],  g_xlo[(size_t)MM*KK];
__device__ __nv_bfloat16 g_ahi[(size_t)MM*NQ],  g_alo[(size_t)MM*NQ];
__device__ __nv_bfloat16 g_qhi[(size_t)MM*NQ],  g_qlo[(size_t)MM*NQ];
__device__ __nv_bfloat16 g_khi[(size_t)MM*NKV], g_klo[(size_t)MM*NKV];
__device__ __half        g_vf[(size_t)MM*NKV];                 // V fp16 single
__device__ __nv_bfloat16 g_wqThi[(size_t)NQ*KK],  g_wqTlo[(size_t)NQ*KK];
__device__ __nv_bfloat16 g_wkThi[(size_t)NKV*KK], g_wkTlo[(size_t)NKV*KK];
__device__ __nv_bfloat16 g_wvThi[(size_t)NKV*KK], g_wvTlo[(size_t)NKV*KK];
__device__ __nv_bfloat16 g_woThi[(size_t)NQ*KK],  g_woTlo[(size_t)NQ*KK];
__device__ float2 g_rope[(size_t)SS*64];          // (cos, sin) per (s, pair)

// ---------------- PTX helpers (sm_80-era: valid on plain sm_103 target) ----
__device__ __forceinline__ uint32_t smem_u32(const void* p) {
    uint32_t a;
    asm("{ .reg .u64 t; cvta.to.shared.u64 t, %1; cvt.u32.u64 %0, t; }"
        : "=r"(a) : "l"(p));
    return a;
}

__device__ __forceinline__ void cp16(uint32_t s, const void* g) {
    asm volatile("cp.async.cg.shared.global [%0], [%1], 16;" :: "r"(s), "l"(g));
}
#define CP_COMMIT() asm volatile("cp.async.commit_group;" ::: "memory")
#define CP_WAIT(n)  asm volatile("cp.async.wait_group %0;" :: "n"(n) : "memory")

__device__ __forceinline__ void ldm_x4(uint32_t& r0, uint32_t& r1,
                                       uint32_t& r2, uint32_t& r3, uint32_t a) {
    asm volatile("ldmatrix.sync.aligned.m8n8.x4.shared.b16 {%0,%1,%2,%3}, [%4];"
                 : "=r"(r0), "=r"(r1), "=r"(r2), "=r"(r3) : "r"(a));
}
__device__ __forceinline__ void ldm_x4_t(uint32_t& r0, uint32_t& r1,
                                         uint32_t& r2, uint32_t& r3, uint32_t a) {
    asm volatile("ldmatrix.sync.aligned.m8n8.x4.trans.shared.b16 {%0,%1,%2,%3}, [%4];"
                 : "=r"(r0), "=r"(r1), "=r"(r2), "=r"(r3) : "r"(a));
}

__device__ __forceinline__ void mma16816(float* c,
    uint32_t a0, uint32_t a1, uint32_t a2, uint32_t a3, uint32_t b0, uint32_t b1)
{
    asm volatile(
        "mma.sync.aligned.m16n8k16.row.col.f32.bf16.bf16.f32 "
        "{%0,%1,%2,%3}, {%4,%5,%6,%7}, {%8,%9}, {%0,%1,%2,%3};"
        : "+f"(c[0]), "+f"(c[1]), "+f"(c[2]), "+f"(c[3])
        : "r"(a0), "r"(a1), "r"(a2), "r"(a3), "r"(b0), "r"(b1));
}

__device__ __forceinline__ void mma16816h(float* c,
    uint32_t a0, uint32_t a1, uint32_t a2, uint32_t a3, uint32_t b0, uint32_t b1)
{
    asm volatile(
        "mma.sync.aligned.m16n8k16.row.col.f32.f16.f16.f32 "
        "{%0,%1,%2,%3}, {%4,%5,%6,%7}, {%8,%9}, {%0,%1,%2,%3};"
        : "+f"(c[0]), "+f"(c[1]), "+f"(c[2]), "+f"(c[3])
        : "r"(a0), "r"(a1), "r"(a2), "r"(a3), "r"(b0), "r"(b1));
}

__device__ __forceinline__ uint32_t pack_h2(float x, float y) {
    __half2 t = __floats2half2_rn(x, y);
    return *reinterpret_cast<uint32_t*>(&t);
}

__device__ __forceinline__ void store_hilo(__nv_bfloat16* hi, __nv_bfloat16* lo,
                                           size_t off, float a, float b)
{
    __nv_bfloat16 ha = __float2bfloat16(a), hb = __float2bfloat16(b);
    *(__nv_bfloat162*)(hi + off) = __halves2bfloat162(ha, hb);
    *(__nv_bfloat162*)(lo + off) = __halves2bfloat162(
        __float2bfloat16(a - __bfloat162float(ha)),
        __float2bfloat16(b - __bfloat162float(hb)));
}

// ---------------------------------------------------------------------------
// Shared GEMM machinery (BK=32, pitch 80 B, 2-stage cp.async)
// ---------------------------------------------------------------------------
#define BK        32
#define ROWB      80
#define TILEB     (128 * ROWB)
#define OFF_AHI   0
#define OFF_ALO   (TILEB)
#define OFF_BHI   (2 * TILEB)
#define OFF_BLO   (3 * TILEB)
#define STAGEB    (4 * TILEB)
#define GEMM_DSMEM (2 * STAGEB)
#define NCHUNK    (KK / BK)

__device__ __forceinline__ void load_stage(uint32_t sBase,
    const __nv_bfloat16* Ahi, const __nv_bfloat16* Alo,
    const __nv_bfloat16* Bhi, const __nv_bfloat16* Blo,
    int row0, int col0, int k0, int tid)
{
#pragma unroll
    for (int t = 0; t < 8; t++) {
        int i    = tid + t * 256;
        int tile = i >> 9;
        int w    = i & 511;
        int r    = w >> 2;
        int seg  = w & 3;
        const __nv_bfloat16* src =
            (tile == 0) ? Ahi : (tile == 1) ? Alo : (tile == 2) ? Bhi : Blo;
        int rb = (tile < 2) ? row0 : col0;
        cp16(sBase + tile * TILEB + r * ROWB + seg * 16,
             src + (size_t)(rb + r) * KK + k0 + seg * 8);
    }
}

__device__ __forceinline__ void gemm_mainloop(uint32_t sBase,
    const __nv_bfloat16* Ahi, const __nv_bfloat16* Alo,
    const __nv_bfloat16* Bhi, const __nv_bfloat16* Blo,
    int row0, int col0, int tid, int lane, int wr, int wc,
    float acc[4][4][4])
{
    load_stage(sBase, Ahi, Alo, Bhi, Blo, row0, col0, 0, tid);
    CP_COMMIT();

#pragma unroll 1
    for (int c = 0; c < NCHUNK; c++) {
        const uint32_t st = sBase + (uint32_t)(c & 1) * STAGEB;
        if (c + 1 < NCHUNK) {
            load_stage(sBase + (uint32_t)((c + 1) & 1) * STAGEB,
                       Ahi, Alo, Bhi, Blo, row0, col0, (c + 1) * BK, tid);
            CP_COMMIT();
            CP_WAIT(1);
        } else {
            CP_WAIT(0);
        }
        __syncthreads();

        const uint32_t aHiW = st + OFF_AHI + (uint32_t)(wr * 64) * ROWB;
        const uint32_t aLoW = st + OFF_ALO + (uint32_t)(wr * 64) * ROWB;
        const uint32_t bHiW = st + OFF_BHI + (uint32_t)(wc * 32) * ROWB;
        const uint32_t bLoW = st + OFF_BLO + (uint32_t)(wc * 32) * ROWB;

#pragma unroll
        for (int ks = 0; ks < 2; ks++) {
            const uint32_t aoff = (uint32_t)((lane & 15) * ROWB
                                + (ks * 16 + ((lane >> 4) << 3)) * 2);
            uint32_t AH[4][4], AL[4][4];
#pragma unroll
            for (int am = 0; am < 4; am++) {
                ldm_x4(AH[am][0], AH[am][1], AH[am][2], AH[am][3],
                       aHiW + (uint32_t)(am * 16) * ROWB + aoff);
                ldm_x4(AL[am][0], AL[am][1], AL[am][2], AL[am][3],
                       aLoW + (uint32_t)(am * 16) * ROWB + aoff);
            }
            const uint32_t boff = (uint32_t)((((lane >> 4) << 3) + (lane & 7)) * ROWB
                                + (ks * 16 + ((lane >> 3) & 1) * 8) * 2);
            uint32_t BH[2][4], BL[2][4];
#pragma unroll
            for (int bn = 0; bn < 2; bn++) {
                ldm_x4(BH[bn][0], BH[bn][1], BH[bn][2], BH[bn][3],
                       bHiW + (uint32_t)(bn * 16) * ROWB + boff);
                ldm_x4(BL[bn][0], BL[bn][1], BL[bn][2], BL[bn][3],
                       bLoW + (uint32_t)(bn * 16) * ROWB + boff);
            }
#pragma unroll
            for (int am = 0; am < 4; am++)
#pragma unroll
                for (int an = 0; an < 4; an++) {
                    uint32_t b0h = BH[an >> 1][(an & 1) * 2];
                    uint32_t b1h = BH[an >> 1][(an & 1) * 2 + 1];
                    uint32_t b0l = BL[an >> 1][(an & 1) * 2];
                    uint32_t b1l = BL[an >> 1][(an & 1) * 2 + 1];
                    mma16816(acc[am][an], AH[am][0], AH[am][1], AH[am][2], AH[am][3], b0h, b1h);
                    mma16816(acc[am][an], AH[am][0], AH[am][1], AH[am][2], AH[am][3], b0l, b1l);
                    mma16816(acc[am][an], AL[am][0], AL[am][1], AL[am][2], AL[am][3], b0h, b1h);
                }
        }
        __syncthreads();
    }
}

// ---------------------------------------------------------------------------
// Fused QKV projection: one launch, 1-D grid of 768 CTAs.
// ---------------------------------------------------------------------------
__global__ __launch_bounds__(256) void gemm_qkv(
    const __nv_bfloat16* __restrict__ xhi, const __nv_bfloat16* __restrict__ xlo,
    const __nv_bfloat16* __restrict__ wqh, const __nv_bfloat16* __restrict__ wql,
    const __nv_bfloat16* __restrict__ wkh, const __nv_bfloat16* __restrict__ wkl,
    const __nv_bfloat16* __restrict__ wvh, const __nv_bfloat16* __restrict__ wvl,
    __nv_bfloat16* __restrict__ qh, __nv_bfloat16* __restrict__ ql,
    __nv_bfloat16* __restrict__ kh, __nv_bfloat16* __restrict__ kl,
    __half* __restrict__ vf,
    const float2* __restrict__ rope)
{
    extern __shared__ char dsm[];
    const uint32_t sBase = smem_u32(dsm);

    const int tid  = threadIdx.x;
    const int lane = tid & 31;
    const int wid  = tid >> 5;
    const int wr   = wid >> 2;
    const int wc   = wid & 3;

    const int bid = blockIdx.x;
    const __nv_bfloat16 *Bh, *Bl;
    __nv_bfloat16 *Oh = nullptr, *Ol = nullptr;
    int row0, col0, N, mode;                  // mode: 0=rope hi/lo, 1=V fp16
    if (bid < 512) {
        row0 = (bid >> 4) * 128; col0 = (bid & 15) * 128;
        Bh = wqh; Bl = wql; Oh = qh; Ol = ql; N = NQ; mode = 0;
    } else if (bid < 640) {
        int i = bid - 512;
        row0 = (i >> 2) * 128; col0 = (i & 3) * 128;
        Bh = wkh; Bl = wkl; Oh = kh; Ol = kl; N = NKV; mode = 0;
    } else {
        int i = bid - 640;
        row0 = (i >> 2) * 128; col0 = (i & 3) * 128;
        Bh = wvh; Bl = wvl; N = NKV; mode = 1;
    }

    float acc[4][4][4];
#pragma unroll
    for (int i = 0; i < 4; i++)
#pragma unroll
        for (int j = 0; j < 4; j++)
#pragma unroll
            for (int l = 0; l < 4; l++) acc[i][j][l] = 0.0f;

    gemm_mainloop(sBase, xhi, xlo, Bh, Bl, row0, col0, tid, lane, wr, wc, acc);

    const int rbase = row0 + wr * 64;
    const int cbase = col0 + wc * 32;
#pragma unroll
    for (int am = 0; am < 4; am++)
#pragma unroll
        for (int an = 0; an < 4; an++) {
            float* cf = acc[am][an];
            int r  = rbase + am * 16 + (lane >> 2);
            int cc = cbase + an * 8 + (lane & 3) * 2;
            if (mode == 0) {
                int p = (cc & 127) >> 1;
                float2 cs0 = rope[(size_t)(r & (SS - 1)) * 64 + p];
                float2 cs1 = rope[(size_t)((r + 8) & (SS - 1)) * 64 + p];
                float o0 = cf[0] * cs0.x - cf[1] * cs0.y;
                float o1 = cf[0] * cs0.y + cf[1] * cs0.x;
                float o2 = cf[2] * cs1.x - cf[3] * cs1.y;
                float o3 = cf[2] * cs1.y + cf[3] * cs1.x;
                store_hilo(Oh, Ol, (size_t)r * N + cc,       o0, o1);
                store_hilo(Oh, Ol, (size_t)(r + 8) * N + cc, o2, o3);
            } else {
                *(__half2*)(vf + (size_t)r * N + cc)       = __floats2half2_rn(cf[0], cf[1]);
                *(__half2*)(vf + (size_t)(r + 8) * N + cc) = __floats2half2_rn(cf[2], cf[3]);
            }
        }
}

// ---------------------------------------------------------------------------
// O-projection GEMM: fp32 C output
// ---------------------------------------------------------------------------
__global__ __launch_bounds__(256) void gemm_oproj(
    const __nv_bfloat16* __restrict__ Ahi, const __nv_bfloat16* __restrict__ Alo,
    const __nv_bfloat16* __restrict__ Bhi, const __nv_bfloat16* __restrict__ Blo,
    float* __restrict__ C, int N)
{
    extern __shared__ char dsm[];
    const uint32_t sBase = smem_u32(dsm);

    const int tid  = threadIdx.x;
    const int lane = tid & 31;
    const int wid  = tid >> 5;
    const int wr   = wid >> 2;
    const int wc   = wid & 3;
    const int row0 = blockIdx.y * 128;
    const int col0 = blockIdx.x * 128;

    float acc[4][4][4];
#pragma unroll
    for (int i = 0; i < 4; i++)
#pragma unroll
        for (int j = 0; j < 4; j++)
#pragma unroll
            for (int l = 0; l < 4; l++) acc[i][j][l] = 0.0f;

    gemm_mainloop(sBase, Ahi, Alo, Bhi, Blo, row0, col0, tid, lane, wr, wc, acc);

    const int rbase = row0 + wr * 64;
    const int cbase = col0 + wc * 32;
#pragma unroll
    for (int am = 0; am < 4; am++)
#pragma unroll
        for (int an = 0; an < 4; an++) {
            float* cf = acc[am][an];
            int r  = rbase + am * 16 + (lane >> 2);
            int cc = cbase + an * 8 + (lane & 3) * 2;
            *(float2*)(C + (size_t)r * N + cc)       = make_float2(cf[0], cf[1]);
            *(float2*)(C + (size_t)(r + 8) * N + cc) = make_float2(cf[2], cf[3]);
        }
}

// ---------------------------------------------------------------------------
// Merged prep kernel: rope table + x split + 4 weight transpose/splits
// in one launch. Regions by blockIdx.x:
//   [0,512):            rope table (SS*64 = 131072 entries)
//   [512,16896):        x fp32 -> bf16 hi/lo (MM*KK/2 float2 = 4194304)
//   [16896,20992):      Wq transpose+split (64x64 tiles)
//   [20992,22016):      Wk (16x64)
//   [22016,23040):      Wv (16x64)
//   [23040,27136):      Wo (64x64)
// ---------------------------------------------------------------------------
#define PREP_GRID 27136

__device__ __forceinline__ void transpose_tile(
    const float* __restrict__ src, __nv_bfloat16* __restrict__ hi,
    __nv_bfloat16* __restrict__ lo, int N, int bx, int by,
    float (*t)[33], int tx, int ty)
{
    int k0 = by * 32, n0 = bx * 32;
#pragma unroll
    for (int j = 0; j < 32; j += 8)
        t[ty + j][tx] = src[(size_t)(k0 + ty + j) * N + n0 + tx];
    __syncthreads();
#pragma unroll
    for (int j = 0; j < 32; j += 8) {
        float v = t[tx][ty + j];
        __nv_bfloat16 h = __float2bfloat16(v);
        size_t o = (size_t)(n0 + ty + j) * KK + k0 + tx;
        hi[o] = h;
        lo[o] = __float2bfloat16(v - __bfloat162float(h));
    }
}

__global__ __launch_bounds__(256) void prep_kernel(
    const float* __restrict__ x,
    __nv_bfloat162* __restrict__ xhi2, __nv_bfloat162* __restrict__ xlo2,
    const float* __restrict__ Wq, const float* __restrict__ Wk,
    const float* __restrict__ Wv, const float* __restrict__ Wo,
    __nv_bfloat16* __restrict__ wqh, __nv_bfloat16* __restrict__ wql,
    __nv_bfloat16* __restrict__ wkh, __nv_bfloat16* __restrict__ wkl,
    __nv_bfloat16* __restrict__ wvh, __nv_bfloat16* __restrict__ wvl,
    __nv_bfloat16* __restrict__ woh, __nv_bfloat16* __restrict__ wol,
    float2* __restrict__ ropet)
{
    __shared__ float t[32][33];
    const int bid = blockIdx.x;
    const int tid = threadIdx.x;

    if (bid < 512) {
        int i = bid * 256 + tid;
        int s = i >> 6, p = i & 63;
        float e   = (float)(2 * p) * (1.0f / 128.0f);
        float inv = 1.0f / powf(10000.0f, e);
        float sn, c;
        sincosf((float)s * inv, &sn, &c);
        ropet[i] = make_float2(c, sn);
    } else if (bid < 16896) {
        int i = (bid - 512) * 256 + tid;
        float2 v = ((const float2*)x)[i];
        __nv_bfloat16 hx = __float2bfloat16(v.x);
        __nv_bfloat16 hy = __float2bfloat16(v.y);
        xhi2[i] = __halves2bfloat162(hx, hy);
        xlo2[i] = __halves2bfloat162(
            __float2bfloat16(v.x - __bfloat162float(hx)),
            __float2bfloat16(v.y - __bfloat162float(hy)));
    } else {
        int r = bid - 16896;
        int tx = tid & 31, ty = tid >> 5;
        if (r < 4096)
            transpose_tile(Wq, wqh, wql, NQ,  r & 63, r >> 6, t, tx, ty);
        else if (r < 5120)
            transpose_tile(Wk, wkh, wkl, NKV, (r - 4096) & 15, (r - 4096) >> 4, t, tx, ty);
        else if (r < 6144)
            transpose_tile(Wv, wvh, wvl, NKV, (r - 5120) & 15, (r - 5120) >> 4, t, tx, ty);
        else
            transpose_tile(Wo, woh, wol, NQ,  (r - 6144) & 63, (r - 6144) >> 6, t, tx, ty);
    }
}

// ---------------------------------------------------------------------------
// Flash attention: S = QK^T in bf16x3, P·V in single fp16. Causal, GQA 4:1.
// LPT 1-D grid. 3-stage KV ring (prefetch distance 2).
// ---------------------------------------------------------------------------
#define AP      272
#define QTB     (128 * AP)
#define KVTB    (64 * AP)
#define KVB     (2 * QTB)
#define KVSTG   (3 * KVTB)
#define ATTN_SMEM (2 * QTB + 3 * KVSTG)   // 226304

__device__ __forceinline__ void load_kv_tile(uint32_t sb, uint32_t stg,
    const __nv_bfloat16* kh, const __nv_bfloat16* kl,
    const __half* vf, int k0, int tid)
{
#pragma unroll
    for (int t = 0; t < 12; t++) {
        int i  = tid + t * 256;
        int m  = i >> 10;
        int w  = i & 1023;
        int r  = w >> 4;
        int sg = w & 15;
        const void* src = (m == 0) ? (const void*)(kh + (size_t)(k0 + r) * NKV + sg * 8)
                        : (m == 1) ? (const void*)(kl + (size_t)(k0 + r) * NKV + sg * 8)
                                   : (const void*)(vf + (size_t)(k0 + r) * NKV + sg * 8);
        cp16(sb + stg + (uint32_t)m * KVTB + (uint32_t)(r * AP + sg * 16), src);
    }
}

__global__ __launch_bounds__(256) void attn_mma(
    const __nv_bfloat16* __restrict__ qhi, const __nv_bfloat16* __restrict__ qlo,
    const __nv_bfloat16* __restrict__ khi, const __nv_bfloat16* __restrict__ klo,
    const __half* __restrict__ vf,
    __nv_bfloat16* __restrict__ ohi, __nv_bfloat16* __restrict__ olo)
{
    extern __shared__ char sm[];
    const uint32_t sb = smem_u32(sm);

    const int bid = blockIdx.x;
    const int qt  = (SS / 128 - 1) - (bid >> 5);
    const int hb  = bid & 31;
    const int h   = hb & 15;
    const int b   = hb >> 4;
    const int kvh = h >> 2;
    const int q0  = qt * 128;

    const int tid  = threadIdx.x;
    const int lane = tid & 31;
    const int wid  = tid >> 5;
    const int wq0  = wid * 16;
    const int gr   = lane >> 2;

    const __nv_bfloat16* qhb = qhi + ((size_t)b * SS + q0) * NQ + h * HDIM;
    const __nv_bfloat16* qlb = qlo + ((size_t)b * SS + q0) * NQ + h * HDIM;
    const __nv_bfloat16* khb = khi + (size_t)b * SS * NKV + kvh * HDIM;
    const __nv_bfloat16* klb = klo + (size_t)b * SS * NKV + kvh * HDIM;
    const __half*        vfb = vf  + (size_t)b * SS * NKV + kvh * HDIM;

    const int ntiles = 2 * qt + 2;

    // group 0: Q + KV tile 0
#pragma unroll
    for (int t = 0; t < 16; t++) {
        int i   = tid + t * 256;
        int hl  = i >> 11;
        int w   = i & 2047;
        int r   = w >> 4;
        int sg  = w & 15;
        const __nv_bfloat16* src = hl ? qlb : qhb;
        cp16(sb + (uint32_t)hl * QTB + (uint32_t)(r * AP + sg * 16),
             src + (size_t)r * NQ + sg * 8);
    }
    load_kv_tile(sb, KVB, khb, klb, vfb, 0, tid);
    CP_COMMIT();
    // group 1: KV tile 1 (ntiles >= 2 always)
    load_kv_tile(sb, KVB + KVSTG, khb, klb, vfb, 64, tid);
    CP_COMMIT();

    float oacc[16][4];
#pragma unroll
    for (int j = 0; j < 16; j++)
#pragma unroll
        for (int e = 0; e < 4; e++) oacc[j][e] = 0.0f;
    float mA = -1e30f, mB = -1e30f, lA = 0.0f, lB = 0.0f;

    const float scale = 0.08838834764831845f;
    const int rAg = q0 + wq0 + gr;
    const int rBg = rAg + 8;

#pragma unroll 1
    for (int t = 0; t < ntiles; t++) {
        if (t + 2 < ntiles) {
            load_kv_tile(sb, KVB + (uint32_t)((t + 2) % 3) * KVSTG,
                         khb, klb, vfb, (t + 2) * 64, tid);
            CP_COMMIT();
            CP_WAIT(2);
        } else if (t + 1 < ntiles) {
            CP_WAIT(1);
        } else {
            CP_WAIT(0);
        }
        __syncthreads();

        const uint32_t kv = sb + KVB + (uint32_t)(t % 3) * KVSTG;

        // ---- S = Q @ K^T (bf16 hi/lo x3, shared fragments) ----
        float sacc[8][4];
#pragma unroll
        for (int j = 0; j < 8; j++)
#pragma unroll
            for (int e = 0; e < 4; e++) sacc[j][e] = 0.0f;

        const uint32_t aB = sb + (uint32_t)wq0 * AP;
#pragma unroll
        for (int c = 0; c < 8; c++) {
            const uint32_t ao = (uint32_t)((lane & 15) * AP
                              + (c * 16 + ((lane >> 4) << 3)) * 2);
            uint32_t ah0, ah1, ah2, ah3, al0, al1, al2, al3;
            ldm_x4(ah0, ah1, ah2, ah3, aB + ao);
            ldm_x4(al0, al1, al2, al3, aB + QTB + ao);
#pragma unroll
            for (int g = 0; g < 4; g++) {
                const uint32_t bo = (uint32_t)((g * 16 + ((lane >> 4) << 3) + (lane & 7)) * AP
                                  + (c * 16 + ((lane >> 3) & 1) * 8) * 2);
                uint32_t bh0, bh1, bh2, bh3, bl0, bl1, bl2, bl3;
                ldm_x4(bh0, bh1, bh2, bh3, kv + bo);
                ldm_x4(bl0, bl1, bl2, bl3, kv + KVTB + bo);
                mma16816(sacc[2 * g],     ah0, ah1, ah2, ah3, bh0, bh1);
                mma16816(sacc[2 * g + 1], ah0, ah1, ah2, ah3, bh2, bh3);
                mma16816(sacc[2 * g],     ah0, ah1, ah2, ah3, bl0, bl1);
                mma16816(sacc[2 * g + 1], ah0, ah1, ah2, ah3, bl2, bl3);
                mma16816(sacc[2 * g],     al0, al1, al2, al3, bh0, bh1);
                mma16816(sacc[2 * g + 1], al0, al1, al2, al3, bh2, bh3);
            }
        }

#pragma unroll
        for (int j = 0; j < 8; j++)
#pragma unroll
            for (int e = 0; e < 4; e++) sacc[j][e] *= scale;

        if (t >= 2 * qt) {
#pragma unroll
            for (int j = 0; j < 8; j++) {
                int col = t * 64 + j * 8 + 2 * (lane & 3);
                if (col     > rAg) sacc[j][0] = -1e30f;
                if (col + 1 > rAg) sacc[j][1] = -1e30f;
                if (col     > rBg) sacc[j][2] = -1e30f;
                if (col + 1 > rBg) sacc[j][3] = -1e30f;
            }
        }

        // ---- online softmax ----
        float mxA = -1e30f, mxB = -1e30f;
#pragma unroll
        for (int j = 0; j < 8; j++) {
            mxA = fmaxf(mxA, fmaxf(sacc[j][0], sacc[j][1]));
            mxB = fmaxf(mxB, fmaxf(sacc[j][2], sacc[j][3]));
        }
        mxA = fmaxf(mxA, __shfl_xor_sync(0xffffffffu, mxA, 1));
        mxA = fmaxf(mxA, __shfl_xor_sync(0xffffffffu, mxA, 2));
        mxB = fmaxf(mxB, __shfl_xor_sync(0xffffffffu, mxB, 1));
        mxB = fmaxf(mxB, __shfl_xor_sync(0xffffffffu, mxB, 2));

        float mnA = fmaxf(mA, mxA), mnB = fmaxf(mB, mxB);
        float facA = __expf(mA - mnA), facB = __expf(mB - mnB);
        float sA = 0.0f, sB = 0.0f;
#pragma unroll
        for (int j = 0; j < 8; j++) {
            float p0 = __expf(sacc[j][0] - mnA);
            float p1 = __expf(sacc[j][1] - mnA);
            float p2 = __expf(sacc[j][2] - mnB);
            float p3 = __expf(sacc[j][3] - mnB);
            sacc[j][0] = p0; sacc[j][1] = p1; sacc[j][2] = p2; sacc[j][3] = p3;
            sA += p0 + p1; sB += p2 + p3;
        }
        sA += __shfl_xor_sync(0xffffffffu, sA, 1);
        sA += __shfl_xor_sync(0xffffffffu, sA, 2);
        sB += __shfl_xor_sync(0xffffffffu, sB, 1);
        sB += __shfl_xor_sync(0xffffffffu, sB, 2);
        lA = lA * facA + sA; lB = lB * facB + sB;
        mA = mnA; mB = mnB;
#pragma unroll
        for (int j = 0; j < 16; j++) {
            oacc[j][0] *= facA; oacc[j][1] *= facA;
            oacc[j][2] *= facB; oacc[j][3] *= facB;
        }

        // ---- O += P @ V (single fp16 pass) ----
#pragma unroll
        for (int kc = 0; kc < 4; kc++) {
            const int j0 = 2 * kc, j1 = 2 * kc + 1;
            uint32_t ph[4];
            ph[0] = pack_h2(sacc[j0][0], sacc[j0][1]);
            ph[1] = pack_h2(sacc[j0][2], sacc[j0][3]);
            ph[2] = pack_h2(sacc[j1][0], sacc[j1][1]);
            ph[3] = pack_h2(sacc[j1][2], sacc[j1][3]);
#pragma unroll
            for (int bn = 0; bn < 8; bn++) {
                const uint32_t rowsel =
                    (uint32_t)((kc * 16 + ((lane >> 4) << 3) + (lane & 7)) * AP
                             + (bn * 16 + ((lane >> 3) & 1) * 8) * 2);
                uint32_t r0, r1, r2, r3;
                ldm_x4_t(r0, r1, r2, r3, kv + 2 * KVTB + rowsel);
                mma16816h(oacc[2 * bn],     ph[0], ph[1], ph[2], ph[3], r0, r2);
                mma16816h(oacc[2 * bn + 1], ph[0], ph[1], ph[2], ph[3], r1, r3);
            }
        }
        __syncthreads();
    }

    const float invA = 1.0f / lA, invB = 1.0f / lB;
    const size_t rowA = ((size_t)b * SS + rAg) * NQ;
    const size_t rowB = ((size_t)b * SS + rBg) * NQ;
#pragma unroll
    for (int j = 0; j < 16; j++) {
        int col = h * HDIM + j * 8 + 2 * (lane & 3);
        store_hilo(ohi, olo, rowA + col, oacc[j][0] * invA, oacc[j][1] * invA);
        store_hilo(ohi, olo, rowB + col, oacc[j][2] * invB, oacc[j][3] * invB);
    }
}

// ---------------------------------------------------------------------------
extern "C" void kernel_launch(void* const* d_in, const int* in_sizes, int n_in,
                              void* d_out, int out_size)
{
    const float* x  = (const float*)d_in[0];
    const float* Wq = (const float*)d_in[2];
    const float* Wk = (const float*)d_in[3];
    const float* Wv = (const float*)d_in[4];
    const float* Wo = (const float*)d_in[5];
    float* out = (float*)d_out;

    __nv_bfloat16 *xhi, *xlo, *ahi, *alo, *qh, *ql, *kh, *kl;
    __half *vf;
    __nv_bfloat16 *wqThi, *wqTlo, *wkThi, *wkTlo, *wvThi, *wvTlo, *woThi, *woTlo;
    float2* rope;
    (void)cudaGetSymbolAddress((void**)&xhi, g_xhi);
    (void)cudaGetSymbolAddress((void**)&xlo, g_xlo);
    (void)cudaGetSymbolAddress((void**)&ahi, g_ahi);
    (void)cudaGetSymbolAddress((void**)&alo, g_alo);
    (void)cudaGetSymbolAddress((void**)&qh, g_qhi);
    (void)cudaGetSymbolAddress((void**)&ql, g_qlo);
    (void)cudaGetSymbolAddress((void**)&kh, g_khi);
    (void)cudaGetSymbolAddress((void**)&kl, g_klo);
    (void)cudaGetSymbolAddress((void**)&vf, g_vf);
    (void)cudaGetSymbolAddress((void**)&wqThi, g_wqThi);
    (void)cudaGetSymbolAddress((void**)&wqTlo, g_wqTlo);
    (void)cudaGetSymbolAddress((void**)&wkThi, g_wkThi);
    (void)cudaGetSymbolAddress((void**)&wkTlo, g_wkTlo);
    (void)cudaGetSymbolAddress((void**)&wvThi, g_wvThi);
    (void)cudaGetSymbolAddress((void**)&wvTlo, g_wvTlo);
    (void)cudaGetSymbolAddress((void**)&woThi, g_woThi);
    (void)cudaGetSymbolAddress((void**)&woTlo, g_woTlo);
    (void)cudaGetSymbolAddress((void**)&rope, g_rope);

    (void)cudaFuncSetAttribute(gemm_qkv,
                               cudaFuncAttributeMaxDynamicSharedMemorySize, GEMM_DSMEM);
    (void)cudaFuncSetAttribute(gemm_oproj,
                               cudaFuncAttributeMaxDynamicSharedMemorySize, GEMM_DSMEM);
    (void)cudaFuncSetAttribute(attn_mma,
                               cudaFuncAttributeMaxDynamicSharedMemorySize, ATTN_SMEM);

    // 1) merged prep: rope table + x split + weight transposes (one launch)
    prep_kernel<<<PREP_GRID, 256>>>(x,
                                    (__nv_bfloat162*)xhi, (__nv_bfloat162*)xlo,
                                    Wq, Wk, Wv, Wo,
                                    wqThi, wqTlo, wkThi, wkTlo,
                                    wvThi, wvTlo, woThi, woTlo, rope);

    // 2) fused QKV projection (Q,K: rope+bf16 hi/lo; V: fp16 single)
    gemm_qkv<<<768, 256, GEMM_DSMEM>>>(xhi, xlo,
                                       wqThi, wqTlo, wkThi, wkTlo, wvThi, wvTlo,
                                       qh, ql, kh, kl, vf, rope);

    // 3) attention (LPT 1-D grid; PV in fp16; 3-stage KV ring)
    attn_mma<<<(SS / 128) * NHQ * BB, 256, ATTN_SMEM>>>(qh, ql, kh, kl, vf, ahi, alo);

    // 4) output projection -> fp32 out
    gemm_oproj<<<dim3(NQ / 128, MM / 128), 256, GEMM_DSMEM>>>(
        ahi, alo, woThi, woTlo, out, NQ);
}

// round 10
// speedup vs baseline: 5.1267x; 1.3473x over previous
#include <cuda_runtime.h>
#include <cuda_bf16.h>
#include <cuda_fp16.h>
#include <math.h>
#include <stdint.h>

#define BB   2
#define SS   2048
#define DD   2048
#define NHQ  16
#define NKVH 4
#define HDIM 128
#define MM   (BB*SS)       // 4096
#define KK   2048
#define NQ   (NHQ*HDIM)    // 2048
#define NKV  (NKVH*HDIM)   // 512

// ---------------- scratch (device globals; no allocation allowed) ----------
__device__ __half g_xhi[(size_t)MM*KK],  g_xlo[(size_t)MM*KK];
__device__ __half g_ahi[(size_t)MM*NQ],  g_alo[(size_t)MM*NQ];
__device__ __half g_qhi[(size_t)MM*NQ],  g_qlo[(size_t)MM*NQ];
__device__ __half g_kf[(size_t)MM*NKV];                // K fp16 single (roped)
__device__ __half g_vf[(size_t)MM*NKV];                // V fp16 single
__device__ __half g_wqT[(size_t)NQ*KK];
__device__ __half g_wkT[(size_t)NKV*KK];
__device__ __half g_wvT[(size_t)NKV*KK];
__device__ __half g_woT[(size_t)NQ*KK];
__device__ float2 g_rope[(size_t)SS*64];               // (cos, sin)

// ---------------- PTX helpers ----------------------------------------------
__device__ __forceinline__ uint32_t smem_u32(const void* p) {
    uint32_t a;
    asm("{ .reg .u64 t; cvta.to.shared.u64 t, %1; cvt.u32.u64 %0, t; }"
        : "=r"(a) : "l"(p));
    return a;
}

__device__ __forceinline__ void cp16(uint32_t s, const void* g) {
    asm volatile("cp.async.cg.shared.global [%0], [%1], 16;" :: "r"(s), "l"(g));
}
#define CP_COMMIT() asm volatile("cp.async.commit_group;" ::: "memory")
#define CP_WAIT(n)  asm volatile("cp.async.wait_group %0;" :: "n"(n) : "memory")

__device__ __forceinline__ void ldm_x4(uint32_t& r0, uint32_t& r1,
                                       uint32_t& r2, uint32_t& r3, uint32_t a) {
    asm volatile("ldmatrix.sync.aligned.m8n8.x4.shared.b16 {%0,%1,%2,%3}, [%4];"
                 : "=r"(r0), "=r"(r1), "=r"(r2), "=r"(r3) : "r"(a));
}
__device__ __forceinline__ void ldm_x4_t(uint32_t& r0, uint32_t& r1,
                                         uint32_t& r2, uint32_t& r3, uint32_t a) {
    asm volatile("ldmatrix.sync.aligned.m8n8.x4.trans.shared.b16 {%0,%1,%2,%3}, [%4];"
                 : "=r"(r0), "=r"(r1), "=r"(r2), "=r"(r3) : "r"(a));
}

__device__ __forceinline__ void mma16816h(float* c,
    uint32_t a0, uint32_t a1, uint32_t a2, uint32_t a3, uint32_t b0, uint32_t b1)
{
    asm volatile(
        "mma.sync.aligned.m16n8k16.row.col.f32.f16.f16.f32 "
        "{%0,%1,%2,%3}, {%4,%5,%6,%7}, {%8,%9}, {%0,%1,%2,%3};"
        : "+f"(c[0]), "+f"(c[1]), "+f"(c[2]), "+f"(c[3])
        : "r"(a0), "r"(a1), "r"(a2), "r"(a3), "r"(b0), "r"(b1));
}

__device__ __forceinline__ uint32_t pack_h2(float x, float y) {
    __half2 t = __floats2half2_rn(x, y);
    return *reinterpret_cast<uint32_t*>(&t);
}

__device__ __forceinline__ void store_hilo_h(__half* hi, __half* lo,
                                             size_t off, float a, float b)
{
    __half ha = __float2half(a), hb = __float2half(b);
    *(__half2*)(hi + off) = __halves2half2(ha, hb);
    *(__half2*)(lo + off) = __halves2half2(
        __float2half(a - __half2float(ha)),
        __float2half(b - __half2float(hb)));
}

// ---------------------------------------------------------------------------
// Shared GEMM machinery: fp16 x2 (A hi/lo, B single). BK=32, pitch 80 B,
// 2-stage cp.async. Stage = Ahi + Alo + B = 3 tiles.
// ---------------------------------------------------------------------------
#define BK        32
#define ROWB      80
#define TILEB     (128 * ROWB)
#define OFF_AHI   0
#define OFF_ALO   (TILEB)
#define OFF_B     (2 * TILEB)
#define STAGEB    (3 * TILEB)          // 30720
#define GEMM_DSMEM (2 * STAGEB)        // 61440
#define NCHUNK    (KK / BK)            // 64

__device__ __forceinline__ void load_stage(uint32_t sBase,
    const __half* Ahi, const __half* Alo, const __half* Bs,
    int row0, int col0, int k0, int tid)
{
#pragma unroll
    for (int t = 0; t < 6; t++) {
        int i    = tid + t * 256;
        int tile = i >> 9;                 // constant per unrolled t
        int w    = i & 511;
        int r    = w >> 2;
        int seg  = w & 3;
        const __half* src = (tile == 0) ? Ahi : (tile == 1) ? Alo : Bs;
        int rb = (tile < 2) ? row0 : col0;
        cp16(sBase + tile * TILEB + r * ROWB + seg * 16,
             src + (size_t)(rb + r) * KK + k0 + seg * 8);
    }
}

__device__ __forceinline__ void gemm_mainloop(uint32_t sBase,
    const __half* Ahi, const __half* Alo, const __half* Bs,
    int row0, int col0, int tid, int lane, int wr, int wc,
    float acc[4][4][4])
{
    load_stage(sBase, Ahi, Alo, Bs, row0, col0, 0, tid);
    CP_COMMIT();

#pragma unroll 1
    for (int c = 0; c < NCHUNK; c++) {
        const uint32_t st = sBase + (uint32_t)(c & 1) * STAGEB;
        if (c + 1 < NCHUNK) {
            load_stage(sBase + (uint32_t)((c + 1) & 1) * STAGEB,
                       Ahi, Alo, Bs, row0, col0, (c + 1) * BK, tid);
            CP_COMMIT();
            CP_WAIT(1);
        } else {
            CP_WAIT(0);
        }
        __syncthreads();

        const uint32_t aHiW = st + OFF_AHI + (uint32_t)(wr * 64) * ROWB;
        const uint32_t aLoW = st + OFF_ALO + (uint32_t)(wr * 64) * ROWB;
        const uint32_t bW   = st + OFF_B   + (uint32_t)(wc * 32) * ROWB;

#pragma unroll
        for (int ks = 0; ks < 2; ks++) {
            const uint32_t aoff = (uint32_t)((lane & 15) * ROWB
                                + (ks * 16 + ((lane >> 4) << 3)) * 2);
            uint32_t AH[4][4], AL[4][4];
#pragma unroll
            for (int am = 0; am < 4; am++) {
                ldm_x4(AH[am][0], AH[am][1], AH[am][2], AH[am][3],
                       aHiW + (uint32_t)(am * 16) * ROWB + aoff);
                ldm_x4(AL[am][0], AL[am][1], AL[am][2], AL[am][3],
                       aLoW + (uint32_t)(am * 16) * ROWB + aoff);
            }
            const uint32_t boff = (uint32_t)((((lane >> 4) << 3) + (lane & 7)) * ROWB
                                + (ks * 16 + ((lane >> 3) & 1) * 8) * 2);
            uint32_t Bx[2][4];
#pragma unroll
            for (int bn = 0; bn < 2; bn++)
                ldm_x4(Bx[bn][0], Bx[bn][1], Bx[bn][2], Bx[bn][3],
                       bW + (uint32_t)(bn * 16) * ROWB + boff);
#pragma unroll
            for (int am = 0; am < 4; am++)
#pragma unroll
                for (int an = 0; an < 4; an++) {
                    uint32_t b0 = Bx[an >> 1][(an & 1) * 2];
                    uint32_t b1 = Bx[an >> 1][(an & 1) * 2 + 1];
                    mma16816h(acc[am][an], AH[am][0], AH[am][1], AH[am][2], AH[am][3], b0, b1);
                    mma16816h(acc[am][an], AL[am][0], AL[am][1], AL[am][2], AL[am][3], b0, b1);
                }
        }
        __syncthreads();
    }
}

// ---------------------------------------------------------------------------
// Fused QKV projection: 1-D grid of 768 CTAs.
//   [0,512):   Q -> rope + fp16 hi/lo
//   [512,640): K -> rope + fp16 single
//   [640,768): V -> fp16 single
// ---------------------------------------------------------------------------
__global__ __launch_bounds__(256) void gemm_qkv(
    const __half* __restrict__ xhi, const __half* __restrict__ xlo,
    const __half* __restrict__ wq, const __half* __restrict__ wk,
    const __half* __restrict__ wv,
    __half* __restrict__ qh, __half* __restrict__ ql,
    __half* __restrict__ kf, __half* __restrict__ vf,
    const float2* __restrict__ rope)
{
    extern __shared__ char dsm[];
    const uint32_t sBase = smem_u32(dsm);

    const int tid  = threadIdx.x;
    const int lane = tid & 31;
    const int wid  = tid >> 5;
    const int wr   = wid >> 2;
    const int wc   = wid & 3;

    const int bid = blockIdx.x;
    const __half* Bs;
    int row0, col0, N, mode;   // 0=Q rope hi/lo, 1=K rope single, 2=V single
    if (bid < 512) {
        row0 = (bid >> 4) * 128; col0 = (bid & 15) * 128;
        Bs = wq; N = NQ; mode = 0;
    } else if (bid < 640) {
        int i = bid - 512;
        row0 = (i >> 2) * 128; col0 = (i & 3) * 128;
        Bs = wk; N = NKV; mode = 1;
    } else {
        int i = bid - 640;
        row0 = (i >> 2) * 128; col0 = (i & 3) * 128;
        Bs = wv; N = NKV; mode = 2;
    }

    float acc[4][4][4];
#pragma unroll
    for (int i = 0; i < 4; i++)
#pragma unroll
        for (int j = 0; j < 4; j++)
#pragma unroll
            for (int l = 0; l < 4; l++) acc[i][j][l] = 0.0f;

    gemm_mainloop(sBase, xhi, xlo, Bs, row0, col0, tid, lane, wr, wc, acc);

    const int rbase = row0 + wr * 64;
    const int cbase = col0 + wc * 32;
#pragma unroll
    for (int am = 0; am < 4; am++)
#pragma unroll
        for (int an = 0; an < 4; an++) {
            float* cf = acc[am][an];
            int r  = rbase + am * 16 + (lane >> 2);
            int cc = cbase + an * 8 + (lane & 3) * 2;
            if (mode == 2) {
                *(__half2*)(vf + (size_t)r * N + cc)       = __floats2half2_rn(cf[0], cf[1]);
                *(__half2*)(vf + (size_t)(r + 8) * N + cc) = __floats2half2_rn(cf[2], cf[3]);
            } else {
                int p = (cc & 127) >> 1;
                float2 cs0 = rope[(size_t)(r & (SS - 1)) * 64 + p];
                float2 cs1 = rope[(size_t)((r + 8) & (SS - 1)) * 64 + p];
                float o0 = cf[0] * cs0.x - cf[1] * cs0.y;
                float o1 = cf[0] * cs0.y + cf[1] * cs0.x;
                float o2 = cf[2] * cs1.x - cf[3] * cs1.y;
                float o3 = cf[2] * cs1.y + cf[3] * cs1.x;
                if (mode == 0) {
                    store_hilo_h(qh, ql, (size_t)r * N + cc,       o0, o1);
                    store_hilo_h(qh, ql, (size_t)(r + 8) * N + cc, o2, o3);
                } else {
                    *(__half2*)(kf + (size_t)r * N + cc)       = __floats2half2_rn(o0, o1);
                    *(__half2*)(kf + (size_t)(r + 8) * N + cc) = __floats2half2_rn(o2, o3);
                }
            }
        }
}

// ---------------------------------------------------------------------------
// O-projection GEMM: fp32 C output
// ---------------------------------------------------------------------------
__global__ __launch_bounds__(256) void gemm_oproj(
    const __half* __restrict__ Ahi, const __half* __restrict__ Alo,
    const __half* __restrict__ Bs, float* __restrict__ C, int N)
{
    extern __shared__ char dsm[];
    const uint32_t sBase = smem_u32(dsm);

    const int tid  = threadIdx.x;
    const int lane = tid & 31;
    const int wid  = tid >> 5;
    const int wr   = wid >> 2;
    const int wc   = wid & 3;
    const int row0 = blockIdx.y * 128;
    const int col0 = blockIdx.x * 128;

    float acc[4][4][4];
#pragma unroll
    for (int i = 0; i < 4; i++)
#pragma unroll
        for (int j = 0; j < 4; j++)
#pragma unroll
            for (int l = 0; l < 4; l++) acc[i][j][l] = 0.0f;

    gemm_mainloop(sBase, Ahi, Alo, Bs, row0, col0, tid, lane, wr, wc, acc);

    const int rbase = row0 + wr * 64;
    const int cbase = col0 + wc * 32;
#pragma unroll
    for (int am = 0; am < 4; am++)
#pragma unroll
        for (int an = 0; an < 4; an++) {
            float* cf = acc[am][an];
            int r  = rbase + am * 16 + (lane >> 2);
            int cc = cbase + an * 8 + (lane & 3) * 2;
            *(float2*)(C + (size_t)r * N + cc)       = make_float2(cf[0], cf[1]);
            *(float2*)(C + (size_t)(r + 8) * N + cc) = make_float2(cf[2], cf[3]);
        }
}

// ---------------------------------------------------------------------------
// Merged prep: rope table + x fp16 hi/lo split + 4 weight transposes (fp16)
//   [0,512):       rope table
//   [512,16896):   x split
//   [16896,20992): Wq   [20992,22016): Wk   [22016,23040): Wv   [23040,27136): Wo
// ---------------------------------------------------------------------------
#define PREP_GRID 27136

__device__ __forceinline__ void transpose_tile_h(
    const float* __restrict__ src, __half* __restrict__ dst,
    int N, int bx, int by, float (*t)[33], int tx, int ty)
{
    int k0 = by * 32, n0 = bx * 32;
#pragma unroll
    for (int j = 0; j < 32; j += 8)
        t[ty + j][tx] = src[(size_t)(k0 + ty + j) * N + n0 + tx];
    __syncthreads();
#pragma unroll
    for (int j = 0; j < 32; j += 8)
        dst[(size_t)(n0 + ty + j) * KK + k0 + tx] = __float2half(t[tx][ty + j]);
}

__global__ __launch_bounds__(256) void prep_kernel(
    const float* __restrict__ x,
    __half2* __restrict__ xhi2, __half2* __restrict__ xlo2,
    const float* __restrict__ Wq, const float* __restrict__ Wk,
    const float* __restrict__ Wv, const float* __restrict__ Wo,
    __half* __restrict__ wq, __half* __restrict__ wk,
    __half* __restrict__ wv, __half* __restrict__ wo,
    float2* __restrict__ ropet)
{
    __shared__ float t[32][33];
    const int bid = blockIdx.x;
    const int tid = threadIdx.x;

    if (bid < 512) {
        int i = bid * 256 + tid;
        int s = i >> 6, p = i & 63;
        float e   = (float)(2 * p) * (1.0f / 128.0f);
        float inv = 1.0f / powf(10000.0f, e);
        float sn, c;
        sincosf((float)s * inv, &sn, &c);
        ropet[i] = make_float2(c, sn);
    } else if (bid < 16896) {
        int i = (bid - 512) * 256 + tid;
        float2 v = ((const float2*)x)[i];
        __half hx = __float2half(v.x);
        __half hy = __float2half(v.y);
        xhi2[i] = __halves2half2(hx, hy);
        xlo2[i] = __halves2half2(__float2half(v.x - __half2float(hx)),
                                 __float2half(v.y - __half2float(hy)));
    } else {
        int r = bid - 16896;
        int tx = tid & 31, ty = tid >> 5;
        if (r < 4096)
            transpose_tile_h(Wq, wq, NQ,  r & 63, r >> 6, t, tx, ty);
        else if (r < 5120)
            transpose_tile_h(Wk, wk, NKV, (r - 4096) & 15, (r - 4096) >> 4, t, tx, ty);
        else if (r < 6144)
            transpose_tile_h(Wv, wv, NKV, (r - 5120) & 15, (r - 5120) >> 4, t, tx, ty);
        else
            transpose_tile_h(Wo, wo, NQ,  (r - 6144) & 63, (r - 6144) >> 6, t, tx, ty);
    }
}

// ---------------------------------------------------------------------------
// Flash attention: S = Qhi·K + Qlo·K (fp16 x2), P·V fp16. Causal, GQA 4:1.
// LPT 1-D grid. 3-stage KV ring; stage = K + V (fp16) = 2 tiles.
// ---------------------------------------------------------------------------
#define AP      272
#define QTB     (128 * AP)
#define KVTB    (64 * AP)
#define KVB     (2 * QTB)
#define KVSTG   (2 * KVTB)
#define ATTN_SMEM (2 * QTB + 3 * KVSTG)   // 174080

__device__ __forceinline__ void load_kv_tile(uint32_t sb, uint32_t stg,
    const __half* kf, const __half* vf, int k0, int tid)
{
#pragma unroll
    for (int t = 0; t < 8; t++) {
        int i  = tid + t * 256;
        int m  = i >> 10;                  // 0..1, constant per unrolled t
        int w  = i & 1023;
        int r  = w >> 4;
        int sg = w & 15;
        const __half* src = m ? vf : kf;
        cp16(sb + stg + (uint32_t)m * KVTB + (uint32_t)(r * AP + sg * 16),
             src + (size_t)(k0 + r) * NKV + sg * 8);
    }
}

__global__ __launch_bounds__(256) void attn_mma(
    const __half* __restrict__ qhi, const __half* __restrict__ qlo,
    const __half* __restrict__ kf, const __half* __restrict__ vf,
    __half* __restrict__ ohi, __half* __restrict__ olo)
{
    extern __shared__ char sm[];
    const uint32_t sb = smem_u32(sm);

    const int bid = blockIdx.x;
    const int qt  = (SS / 128 - 1) - (bid >> 5);
    const int hb  = bid & 31;
    const int h   = hb & 15;
    const int b   = hb >> 4;
    const int kvh = h >> 2;
    const int q0  = qt * 128;

    const int tid  = threadIdx.x;
    const int lane = tid & 31;
    const int wid  = tid >> 5;
    const int wq0  = wid * 16;
    const int gr   = lane >> 2;

    const __half* qhb = qhi + ((size_t)b * SS + q0) * NQ + h * HDIM;
    const __half* qlb = qlo + ((size_t)b * SS + q0) * NQ + h * HDIM;
    const __half* kfb = kf + (size_t)b * SS * NKV + kvh * HDIM;
    const __half* vfb = vf + (size_t)b * SS * NKV + kvh * HDIM;

    const int ntiles = 2 * qt + 2;

    // group 0: Q hi/lo + KV tile 0
#pragma unroll
    for (int t = 0; t < 16; t++) {
        int i   = tid + t * 256;
        int hl  = i >> 11;
        int w   = i & 2047;
        int r   = w >> 4;
        int sg  = w & 15;
        const __half* src = hl ? qlb : qhb;
        cp16(sb + (uint32_t)hl * QTB + (uint32_t)(r * AP + sg * 16),
             src + (size_t)r * NQ + sg * 8);
    }
    load_kv_tile(sb, KVB, kfb, vfb, 0, tid);
    CP_COMMIT();
    load_kv_tile(sb, KVB + KVSTG, kfb, vfb, 64, tid);
    CP_COMMIT();

    float oacc[16][4];
#pragma unroll
    for (int j = 0; j < 16; j++)
#pragma unroll
        for (int e = 0; e < 4; e++) oacc[j][e] = 0.0f;
    float mA = -1e30f, mB = -1e30f, lA = 0.0f, lB = 0.0f;

    const float scale = 0.08838834764831845f;
    const int rAg = q0 + wq0 + gr;
    const int rBg = rAg + 8;

#pragma unroll 1
    for (int t = 0; t < ntiles; t++) {
        if (t + 2 < ntiles) {
            load_kv_tile(sb, KVB + (uint32_t)((t + 2) % 3) * KVSTG,
                         kfb, vfb, (t + 2) * 64, tid);
            CP_COMMIT();
            CP_WAIT(2);
        } else if (t + 1 < ntiles) {
            CP_WAIT(1);
        } else {
            CP_WAIT(0);
        }
        __syncthreads();

        const uint32_t kv = sb + KVB + (uint32_t)(t % 3) * KVSTG;

        // ---- S = Q @ K^T (fp16 x2) ----
        float sacc[8][4];
#pragma unroll
        for (int j = 0; j < 8; j++)
#pragma unroll
            for (int e = 0; e < 4; e++) sacc[j][e] = 0.0f;

        const uint32_t aB = sb + (uint32_t)wq0 * AP;
#pragma unroll
        for (int c = 0; c < 8; c++) {
            const uint32_t ao = (uint32_t)((lane & 15) * AP
                              + (c * 16 + ((lane >> 4) << 3)) * 2);
            uint32_t ah0, ah1, ah2, ah3, al0, al1, al2, al3;
            ldm_x4(ah0, ah1, ah2, ah3, aB + ao);
            ldm_x4(al0, al1, al2, al3, aB + QTB + ao);
#pragma unroll
            for (int g = 0; g < 4; g++) {
                const uint32_t bo = (uint32_t)((g * 16 + ((lane >> 4) << 3) + (lane & 7)) * AP
                                  + (c * 16 + ((lane >> 3) & 1) * 8) * 2);
                uint32_t bh0, bh1, bh2, bh3;
                ldm_x4(bh0, bh1, bh2, bh3, kv + bo);
                mma16816h(sacc[2 * g],     ah0, ah1, ah2, ah3, bh0, bh1);
                mma16816h(sacc[2 * g + 1], ah0, ah1, ah2, ah3, bh2, bh3);
                mma16816h(sacc[2 * g],     al0, al1, al2, al3, bh0, bh1);
                mma16816h(sacc[2 * g + 1], al0, al1, al2, al3, bh2, bh3);
            }
        }

#pragma unroll
        for (int j = 0; j < 8; j++)
#pragma unroll
            for (int e = 0; e < 4; e++) sacc[j][e] *= scale;

        if (t >= 2 * qt) {
#pragma unroll
            for (int j = 0; j < 8; j++) {
                int col = t * 64 + j * 8 + 2 * (lane & 3);
                if (col     > rAg) sacc[j][0] = -1e30f;
                if (col + 1 > rAg) sacc[j][1] = -1e30f;
                if (col     > rBg) sacc[j][2] = -1e30f;
                if (col + 1 > rBg) sacc[j][3] = -1e30f;
            }
        }

        // ---- online softmax ----
        float mxA = -1e30f, mxB = -1e30f;
#pragma unroll
        for (int j = 0; j < 8; j++) {
            mxA = fmaxf(mxA, fmaxf(sacc[j][0], sacc[j][1]));
            mxB = fmaxf(mxB, fmaxf(sacc[j][2], sacc[j][3]));
        }
        mxA = fmaxf(mxA, __shfl_xor_sync(0xffffffffu, mxA, 1));
        mxA = fmaxf(mxA, __shfl_xor_sync(0xffffffffu, mxA, 2));
        mxB = fmaxf(mxB, __shfl_xor_sync(0xffffffffu, mxB, 1));
        mxB = fmaxf(mxB, __shfl_xor_sync(0xffffffffu, mxB, 2));

        float mnA = fmaxf(mA, mxA), mnB = fmaxf(mB, mxB);
        float facA = __expf(mA - mnA), facB = __expf(mB - mnB);
        float sA = 0.0f, sB = 0.0f;
#pragma unroll
        for (int j = 0; j < 8; j++) {
            float p0 = __expf(sacc[j][0] - mnA);
            float p1 = __expf(sacc[j][1] - mnA);
            float p2 = __expf(sacc[j][2] - mnB);
            float p3 = __expf(sacc[j][3] - mnB);
            sacc[j][0] = p0; sacc[j][1] = p1; sacc[j][2] = p2; sacc[j][3] = p3;
            sA += p0 + p1; sB += p2 + p3;
        }
        sA += __shfl_xor_sync(0xffffffffu, sA, 1);
        sA += __shfl_xor_sync(0xffffffffu, sA, 2);
        sB += __shfl_xor_sync(0xffffffffu, sB, 1);
        sB += __shfl_xor_sync(0xffffffffu, sB, 2);
        lA = lA * facA + sA; lB = lB * facB + sB;
        mA = mnA; mB = mnB;
#pragma unroll
        for (int j = 0; j < 16; j++) {
            oacc[j][0] *= facA; oacc[j][1] *= facA;
            oacc[j][2] *= facB; oacc[j][3] *= facB;
        }

        // ---- O += P @ V (single fp16 pass) ----
#pragma unroll
        for (int kc = 0; kc < 4; kc++) {
            const int j0 = 2 * kc, j1 = 2 * kc + 1;
            uint32_t ph[4];
            ph[0] = pack_h2(sacc[j0][0], sacc[j0][1]);
            ph[1] = pack_h2(sacc[j0][2], sacc[j0][3]);
            ph[2] = pack_h2(sacc[j1][0], sacc[j1][1]);
            ph[3] = pack_h2(sacc[j1][2], sacc[j1][3]);
#pragma unroll
            for (int bn = 0; bn < 8; bn++) {
                const uint32_t rowsel =
                    (uint32_t)((kc * 16 + ((lane >> 4) << 3) + (lane & 7)) * AP
                             + (bn * 16 + ((lane >> 3) & 1) * 8) * 2);
                uint32_t r0, r1, r2, r3;
                ldm_x4_t(r0, r1, r2, r3, kv + KVTB + rowsel);
                mma16816h(oacc[2 * bn],     ph[0], ph[1], ph[2], ph[3], r0, r2);
                mma16816h(oacc[2 * bn + 1], ph[0], ph[1], ph[2], ph[3], r1, r3);
            }
        }
        __syncthreads();
    }

    const float invA = 1.0f / lA, invB = 1.0f / lB;
    const size_t rowA = ((size_t)b * SS + rAg) * NQ;
    const size_t rowB = ((size_t)b * SS + rBg) * NQ;
#pragma unroll
    for (int j = 0; j < 16; j++) {
        int col = h * HDIM + j * 8 + 2 * (lane & 3);
        store_hilo_h(ohi, olo, rowA + col, oacc[j][0] * invA, oacc[j][1] * invA);
        store_hilo_h(ohi, olo, rowB + col, oacc[j][2] * invB, oacc[j][3] * invB);
    }
}

// ---------------------------------------------------------------------------
extern "C" void kernel_launch(void* const* d_in, const int* in_sizes, int n_in,
                              void* d_out, int out_size)
{
    const float* x  = (const float*)d_in[0];
    const float* Wq = (const float*)d_in[2];
    const float* Wk = (const float*)d_in[3];
    const float* Wv = (const float*)d_in[4];
    const float* Wo = (const float*)d_in[5];
    float* out = (float*)d_out;

    __half *xhi, *xlo, *ahi, *alo, *qh, *ql, *kf, *vf;
    __half *wq, *wk, *wv, *wo;
    float2* rope;
    (void)cudaGetSymbolAddress((void**)&xhi, g_xhi);
    (void)cudaGetSymbolAddress((void**)&xlo, g_xlo);
    (void)cudaGetSymbolAddress((void**)&ahi, g_ahi);
    (void)cudaGetSymbolAddress((void**)&alo, g_alo);
    (void)cudaGetSymbolAddress((void**)&qh, g_qhi);
    (void)cudaGetSymbolAddress((void**)&ql, g_qlo);
    (void)cudaGetSymbolAddress((void**)&kf, g_kf);
    (void)cudaGetSymbolAddress((void**)&vf, g_vf);
    (void)cudaGetSymbolAddress((void**)&wq, g_wqT);
    (void)cudaGetSymbolAddress((void**)&wk, g_wkT);
    (void)cudaGetSymbolAddress((void**)&wv, g_wvT);
    (void)cudaGetSymbolAddress((void**)&wo, g_woT);
    (void)cudaGetSymbolAddress((void**)&rope, g_rope);

    (void)cudaFuncSetAttribute(gemm_qkv,
                               cudaFuncAttributeMaxDynamicSharedMemorySize, GEMM_DSMEM);
    (void)cudaFuncSetAttribute(gemm_oproj,
                               cudaFuncAttributeMaxDynamicSharedMemorySize, GEMM_DSMEM);
    (void)cudaFuncSetAttribute(attn_mma,
                               cudaFuncAttributeMaxDynamicSharedMemorySize, ATTN_SMEM);

    // 1) merged prep
    prep_kernel<<<PREP_GRID, 256>>>(x,
                                    (__half2*)xhi, (__half2*)xlo,
                                    Wq, Wk, Wv, Wo,
                                    wq, wk, wv, wo, rope);

    // 2) fused QKV projection (fp16 x2)
    gemm_qkv<<<768, 256, GEMM_DSMEM>>>(xhi, xlo, wq, wk, wv,
                                       qh, ql, kf, vf, rope);

    // 3) attention (fp16 x2 S, fp16 PV)
    attn_mma<<<(SS / 128) * NHQ * BB, 256, ATTN_SMEM>>>(qh, ql, kf, vf, ahi, alo);

    // 4) output projection (fp16 x2) -> fp32 out
    gemm_oproj<<<dim3(NQ / 128, MM / 128), 256, GEMM_DSMEM>>>(
        ahi, alo, wo, out, NQ);
}